// round 6
// baseline (speedup 1.0000x reference)
#include <cuda_runtime.h>
#include <cstdint>
#include <math.h>

#define BB 8192

// TF32 operand rounding (matches cuBLAS/cuDNN TF32)
__device__ __forceinline__ float tf32r(float x) {
    uint32_t u;
    asm("cvt.rna.tf32.f32 %0, %1;" : "=r"(u) : "f"(x));
    return __uint_as_float(u);
}

// ---------------- scratch ----------------------------------------------------
__device__ float g_A[96 * 96];
__device__ float g_At[96 * 96];
__device__ float g_buf1[(size_t)BB * 6144];
__device__ float g_buf2[(size_t)BB * 3072];

// ---------------- build dense normalized adjacency (+ transpose) -------------
__global__ void k_build_adj(const int* __restrict__ ei, int ne) {
    __shared__ float deg[96];
    __shared__ float dinv[96];
    int t = threadIdx.x;
    if (t < 96) deg[t] = 0.f;
    for (int i = t; i < 9216; i += 256) { g_A[i] = 0.f; g_At[i] = 0.f; }
    __syncthreads();
    for (int e = t; e < ne; e += 256) atomicAdd(&deg[ei[e]], 1.0f);
    if (t < 96) atomicAdd(&deg[t], 1.0f);
    __syncthreads();
    if (t < 96) dinv[t] = 1.0f / sqrtf(fmaxf(deg[t], 1e-12f));
    __syncthreads();
    for (int e = t; e < ne; e += 256) {
        int r = ei[e], c = ei[ne + e];
        float v = dinv[r] * dinv[c];
        atomicAdd(&g_A[r * 96 + c], v);
        atomicAdd(&g_At[c * 96 + r], v);
    }
    if (t < 96) {
        float v = dinv[t] * dinv[t];
        atomicAdd(&g_A[t * 96 + t], v);
        atomicAdd(&g_At[t * 96 + t], v);
    }
}

// ---------------- fused GCN1+GCN2 (one block = one batch) --------------------
__global__ void __launch_bounds__(256, 2) k_gcn(const float* __restrict__ src,
                                                const float* __restrict__ W1,
                                                const float* __restrict__ b1,
                                                const float* __restrict__ W2,
                                                const float* __restrict__ b2) {
    extern __shared__ float sm[];
    float* sAt = sm;              // [m][n] 96*96
    float* sX  = sAt + 9216;     // [m][c] pad 20
    float* sYt = sX + 1920;     // [c][n] 16*96
    float* sW1 = sYt + 1536;     // [c][f] 16*64
    float* sHt = sW1 + 1024;     // [f][n] 64*96
    float* sW2 = sHt + 6144;     // [f][g] 64*32
    float* sT  = sW2 + 2048;     // [m][g] 96*32
    float* sB1 = sT + 3072;      // 64
    float* sB2 = sB1 + 64;       // 32
    int t = threadIdx.x, b = blockIdx.x;

    for (int i = t; i < 9216; i += 256) sAt[i] = g_At[i];
    const float* xb = src + (size_t)b * 1536;
    for (int i = t; i < 1536; i += 256) { int c = i / 96, m = i % 96; sX[m * 20 + c] = tf32r(xb[i]); }
    for (int i = t; i < 1024; i += 256) sW1[i] = tf32r(W1[i]);
    for (int i = t; i < 2048; i += 256) sW2[i] = tf32r(W2[i]);
    if (t < 64) sB1[t] = b1[t];
    if (t < 32) sB2[t] = b2[t];
    __syncthreads();

    if (t < 96) {   // Y = A@Xq -> sYt[c][n]
        int n0 = (t % 24) * 4, c0 = (t / 24) * 4;
        float acc[4][4] = {};
        for (int m = 0; m < 96; m++) {
            float4 a4 = *(const float4*)&sAt[m * 96 + n0];
            float4 x4 = *(const float4*)&sX[m * 20 + c0];
            float av[4] = {a4.x, a4.y, a4.z, a4.w};
            float xv[4] = {x4.x, x4.y, x4.z, x4.w};
            #pragma unroll
            for (int ci = 0; ci < 4; ci++)
                #pragma unroll
                for (int nj = 0; nj < 4; nj++) acc[ci][nj] += xv[ci] * av[nj];
        }
        #pragma unroll
        for (int ci = 0; ci < 4; ci++)
            #pragma unroll
            for (int nj = 0; nj < 4; nj++) sYt[(c0 + ci) * 96 + n0 + nj] = acc[ci][nj];
    }
    __syncthreads();

    for (int tile = t; tile < 384; tile += 256) {   // H = relu(Y@W1+b1) -> sHt[f][n]
        int n0 = (tile % 24) * 4, f0 = (tile / 24) * 4;
        float acc[4][4] = {};
        #pragma unroll
        for (int c = 0; c < 16; c++) {
            float4 y4 = *(const float4*)&sYt[c * 96 + n0];
            float4 w4 = *(const float4*)&sW1[c * 64 + f0];
            float yv[4] = {y4.x, y4.y, y4.z, y4.w};
            float wv[4] = {w4.x, w4.y, w4.z, w4.w};
            #pragma unroll
            for (int nj = 0; nj < 4; nj++)
                #pragma unroll
                for (int fi = 0; fi < 4; fi++) acc[nj][fi] += yv[nj] * wv[fi];
        }
        #pragma unroll
        for (int fi = 0; fi < 4; fi++)
            #pragma unroll
            for (int nj = 0; nj < 4; nj++)
                sHt[(f0 + fi) * 96 + n0 + nj] = tf32r(fmaxf(acc[nj][fi] + sB1[f0 + fi], 0.f));
    }
    __syncthreads();

    if (t < 192) {   // T = Hq@W2q -> sT[n][g]
        int n0 = (t % 24) * 4, g0 = (t / 24) * 4;
        float acc[4][4] = {};
        for (int f = 0; f < 64; f++) {
            float4 h4 = *(const float4*)&sHt[f * 96 + n0];
            float4 w4 = *(const float4*)&sW2[f * 32 + g0];
            float hv[4] = {h4.x, h4.y, h4.z, h4.w};
            float wv[4] = {w4.x, w4.y, w4.z, w4.w};
            #pragma unroll
            for (int nj = 0; nj < 4; nj++)
                #pragma unroll
                for (int gi = 0; gi < 4; gi++) acc[nj][gi] += hv[nj] * wv[gi];
        }
        #pragma unroll
        for (int nj = 0; nj < 4; nj++)
            #pragma unroll
            for (int gi = 0; gi < 4; gi++) sT[(n0 + nj) * 32 + g0 + gi] = acc[nj][gi];
    }
    __syncthreads();

    if (t < 192) {   // out[g][n] = relu(A@T + b2)
        int n0 = (t % 24) * 4, g0 = (t / 24) * 4;
        float acc[4][4] = {};
        for (int m = 0; m < 96; m++) {
            float4 a4 = *(const float4*)&sAt[m * 96 + n0];
            float4 t4 = *(const float4*)&sT[m * 32 + g0];
            float av[4] = {a4.x, a4.y, a4.z, a4.w};
            float tv[4] = {t4.x, t4.y, t4.z, t4.w};
            #pragma unroll
            for (int nj = 0; nj < 4; nj++)
                #pragma unroll
                for (int gi = 0; gi < 4; gi++) acc[nj][gi] += av[nj] * tv[gi];
        }
        float* out = g_buf2 + (size_t)b * 3072;
        #pragma unroll
        for (int gi = 0; gi < 4; gi++)
            #pragma unroll
            for (int nj = 0; nj < 4; nj++)
                out[(g0 + gi) * 96 + n0 + nj] = fmaxf(acc[nj][gi] + sB2[g0 + gi], 0.f);
    }
}

// ---------------- conv1: [B,32,96]->[B,64,48], k=7 s=2 p=3 -------------------
// 4 batches/block, weight chunks of 8 ch (loaded once), float4 windows
__global__ void __launch_bounds__(256, 2) k_conv1(const float* __restrict__ w,
                                                  const float* __restrict__ bias) {
    extern __shared__ float sm[];
    float* sIn = sm;                    // [4][32][104] offset 3
    float* sW  = sIn + 4 * 32 * 104;    // [64][57]
    int t = threadIdx.x;
    int b0 = blockIdx.x * 4;

    for (int i = t; i < 4 * 32 * 104; i += 256) {
        int lb = i / (32 * 104); int r = i % (32 * 104); int c = r / 104; int j = r % 104;
        int p = j - 3;
        float v = 0.f;
        if (p >= 0 && p < 96) v = tf32r(g_buf2[(size_t)(b0 + lb) * 3072 + c * 96 + p]);
        sIn[i] = v;
    }

    int lb = t >> 6, o = t & 63;
    const float* in = sIn + lb * 32 * 104;
    float bo = bias[o];
    float acc[4][12];
    #pragma unroll
    for (int tg = 0; tg < 4; tg++)
        #pragma unroll
        for (int i = 0; i < 12; i++) acc[tg][i] = bo;

    for (int cc = 0; cc < 4; cc++) {
        __syncthreads();
        for (int i = t; i < 64 * 56; i += 256)
            sW[(i / 56) * 57 + (i % 56)] = tf32r(w[(i / 56) * 224 + cc * 56 + (i % 56)]);
        __syncthreads();
        const float* wrow = sW + o * 57;
        #pragma unroll
        for (int c = 0; c < 8; c++) {
            float wr[7];
            #pragma unroll
            for (int k = 0; k < 7; k++) wr[k] = wrow[c * 7 + k];
            const float* ir = in + (cc * 8 + c) * 104;
            #pragma unroll
            for (int tg = 0; tg < 4; tg++) {
                float win[29];
                const float4* ir4 = (const float4*)(ir + tg * 24);
                #pragma unroll
                for (int j = 0; j < 7; j++) {
                    float4 v = ir4[j];
                    win[4 * j] = v.x; win[4 * j + 1] = v.y;
                    win[4 * j + 2] = v.z; win[4 * j + 3] = v.w;
                }
                win[28] = ir[tg * 24 + 28];
                #pragma unroll
                for (int tt = 0; tt < 12; tt++)
                    #pragma unroll
                    for (int k = 0; k < 7; k++) acc[tg][tt] += wr[k] * win[2 * tt + k];
            }
        }
    }
    float* out = g_buf1 + (size_t)(b0 + lb) * 3072 + o * 48;
    #pragma unroll
    for (int tg = 0; tg < 4; tg++)
        #pragma unroll
        for (int i = 0; i < 12; i++) out[tg * 12 + i] = fmaxf(acc[tg][i], 0.f);
}

// ---------------- conv2: [B,64,48]->[B,128,24], k=5 s=2 p=2 ------------------
// 4 batches/block, 2 output channels/thread, weight chunks of 16 ch, float4 win
__global__ void __launch_bounds__(256, 2) k_conv2(const float* __restrict__ w,
                                                  const float* __restrict__ bias) {
    extern __shared__ float sm[];
    float* sIn = sm;                    // [4][64][52] offset 2
    float* sW  = sIn + 4 * 64 * 52;     // [128][81]
    int t = threadIdx.x;
    int b0 = blockIdx.x * 4;

    for (int i = t; i < 4 * 64 * 52; i += 256) {
        int lb = i / (64 * 52); int r = i % (64 * 52); int c = r / 52; int j = r % 52;
        int p = j - 2;
        float v = 0.f;
        if (p >= 0 && p < 48) v = tf32r(g_buf1[(size_t)(b0 + lb) * 3072 + c * 48 + p]);
        sIn[i] = v;
    }

    int lb = t >> 6, op = t & 63;       // o0 = op, o1 = op + 64
    const float* in = sIn + lb * 64 * 52;
    float acc[2][24];
    #pragma unroll
    for (int q = 0; q < 2; q++) {
        float bo = bias[op + q * 64];
        #pragma unroll
        for (int i = 0; i < 24; i++) acc[q][i] = bo;
    }

    for (int cc = 0; cc < 4; cc++) {
        __syncthreads();
        for (int i = t; i < 128 * 80; i += 256)
            sW[(i / 80) * 81 + (i % 80)] = tf32r(w[(i / 80) * 320 + cc * 80 + (i % 80)]);
        __syncthreads();
        #pragma unroll
        for (int c = 0; c < 16; c++) {
            float wr[2][5];
            #pragma unroll
            for (int q = 0; q < 2; q++)
                #pragma unroll
                for (int k = 0; k < 5; k++) wr[q][k] = sW[(op + q * 64) * 81 + c * 5 + k];
            const float* ir = in + (cc * 16 + c) * 52;
            #pragma unroll
            for (int tg = 0; tg < 2; tg++) {
                float win[27];
                const float4* ir4 = (const float4*)(ir + tg * 24);
                #pragma unroll
                for (int j = 0; j < 6; j++) {
                    float4 v = ir4[j];
                    win[4 * j] = v.x; win[4 * j + 1] = v.y;
                    win[4 * j + 2] = v.z; win[4 * j + 3] = v.w;
                }
                win[24] = ir[tg * 24 + 24];
                win[25] = ir[tg * 24 + 25];
                win[26] = ir[tg * 24 + 26];
                #pragma unroll
                for (int tt = 0; tt < 12; tt++)
                    #pragma unroll
                    for (int k = 0; k < 5; k++) {
                        acc[0][tg * 12 + tt] += wr[0][k] * win[2 * tt + k];
                        acc[1][tg * 12 + tt] += wr[1][k] * win[2 * tt + k];
                    }
            }
        }
    }
    #pragma unroll
    for (int q = 0; q < 2; q++) {
        float* out = g_buf2 + (size_t)(b0 + lb) * 3072 + (op + q * 64) * 24;
        #pragma unroll
        for (int i = 0; i < 24; i++) out[i] = fmaxf(acc[q][i], 0.f);
    }
}

// ---------------- conv3: [B,128,24]->[B,256,12], k=3 s=2 p=1 -----------------
// 2 batches/block, 2 output channels/thread, stride-28 padded rows, float4 win
__global__ void __launch_bounds__(256, 3) k_conv3(const float* __restrict__ w,
                                                  const float* __restrict__ bias) {
    extern __shared__ float sm[];
    float* sIn = sm;                    // [2][128][28] offset 1, tail pad
    float* sW  = sIn + 2 * 128 * 28;    // [256][25]
    int t = threadIdx.x;
    int b0 = blockIdx.x * 2;

    for (int i = t; i < 2 * 128 * 28; i += 256) {
        int lb = i / (128 * 28); int r = i % (128 * 28); int c = r / 28; int j = r % 28;
        int p = j - 1;
        float v = 0.f;
        if (p >= 0 && p < 24) v = tf32r(g_buf2[(size_t)(b0 + lb) * 3072 + c * 24 + p]);
        sIn[i] = v;
    }

    int lb = t >> 7, ol = t & 127;
    const float* in = sIn + lb * 128 * 28;
    float acc[2][12];
    #pragma unroll
    for (int q = 0; q < 2; q++) {
        float bo = bias[ol + q * 128];
        #pragma unroll
        for (int i = 0; i < 12; i++) acc[q][i] = bo;
    }

    for (int cc = 0; cc < 16; cc++) {
        __syncthreads();
        for (int i = t; i < 256 * 24; i += 256)
            sW[(i / 24) * 25 + (i % 24)] = tf32r(w[(i / 24) * 384 + cc * 24 + (i % 24)]);
        __syncthreads();
        #pragma unroll
        for (int c = 0; c < 8; c++) {
            float wr[2][3];
            #pragma unroll
            for (int q = 0; q < 2; q++)
                #pragma unroll
                for (int k = 0; k < 3; k++) wr[q][k] = sW[(ol + q * 128) * 25 + c * 3 + k];
            const float* ir = in + (cc * 8 + c) * 28;
            float win[25];
            const float4* ir4 = (const float4*)ir;
            #pragma unroll
            for (int j = 0; j < 6; j++) {
                float4 v = ir4[j];
                win[4 * j] = v.x; win[4 * j + 1] = v.y;
                win[4 * j + 2] = v.z; win[4 * j + 3] = v.w;
            }
            win[24] = ir[24];
            #pragma unroll
            for (int tt = 0; tt < 12; tt++)
                #pragma unroll
                for (int k = 0; k < 3; k++) {
                    acc[0][tt] += wr[0][k] * win[2 * tt + k];
                    acc[1][tt] += wr[1][k] * win[2 * tt + k];
                }
        }
    }
    #pragma unroll
    for (int q = 0; q < 2; q++) {
        float* out = g_buf1 + (size_t)(b0 + lb) * 3072 + (ol + q * 128) * 12;
        #pragma unroll
        for (int i = 0; i < 12; i++) out[i] = fmaxf(acc[q][i], 0.f);
    }
}

// ---------------- fc1: [B,3072]@[3072,128]+b -> feat & relu ------------------
__global__ void __launch_bounds__(256) k_fc1(const float* __restrict__ W,
                                             const float* __restrict__ bias,
                                             float* __restrict__ feat_out) {
    __shared__ __align__(16) float sAt[32 * 36];
    __shared__ __align__(16) float sB[32 * 128];
    int t = threadIdx.x;
    int row0 = blockIdx.x * 32;
    int nt = t & 31, mt = t >> 5;
    float acc[4][4] = {};
    const float* Ain = g_buf1 + (size_t)row0 * 3072;

    for (int k0 = 0; k0 < 3072; k0 += 32) {
        __syncthreads();
        for (int i = t; i < 1024; i += 256) {
            int m = i >> 5, k = i & 31;
            sAt[k * 36 + m] = tf32r(Ain[(size_t)m * 3072 + k0 + k]);
        }
        for (int i = t; i < 4096; i += 256) {
            int k = i >> 7, n = i & 127;
            sB[i] = tf32r(W[(size_t)(k0 + k) * 128 + n]);
        }
        __syncthreads();
        #pragma unroll
        for (int k = 0; k < 32; k++) {
            float4 a4 = *(const float4*)&sAt[k * 36 + mt * 4];
            float4 b4 = *(const float4*)&sB[k * 128 + nt * 4];
            float av[4] = {a4.x, a4.y, a4.z, a4.w};
            float bv[4] = {b4.x, b4.y, b4.z, b4.w};
            #pragma unroll
            for (int i = 0; i < 4; i++)
                #pragma unroll
                for (int j = 0; j < 4; j++) acc[i][j] += av[i] * bv[j];
        }
    }
    #pragma unroll
    for (int i = 0; i < 4; i++) {
        int r = row0 + mt * 4 + i;
        #pragma unroll
        for (int j = 0; j < 4; j++) {
            int n = nt * 4 + j;
            float f = acc[i][j] + bias[n];
            feat_out[(size_t)r * 128 + n] = f;
            g_buf2[(size_t)r * 128 + n] = fmaxf(f, 0.f);
        }
    }
}

// ---------------- cls1: relu([B,128]@[128,128]+b) ----------------------------
__global__ void k_cls1(const float* __restrict__ W, const float* __restrict__ bias) {
    extern __shared__ float sm[];
    float* sIn = sm;              // [64][129]
    float* sW  = sIn + 64 * 129;  // [128][128]
    int t = threadIdx.x;
    int b0 = blockIdx.x * 64;
    for (int i = t; i < 64 * 128; i += 256) {
        int r = i >> 7, k = i & 127;
        sIn[r * 129 + k] = tf32r(g_buf2[(size_t)(b0 + r) * 128 + k]);
    }
    for (int i = t; i < 128 * 128; i += 256) sW[i] = tf32r(W[i]);
    __syncthreads();
    for (int idx = t; idx < 64 * 128; idx += 256) {
        int r = idx >> 7, n = idx & 127;
        float acc = bias[n];
        #pragma unroll 8
        for (int k = 0; k < 128; k++) acc += sIn[r * 129 + k] * sW[k * 128 + n];
        g_buf1[(size_t)(b0 + r) * 128 + n] = fmaxf(acc, 0.f);
    }
}

// ---------------- cls2: [B,128]@[128,210]+b -> x -----------------------------
__global__ void k_cls2(const float* __restrict__ W, const float* __restrict__ bias,
                       float* __restrict__ out_x) {
    extern __shared__ float sm[];
    float* sIn = sm;              // [64][129]
    float* sW  = sIn + 64 * 129;  // [128][210]
    int t = threadIdx.x;
    int b0 = blockIdx.x * 64;
    for (int i = t; i < 64 * 128; i += 256) {
        int r = i >> 7, k = i & 127;
        sIn[r * 129 + k] = tf32r(g_buf1[(size_t)(b0 + r) * 128 + k]);
    }
    for (int i = t; i < 128 * 210; i += 256) sW[i] = tf32r(W[i]);
    __syncthreads();
    for (int idx = t; idx < 64 * 210; idx += 256) {
        int r = idx / 210, n = idx % 210;
        float acc = bias[n];
        #pragma unroll 8
        for (int k = 0; k < 128; k++) acc += sIn[r * 129 + k] * sW[k * 210 + n];
        out_x[(size_t)(b0 + r) * 210 + n] = acc;
    }
}

// ---------------- launch ------------------------------------------------------
extern "C" void kernel_launch(void* const* d_in, const int* in_sizes, int n_in,
                              void* d_out, int out_size) {
    const float* src     = (const float*)d_in[0];
    const int*   ei      = (const int*)d_in[1];
    const float* gcn1_w  = (const float*)d_in[2];
    const float* gcn1_b  = (const float*)d_in[3];
    const float* gcn2_w  = (const float*)d_in[4];
    const float* gcn2_b  = (const float*)d_in[5];
    const float* conv1_w = (const float*)d_in[6];
    const float* conv1_b = (const float*)d_in[7];
    const float* conv2_w = (const float*)d_in[8];
    const float* conv2_b = (const float*)d_in[9];
    const float* conv3_w = (const float*)d_in[10];
    const float* conv3_b = (const float*)d_in[11];
    const float* fc1_w   = (const float*)d_in[12];
    const float* fc1_b   = (const float*)d_in[13];
    const float* cls1_w  = (const float*)d_in[14];
    const float* cls1_b  = (const float*)d_in[15];
    const float* cls2_w  = (const float*)d_in[16];
    const float* cls2_b  = (const float*)d_in[17];

    int ne = in_sizes[1] / 2;

    float* out   = (float*)d_out;
    float* out_x = out;                          // [B,210]
    float* out_f = out + (size_t)BB * 210;       // [B,128]

    const int GCN_SMEM   = (9216 + 1920 + 1536 + 1024 + 6144 + 2048 + 3072 + 96) * 4; // 100224
    const int CONV1_SMEM = (4 * 32 * 104 + 64 * 57) * 4;    // 67840
    const int CONV2_SMEM = (4 * 64 * 52 + 128 * 81) * 4;    // 94720
    const int CONV3_SMEM = (2 * 128 * 28 + 256 * 25) * 4;   // 54272

    cudaFuncSetAttribute(k_gcn,   cudaFuncAttributeMaxDynamicSharedMemorySize, GCN_SMEM);
    cudaFuncSetAttribute(k_conv1, cudaFuncAttributeMaxDynamicSharedMemorySize, CONV1_SMEM);
    cudaFuncSetAttribute(k_conv2, cudaFuncAttributeMaxDynamicSharedMemorySize, CONV2_SMEM);
    cudaFuncSetAttribute(k_conv3, cudaFuncAttributeMaxDynamicSharedMemorySize, CONV3_SMEM);
    cudaFuncSetAttribute(k_cls1,  cudaFuncAttributeMaxDynamicSharedMemorySize, 98560);
    cudaFuncSetAttribute(k_cls2,  cudaFuncAttributeMaxDynamicSharedMemorySize, 140544);

    k_build_adj<<<1, 256>>>(ei, ne);
    k_gcn<<<BB, 256, GCN_SMEM>>>(src, gcn1_w, gcn1_b, gcn2_w, gcn2_b);
    k_conv1<<<BB / 4, 256, CONV1_SMEM>>>(conv1_w, conv1_b);
    k_conv2<<<BB / 4, 256, CONV2_SMEM>>>(conv2_w, conv2_b);
    k_conv3<<<BB / 2, 256, CONV3_SMEM>>>(conv3_w, conv3_b);
    k_fc1<<<BB / 32, 256>>>(fc1_w, fc1_b, out_f);
    k_cls1<<<BB / 64, 256, 98560>>>(cls1_w, cls1_b);
    k_cls2<<<BB / 64, 256, 140544>>>(cls2_w, cls2_b, out_x);
}

// round 7
// speedup vs baseline: 1.5229x; 1.5229x over previous
#include <cuda_runtime.h>
#include <cstdint>
#include <math.h>

#define BB 8192

// TF32 operand rounding (matches cuBLAS/cuDNN TF32)
__device__ __forceinline__ float tf32r(float x) {
    uint32_t u;
    asm("cvt.rna.tf32.f32 %0, %1;" : "=r"(u) : "f"(x));
    return __uint_as_float(u);
}

// ---------------- scratch ----------------------------------------------------
__device__ float g_A[96 * 96];
__device__ float g_At[96 * 96];
__device__ float g_buf1[(size_t)BB * 6144];
__device__ float g_buf2[(size_t)BB * 3072];

// ---------------- build dense normalized adjacency (+ transpose) -------------
__global__ void k_build_adj(const int* __restrict__ ei, int ne) {
    __shared__ float deg[96];
    __shared__ float dinv[96];
    int t = threadIdx.x;
    if (t < 96) deg[t] = 0.f;
    for (int i = t; i < 9216; i += 256) { g_A[i] = 0.f; g_At[i] = 0.f; }
    __syncthreads();
    for (int e = t; e < ne; e += 256) atomicAdd(&deg[ei[e]], 1.0f);
    if (t < 96) atomicAdd(&deg[t], 1.0f);
    __syncthreads();
    if (t < 96) dinv[t] = 1.0f / sqrtf(fmaxf(deg[t], 1e-12f));
    __syncthreads();
    for (int e = t; e < ne; e += 256) {
        int r = ei[e], c = ei[ne + e];
        float v = dinv[r] * dinv[c];
        atomicAdd(&g_A[r * 96 + c], v);
        atomicAdd(&g_At[c * 96 + r], v);
    }
    if (t < 96) {
        float v = dinv[t] * dinv[t];
        atomicAdd(&g_A[t * 96 + t], v);
        atomicAdd(&g_At[t * 96 + t], v);
    }
}

// ---------------- fused GCN1+GCN2 (one block = one batch) --------------------
__global__ void __launch_bounds__(256, 2) k_gcn(const float* __restrict__ src,
                                                const float* __restrict__ W1,
                                                const float* __restrict__ b1,
                                                const float* __restrict__ W2,
                                                const float* __restrict__ b2) {
    extern __shared__ float sm[];
    float* sAt = sm;              // [m][n] 96*96
    float* sX  = sAt + 9216;     // [m][c] pad 20
    float* sYt = sX + 1920;     // [c][n] 16*96
    float* sW1 = sYt + 1536;     // [c][f] 16*64
    float* sHt = sW1 + 1024;     // [f][n] 64*96
    float* sW2 = sHt + 6144;     // [f][g] 64*32
    float* sT  = sW2 + 2048;     // [m][g] 96*32
    float* sB1 = sT + 3072;      // 64
    float* sB2 = sB1 + 64;       // 32
    int t = threadIdx.x, b = blockIdx.x;

    for (int i = t; i < 9216; i += 256) sAt[i] = g_At[i];
    const float* xb = src + (size_t)b * 1536;
    for (int i = t; i < 1536; i += 256) { int c = i / 96, m = i % 96; sX[m * 20 + c] = tf32r(xb[i]); }
    for (int i = t; i < 1024; i += 256) sW1[i] = tf32r(W1[i]);
    for (int i = t; i < 2048; i += 256) sW2[i] = tf32r(W2[i]);
    if (t < 64) sB1[t] = b1[t];
    if (t < 32) sB2[t] = b2[t];
    __syncthreads();

    if (t < 96) {   // Y = A@Xq -> sYt[c][n]
        int n0 = (t % 24) * 4, c0 = (t / 24) * 4;
        float acc[4][4] = {};
        for (int m = 0; m < 96; m++) {
            float4 a4 = *(const float4*)&sAt[m * 96 + n0];
            float4 x4 = *(const float4*)&sX[m * 20 + c0];
            float av[4] = {a4.x, a4.y, a4.z, a4.w};
            float xv[4] = {x4.x, x4.y, x4.z, x4.w};
            #pragma unroll
            for (int ci = 0; ci < 4; ci++)
                #pragma unroll
                for (int nj = 0; nj < 4; nj++) acc[ci][nj] += xv[ci] * av[nj];
        }
        #pragma unroll
        for (int ci = 0; ci < 4; ci++)
            #pragma unroll
            for (int nj = 0; nj < 4; nj++) sYt[(c0 + ci) * 96 + n0 + nj] = acc[ci][nj];
    }
    __syncthreads();

    for (int tile = t; tile < 384; tile += 256) {   // H = relu(Y@W1+b1) -> sHt[f][n]
        int n0 = (tile % 24) * 4, f0 = (tile / 24) * 4;
        float acc[4][4] = {};
        #pragma unroll
        for (int c = 0; c < 16; c++) {
            float4 y4 = *(const float4*)&sYt[c * 96 + n0];
            float4 w4 = *(const float4*)&sW1[c * 64 + f0];
            float yv[4] = {y4.x, y4.y, y4.z, y4.w};
            float wv[4] = {w4.x, w4.y, w4.z, w4.w};
            #pragma unroll
            for (int nj = 0; nj < 4; nj++)
                #pragma unroll
                for (int fi = 0; fi < 4; fi++) acc[nj][fi] += yv[nj] * wv[fi];
        }
        #pragma unroll
        for (int fi = 0; fi < 4; fi++)
            #pragma unroll
            for (int nj = 0; nj < 4; nj++)
                sHt[(f0 + fi) * 96 + n0 + nj] = tf32r(fmaxf(acc[nj][fi] + sB1[f0 + fi], 0.f));
    }
    __syncthreads();

    if (t < 192) {   // T = Hq@W2q -> sT[n][g]
        int n0 = (t % 24) * 4, g0 = (t / 24) * 4;
        float acc[4][4] = {};
        for (int f = 0; f < 64; f++) {
            float4 h4 = *(const float4*)&sHt[f * 96 + n0];
            float4 w4 = *(const float4*)&sW2[f * 32 + g0];
            float hv[4] = {h4.x, h4.y, h4.z, h4.w};
            float wv[4] = {w4.x, w4.y, w4.z, w4.w};
            #pragma unroll
            for (int nj = 0; nj < 4; nj++)
                #pragma unroll
                for (int gi = 0; gi < 4; gi++) acc[nj][gi] += hv[nj] * wv[gi];
        }
        #pragma unroll
        for (int nj = 0; nj < 4; nj++)
            #pragma unroll
            for (int gi = 0; gi < 4; gi++) sT[(n0 + nj) * 32 + g0 + gi] = acc[nj][gi];
    }
    __syncthreads();

    if (t < 192) {   // out[g][n] = relu(A@T + b2)
        int n0 = (t % 24) * 4, g0 = (t / 24) * 4;
        float acc[4][4] = {};
        for (int m = 0; m < 96; m++) {
            float4 a4 = *(const float4*)&sAt[m * 96 + n0];
            float4 t4 = *(const float4*)&sT[m * 32 + g0];
            float av[4] = {a4.x, a4.y, a4.z, a4.w};
            float tv[4] = {t4.x, t4.y, t4.z, t4.w};
            #pragma unroll
            for (int nj = 0; nj < 4; nj++)
                #pragma unroll
                for (int gi = 0; gi < 4; gi++) acc[nj][gi] += av[nj] * tv[gi];
        }
        float* out = g_buf2 + (size_t)b * 3072;
        #pragma unroll
        for (int gi = 0; gi < 4; gi++)
            #pragma unroll
            for (int nj = 0; nj < 4; nj++)
                out[(g0 + gi) * 96 + n0 + nj] = fmaxf(acc[nj][gi] + sB2[g0 + gi], 0.f);
    }
}

// ---------------- conv1: [B,32,96]->[B,64,48], k=7 s=2 p=3 -------------------
// R5 structure (4 batches/block, tg-pairs, min 3 blocks/SM) + float4 windows
__global__ void __launch_bounds__(256, 3) k_conv1(const float* __restrict__ w,
                                                  const float* __restrict__ bias) {
    extern __shared__ float sm[];
    float* sIn = sm;                    // [4][32][104] offset 3
    float* sW  = sIn + 4 * 32 * 104;    // [64][57]
    int t = threadIdx.x;
    int b0 = blockIdx.x * 4;

    for (int i = t; i < 4 * 32 * 104; i += 256) {
        int lb = i / (32 * 104); int r = i % (32 * 104); int c = r / 104; int j = r % 104;
        int p = j - 3;
        float v = 0.f;
        if (p >= 0 && p < 96) v = tf32r(g_buf2[(size_t)(b0 + lb) * 3072 + c * 96 + p]);
        sIn[i] = v;
    }

    int lb = t >> 6, o = t & 63;
    const float* in = sIn + lb * 32 * 104;
    float bo = bias[o];

    for (int p = 0; p < 2; p++) {                 // tg pairs {0,1},{2,3}
        float acc[2][12];
        #pragma unroll
        for (int q = 0; q < 2; q++)
            #pragma unroll
            for (int i = 0; i < 12; i++) acc[q][i] = bo;

        for (int cc = 0; cc < 4; cc++) {          // channel chunks of 8
            __syncthreads();
            for (int i = t; i < 64 * 56; i += 256)
                sW[(i / 56) * 57 + (i % 56)] = tf32r(w[(i / 56) * 224 + cc * 56 + (i % 56)]);
            __syncthreads();
            const float* wrow = sW + o * 57;
            #pragma unroll
            for (int c = 0; c < 8; c++) {
                float wr[7];
                #pragma unroll
                for (int k = 0; k < 7; k++) wr[k] = wrow[c * 7 + k];
                const float* ir = in + (cc * 8 + c) * 104;
                #pragma unroll
                for (int q = 0; q < 2; q++) {
                    int tg = p * 2 + q;
                    float win[29];
                    const float4* ir4 = (const float4*)(ir + tg * 24);   // 96B aligned
                    #pragma unroll
                    for (int j = 0; j < 7; j++) {
                        float4 v = ir4[j];
                        win[4 * j] = v.x; win[4 * j + 1] = v.y;
                        win[4 * j + 2] = v.z; win[4 * j + 3] = v.w;
                    }
                    win[28] = ir[tg * 24 + 28];
                    #pragma unroll
                    for (int tt = 0; tt < 12; tt++)
                        #pragma unroll
                        for (int k = 0; k < 7; k++) acc[q][tt] += wr[k] * win[2 * tt + k];
                }
            }
        }
        float* out = g_buf1 + (size_t)(b0 + lb) * 3072 + o * 48;
        #pragma unroll
        for (int q = 0; q < 2; q++)
            #pragma unroll
            for (int i = 0; i < 12; i++) out[(p * 2 + q) * 12 + i] = fmaxf(acc[q][i], 0.f);
    }
}

// ---------------- conv2: [B,64,48]->[B,128,24], k=5 s=2 p=2 ------------------
// R5 structure (2 batches/block, 1 oc/thread, min 3 blocks/SM) + float4 windows
__global__ void __launch_bounds__(256, 3) k_conv2(const float* __restrict__ w,
                                                  const float* __restrict__ bias) {
    extern __shared__ float sm[];
    float* sIn = sm;                    // [2][64][52] offset 2
    float* sW  = sIn + 2 * 64 * 52;     // [128][81]
    int t = threadIdx.x;
    int b0 = blockIdx.x * 2;

    for (int i = t; i < 2 * 64 * 52; i += 256) {
        int lb = i / (64 * 52); int r = i % (64 * 52); int c = r / 52; int j = r % 52;
        int p = j - 2;
        float v = 0.f;
        if (p >= 0 && p < 48) v = tf32r(g_buf1[(size_t)(b0 + lb) * 3072 + c * 48 + p]);
        sIn[i] = v;
    }

    int lb = t >> 7, o = t & 127;
    const float* in = sIn + lb * 64 * 52;
    float acc[24];
    float bo = bias[o];
    #pragma unroll
    for (int i = 0; i < 24; i++) acc[i] = bo;

    for (int cc = 0; cc < 4; cc++) {              // channel chunks of 16
        __syncthreads();
        for (int i = t; i < 128 * 80; i += 256)
            sW[(i / 80) * 81 + (i % 80)] = tf32r(w[(i / 80) * 320 + cc * 80 + (i % 80)]);
        __syncthreads();
        const float* wrow = sW + o * 81;
        #pragma unroll
        for (int c = 0; c < 16; c++) {
            float wr[5];
            #pragma unroll
            for (int k = 0; k < 5; k++) wr[k] = wrow[c * 5 + k];
            const float* ir = in + (cc * 16 + c) * 52;
            #pragma unroll
            for (int tg = 0; tg < 2; tg++) {
                float win[27];
                const float4* ir4 = (const float4*)(ir + tg * 24);   // 96B aligned
                #pragma unroll
                for (int j = 0; j < 6; j++) {
                    float4 v = ir4[j];
                    win[4 * j] = v.x; win[4 * j + 1] = v.y;
                    win[4 * j + 2] = v.z; win[4 * j + 3] = v.w;
                }
                win[24] = ir[tg * 24 + 24];
                win[25] = ir[tg * 24 + 25];
                win[26] = ir[tg * 24 + 26];
                #pragma unroll
                for (int tt = 0; tt < 12; tt++)
                    #pragma unroll
                    for (int k = 0; k < 5; k++) acc[tg * 12 + tt] += wr[k] * win[2 * tt + k];
            }
        }
    }
    float* out = g_buf2 + (size_t)(b0 + lb) * 3072 + o * 24;
    #pragma unroll
    for (int i = 0; i < 24; i++) out[i] = fmaxf(acc[i], 0.f);
}

// ---------------- conv3: [B,128,24]->[B,256,12], k=3 s=2 p=1 -----------------
// R5 structure (2 batches/block, 2 oc/thread, min 3 blocks/SM) + stride 28 + float4
__global__ void __launch_bounds__(256, 3) k_conv3(const float* __restrict__ w,
                                                  const float* __restrict__ bias) {
    extern __shared__ float sm[];
    float* sIn = sm;                    // [2][128][28] offset 1
    float* sW  = sIn + 2 * 128 * 28;    // [256][25]
    int t = threadIdx.x;
    int b0 = blockIdx.x * 2;

    for (int i = t; i < 2 * 128 * 28; i += 256) {
        int lb = i / (128 * 28); int r = i % (128 * 28); int c = r / 28; int j = r % 28;
        int p = j - 1;
        float v = 0.f;
        if (p >= 0 && p < 24) v = tf32r(g_buf2[(size_t)(b0 + lb) * 3072 + c * 24 + p]);
        sIn[i] = v;
    }

    int lb = t >> 7, ol = t & 127;
    const float* in = sIn + lb * 128 * 28;
    float acc[2][12];
    #pragma unroll
    for (int q = 0; q < 2; q++) {
        float bo = bias[ol + q * 128];
        #pragma unroll
        for (int i = 0; i < 12; i++) acc[q][i] = bo;
    }

    for (int cc = 0; cc < 16; cc++) {             // channel chunks of 8
        __syncthreads();
        for (int i = t; i < 256 * 24; i += 256)
            sW[(i / 24) * 25 + (i % 24)] = tf32r(w[(i / 24) * 384 + cc * 24 + (i % 24)]);
        __syncthreads();
        #pragma unroll
        for (int c = 0; c < 8; c++) {
            float wr[2][3];
            #pragma unroll
            for (int q = 0; q < 2; q++)
                #pragma unroll
                for (int k = 0; k < 3; k++) wr[q][k] = sW[(ol + q * 128) * 25 + c * 3 + k];
            const float* ir = in + (cc * 8 + c) * 28;                 // 112B aligned
            float win[25];
            const float4* ir4 = (const float4*)ir;
            #pragma unroll
            for (int j = 0; j < 6; j++) {
                float4 v = ir4[j];
                win[4 * j] = v.x; win[4 * j + 1] = v.y;
                win[4 * j + 2] = v.z; win[4 * j + 3] = v.w;
            }
            win[24] = ir[24];
            #pragma unroll
            for (int tt = 0; tt < 12; tt++)
                #pragma unroll
                for (int k = 0; k < 3; k++) {
                    acc[0][tt] += wr[0][k] * win[2 * tt + k];
                    acc[1][tt] += wr[1][k] * win[2 * tt + k];
                }
        }
    }
    #pragma unroll
    for (int q = 0; q < 2; q++) {
        float* out = g_buf1 + (size_t)(b0 + lb) * 3072 + (ol + q * 128) * 12;
        #pragma unroll
        for (int i = 0; i < 12; i++) out[i] = fmaxf(acc[q][i], 0.f);
    }
}

// ---------------- fc1: [B,3072]@[3072,128]+b -> feat & relu ------------------
__global__ void __launch_bounds__(256) k_fc1(const float* __restrict__ W,
                                             const float* __restrict__ bias,
                                             float* __restrict__ feat_out) {
    __shared__ __align__(16) float sAt[32 * 36];
    __shared__ __align__(16) float sB[32 * 128];
    int t = threadIdx.x;
    int row0 = blockIdx.x * 32;
    int nt = t & 31, mt = t >> 5;
    float acc[4][4] = {};
    const float* Ain = g_buf1 + (size_t)row0 * 3072;

    for (int k0 = 0; k0 < 3072; k0 += 32) {
        __syncthreads();
        for (int i = t; i < 1024; i += 256) {
            int m = i >> 5, k = i & 31;
            sAt[k * 36 + m] = tf32r(Ain[(size_t)m * 3072 + k0 + k]);
        }
        for (int i = t; i < 4096; i += 256) {
            int k = i >> 7, n = i & 127;
            sB[i] = tf32r(W[(size_t)(k0 + k) * 128 + n]);
        }
        __syncthreads();
        #pragma unroll
        for (int k = 0; k < 32; k++) {
            float4 a4 = *(const float4*)&sAt[k * 36 + mt * 4];
            float4 b4 = *(const float4*)&sB[k * 128 + nt * 4];
            float av[4] = {a4.x, a4.y, a4.z, a4.w};
            float bv[4] = {b4.x, b4.y, b4.z, b4.w};
            #pragma unroll
            for (int i = 0; i < 4; i++)
                #pragma unroll
                for (int j = 0; j < 4; j++) acc[i][j] += av[i] * bv[j];
        }
    }
    #pragma unroll
    for (int i = 0; i < 4; i++) {
        int r = row0 + mt * 4 + i;
        #pragma unroll
        for (int j = 0; j < 4; j++) {
            int n = nt * 4 + j;
            float f = acc[i][j] + bias[n];
            feat_out[(size_t)r * 128 + n] = f;
            g_buf2[(size_t)r * 128 + n] = fmaxf(f, 0.f);
        }
    }
}

// ---------------- cls1: relu([B,128]@[128,128]+b) ----------------------------
__global__ void k_cls1(const float* __restrict__ W, const float* __restrict__ bias) {
    extern __shared__ float sm[];
    float* sIn = sm;              // [64][129]
    float* sW  = sIn + 64 * 129;  // [128][128]
    int t = threadIdx.x;
    int b0 = blockIdx.x * 64;
    for (int i = t; i < 64 * 128; i += 256) {
        int r = i >> 7, k = i & 127;
        sIn[r * 129 + k] = tf32r(g_buf2[(size_t)(b0 + r) * 128 + k]);
    }
    for (int i = t; i < 128 * 128; i += 256) sW[i] = tf32r(W[i]);
    __syncthreads();
    for (int idx = t; idx < 64 * 128; idx += 256) {
        int r = idx >> 7, n = idx & 127;
        float acc = bias[n];
        #pragma unroll 8
        for (int k = 0; k < 128; k++) acc += sIn[r * 129 + k] * sW[k * 128 + n];
        g_buf1[(size_t)(b0 + r) * 128 + n] = fmaxf(acc, 0.f);
    }
}

// ---------------- cls2: [B,128]@[128,210]+b -> x -----------------------------
__global__ void k_cls2(const float* __restrict__ W, const float* __restrict__ bias,
                       float* __restrict__ out_x) {
    extern __shared__ float sm[];
    float* sIn = sm;              // [64][129]
    float* sW  = sIn + 64 * 129;  // [128][210]
    int t = threadIdx.x;
    int b0 = blockIdx.x * 64;
    for (int i = t; i < 64 * 128; i += 256) {
        int r = i >> 7, k = i & 127;
        sIn[r * 129 + k] = tf32r(g_buf1[(size_t)(b0 + r) * 128 + k]);
    }
    for (int i = t; i < 128 * 210; i += 256) sW[i] = tf32r(W[i]);
    __syncthreads();
    for (int idx = t; idx < 64 * 210; idx += 256) {
        int r = idx / 210, n = idx % 210;
        float acc = bias[n];
        #pragma unroll 8
        for (int k = 0; k < 128; k++) acc += sIn[r * 129 + k] * sW[k * 210 + n];
        out_x[(size_t)(b0 + r) * 210 + n] = acc;
    }
}

// ---------------- launch ------------------------------------------------------
extern "C" void kernel_launch(void* const* d_in, const int* in_sizes, int n_in,
                              void* d_out, int out_size) {
    const float* src     = (const float*)d_in[0];
    const int*   ei      = (const int*)d_in[1];
    const float* gcn1_w  = (const float*)d_in[2];
    const float* gcn1_b  = (const float*)d_in[3];
    const float* gcn2_w  = (const float*)d_in[4];
    const float* gcn2_b  = (const float*)d_in[5];
    const float* conv1_w = (const float*)d_in[6];
    const float* conv1_b = (const float*)d_in[7];
    const float* conv2_w = (const float*)d_in[8];
    const float* conv2_b = (const float*)d_in[9];
    const float* conv3_w = (const float*)d_in[10];
    const float* conv3_b = (const float*)d_in[11];
    const float* fc1_w   = (const float*)d_in[12];
    const float* fc1_b   = (const float*)d_in[13];
    const float* cls1_w  = (const float*)d_in[14];
    const float* cls1_b  = (const float*)d_in[15];
    const float* cls2_w  = (const float*)d_in[16];
    const float* cls2_b  = (const float*)d_in[17];

    int ne = in_sizes[1] / 2;

    float* out   = (float*)d_out;
    float* out_x = out;                          // [B,210]
    float* out_f = out + (size_t)BB * 210;       // [B,128]

    const int GCN_SMEM   = (9216 + 1920 + 1536 + 1024 + 6144 + 2048 + 3072 + 96) * 4; // 100224
    const int CONV1_SMEM = (4 * 32 * 104 + 64 * 57) * 4;    // 67840
    const int CONV2_SMEM = (2 * 64 * 52 + 128 * 81) * 4;    // 68096
    const int CONV3_SMEM = (2 * 128 * 28 + 256 * 25) * 4;   // 54272

    cudaFuncSetAttribute(k_gcn,   cudaFuncAttributeMaxDynamicSharedMemorySize, GCN_SMEM);
    cudaFuncSetAttribute(k_conv1, cudaFuncAttributeMaxDynamicSharedMemorySize, CONV1_SMEM);
    cudaFuncSetAttribute(k_conv2, cudaFuncAttributeMaxDynamicSharedMemorySize, CONV2_SMEM);
    cudaFuncSetAttribute(k_conv3, cudaFuncAttributeMaxDynamicSharedMemorySize, CONV3_SMEM);
    cudaFuncSetAttribute(k_cls1,  cudaFuncAttributeMaxDynamicSharedMemorySize, 98560);
    cudaFuncSetAttribute(k_cls2,  cudaFuncAttributeMaxDynamicSharedMemorySize, 140544);

    k_build_adj<<<1, 256>>>(ei, ne);
    k_gcn<<<BB, 256, GCN_SMEM>>>(src, gcn1_w, gcn1_b, gcn2_w, gcn2_b);
    k_conv1<<<BB / 4, 256, CONV1_SMEM>>>(conv1_w, conv1_b);
    k_conv2<<<BB / 2, 256, CONV2_SMEM>>>(conv2_w, conv2_b);
    k_conv3<<<BB / 2, 256, CONV3_SMEM>>>(conv3_w, conv3_b);
    k_fc1<<<BB / 32, 256>>>(fc1_w, fc1_b, out_f);
    k_cls1<<<BB / 64, 256, 98560>>>(cls1_w, cls1_b);
    k_cls2<<<BB / 64, 256, 140544>>>(cls2_w, cls2_b, out_x);
}

// round 8
// speedup vs baseline: 2.4828x; 1.6303x over previous
#include <cuda_runtime.h>
#include <cstdint>
#include <math.h>

#define BB 8192

// TF32 operand rounding (matches cuBLAS/cuDNN TF32)
__device__ __forceinline__ float tf32r(float x) {
    uint32_t u;
    asm("cvt.rna.tf32.f32 %0, %1;" : "=r"(u) : "f"(x));
    return __uint_as_float(u);
}

// m16n8k8 tf32 mma: D = A*B + D (fp32 accum)
__device__ __forceinline__ void mma_tf32(float c[4],
                                         uint32_t a0, uint32_t a1, uint32_t a2, uint32_t a3,
                                         uint32_t b0, uint32_t b1) {
    asm volatile(
        "mma.sync.aligned.m16n8k8.row.col.f32.tf32.tf32.f32 "
        "{%0,%1,%2,%3}, {%4,%5,%6,%7}, {%8,%9}, {%0,%1,%2,%3};"
        : "+f"(c[0]), "+f"(c[1]), "+f"(c[2]), "+f"(c[3])
        : "r"(a0), "r"(a1), "r"(a2), "r"(a3), "r"(b0), "r"(b1));
}

// ---------------- scratch ----------------------------------------------------
__device__ float g_A[96 * 96];
__device__ float g_At[96 * 96];
__device__ float g_buf1[(size_t)BB * 6144];
__device__ float g_buf2[(size_t)BB * 3072];

// ---------------- build dense normalized adjacency (+ transpose) -------------
__global__ void k_build_adj(const int* __restrict__ ei, int ne) {
    __shared__ float deg[96];
    __shared__ float dinv[96];
    int t = threadIdx.x;
    if (t < 96) deg[t] = 0.f;
    for (int i = t; i < 9216; i += 256) { g_A[i] = 0.f; g_At[i] = 0.f; }
    __syncthreads();
    for (int e = t; e < ne; e += 256) atomicAdd(&deg[ei[e]], 1.0f);
    if (t < 96) atomicAdd(&deg[t], 1.0f);
    __syncthreads();
    if (t < 96) dinv[t] = 1.0f / sqrtf(fmaxf(deg[t], 1e-12f));
    __syncthreads();
    for (int e = t; e < ne; e += 256) {
        int r = ei[e], c = ei[ne + e];
        float v = dinv[r] * dinv[c];
        atomicAdd(&g_A[r * 96 + c], v);
        atomicAdd(&g_At[c * 96 + r], v);
    }
    if (t < 96) {
        float v = dinv[t] * dinv[t];
        atomicAdd(&g_A[t * 96 + t], v);
        atomicAdd(&g_At[t * 96 + t], v);
    }
}

// ---------------- fused GCN1+GCN2 (one block = one batch) --------------------
__global__ void __launch_bounds__(256, 2) k_gcn(const float* __restrict__ src,
                                                const float* __restrict__ W1,
                                                const float* __restrict__ b1,
                                                const float* __restrict__ W2,
                                                const float* __restrict__ b2) {
    extern __shared__ float sm[];
    float* sAt = sm;              // [m][n] 96*96
    float* sX  = sAt + 9216;     // [m][c] pad 20
    float* sYt = sX + 1920;     // [c][n] 16*96
    float* sW1 = sYt + 1536;     // [c][f] 16*64
    float* sHt = sW1 + 1024;     // [f][n] 64*96
    float* sW2 = sHt + 6144;     // [f][g] 64*32
    float* sT  = sW2 + 2048;     // [m][g] 96*32
    float* sB1 = sT + 3072;      // 64
    float* sB2 = sB1 + 64;       // 32
    int t = threadIdx.x, b = blockIdx.x;

    for (int i = t; i < 9216; i += 256) sAt[i] = g_At[i];
    const float* xb = src + (size_t)b * 1536;
    for (int i = t; i < 1536; i += 256) { int c = i / 96, m = i % 96; sX[m * 20 + c] = tf32r(xb[i]); }
    for (int i = t; i < 1024; i += 256) sW1[i] = tf32r(W1[i]);
    for (int i = t; i < 2048; i += 256) sW2[i] = tf32r(W2[i]);
    if (t < 64) sB1[t] = b1[t];
    if (t < 32) sB2[t] = b2[t];
    __syncthreads();

    if (t < 96) {   // Y = A@Xq -> sYt[c][n]
        int n0 = (t % 24) * 4, c0 = (t / 24) * 4;
        float acc[4][4] = {};
        for (int m = 0; m < 96; m++) {
            float4 a4 = *(const float4*)&sAt[m * 96 + n0];
            float4 x4 = *(const float4*)&sX[m * 20 + c0];
            float av[4] = {a4.x, a4.y, a4.z, a4.w};
            float xv[4] = {x4.x, x4.y, x4.z, x4.w};
            #pragma unroll
            for (int ci = 0; ci < 4; ci++)
                #pragma unroll
                for (int nj = 0; nj < 4; nj++) acc[ci][nj] += xv[ci] * av[nj];
        }
        #pragma unroll
        for (int ci = 0; ci < 4; ci++)
            #pragma unroll
            for (int nj = 0; nj < 4; nj++) sYt[(c0 + ci) * 96 + n0 + nj] = acc[ci][nj];
    }
    __syncthreads();

    for (int tile = t; tile < 384; tile += 256) {   // H = relu(Y@W1+b1) -> sHt[f][n]
        int n0 = (tile % 24) * 4, f0 = (tile / 24) * 4;
        float acc[4][4] = {};
        #pragma unroll
        for (int c = 0; c < 16; c++) {
            float4 y4 = *(const float4*)&sYt[c * 96 + n0];
            float4 w4 = *(const float4*)&sW1[c * 64 + f0];
            float yv[4] = {y4.x, y4.y, y4.z, y4.w};
            float wv[4] = {w4.x, w4.y, w4.z, w4.w};
            #pragma unroll
            for (int nj = 0; nj < 4; nj++)
                #pragma unroll
                for (int fi = 0; fi < 4; fi++) acc[nj][fi] += yv[nj] * wv[fi];
        }
        #pragma unroll
        for (int fi = 0; fi < 4; fi++)
            #pragma unroll
            for (int nj = 0; nj < 4; nj++)
                sHt[(f0 + fi) * 96 + n0 + nj] = tf32r(fmaxf(acc[nj][fi] + sB1[f0 + fi], 0.f));
    }
    __syncthreads();

    if (t < 192) {   // T = Hq@W2q -> sT[n][g]
        int n0 = (t % 24) * 4, g0 = (t / 24) * 4;
        float acc[4][4] = {};
        for (int f = 0; f < 64; f++) {
            float4 h4 = *(const float4*)&sHt[f * 96 + n0];
            float4 w4 = *(const float4*)&sW2[f * 32 + g0];
            float hv[4] = {h4.x, h4.y, h4.z, h4.w};
            float wv[4] = {w4.x, w4.y, w4.z, w4.w};
            #pragma unroll
            for (int nj = 0; nj < 4; nj++)
                #pragma unroll
                for (int gi = 0; gi < 4; gi++) acc[nj][gi] += hv[nj] * wv[gi];
        }
        #pragma unroll
        for (int nj = 0; nj < 4; nj++)
            #pragma unroll
            for (int gi = 0; gi < 4; gi++) sT[(n0 + nj) * 32 + g0 + gi] = acc[nj][gi];
    }
    __syncthreads();

    if (t < 192) {   // out[g][n] = relu(A@T + b2)
        int n0 = (t % 24) * 4, g0 = (t / 24) * 4;
        float acc[4][4] = {};
        for (int m = 0; m < 96; m++) {
            float4 a4 = *(const float4*)&sAt[m * 96 + n0];
            float4 t4 = *(const float4*)&sT[m * 32 + g0];
            float av[4] = {a4.x, a4.y, a4.z, a4.w};
            float tv[4] = {t4.x, t4.y, t4.z, t4.w};
            #pragma unroll
            for (int nj = 0; nj < 4; nj++)
                #pragma unroll
                for (int gi = 0; gi < 4; gi++) acc[nj][gi] += av[nj] * tv[gi];
        }
        float* out = g_buf2 + (size_t)b * 3072;
        #pragma unroll
        for (int gi = 0; gi < 4; gi++)
            #pragma unroll
            for (int nj = 0; nj < 4; nj++)
                out[(g0 + gi) * 96 + n0 + nj] = fmaxf(acc[nj][gi] + sB2[g0 + gi], 0.f);
    }
}

// ---------------- conv as implicit GEMM on tensor cores (tf32 mma) -----------
// C[M, N] = W[M, K] @ im2col[K, N], N = B*NPOS, K = IC*KK, stride 2.
// 8 warps: warp (wm, wn) computes rows wm*16..+15, cols wn*64..+63.
// IO=0: in g_buf2 -> out g_buf1 ; IO=1: in g_buf1 -> out g_buf2.
template<int M_BLK, int WM, int WN, int KTOT, int KK, int NPOS, int LIN, int PAD, int IO>
__global__ void __launch_bounds__(256, 3) k_convmma(const float* __restrict__ w,
                                                    const float* __restrict__ bias) {
    const float* in = (IO == 0) ? g_buf2 : g_buf1;
    float* outp     = (IO == 0) ? g_buf1 : g_buf2;
    constexpr int N_BLK = WN * 64;
    __shared__ float sA[M_BLK * 36];   // [m][k] pad 36
    __shared__ float sB[N_BLK * 36];   // [n][k] pad 36
    int t = threadIdx.x;
    int warp = t >> 5, lane = t & 31;
    int g = lane >> 2, tg = lane & 3;
    int wm = warp % WM, wn = warp / WM;
    int mbase = blockIdx.y * M_BLK;
    long n0 = (long)blockIdx.x * N_BLK;

    float acc[8][4] = {};

    for (int k0 = 0; k0 < KTOT; k0 += 32) {
        __syncthreads();
        // A tile: weights [M_BLK][32], contiguous in w
        for (int i = t; i < M_BLK * 8; i += 256) {
            int m = i >> 3, k4 = i & 7;
            float4 v = *(const float4*)&w[(size_t)(mbase + m) * KTOT + k0 + k4 * 4];
            v.x = tf32r(v.x); v.y = tf32r(v.y); v.z = tf32r(v.z); v.w = tf32r(v.w);
            *(float4*)&sA[m * 36 + k4 * 4] = v;
        }
        // B tile: im2col [N_BLK][32]
        for (int i = t; i < N_BLK * 32; i += 256) {
            int n = i >> 5, k = i & 31;
            long ng = n0 + n;
            int b = (int)(ng / NPOS), p = (int)(ng % NPOS);
            int kg = k0 + k;
            int ic = kg / KK, kk = kg - ic * KK;
            int pos = p * 2 + kk - PAD;
            float v = 0.f;
            if (pos >= 0 && pos < LIN) v = tf32r(in[(size_t)b * 3072 + ic * LIN + pos]);
            sB[n * 36 + k] = v;
        }
        __syncthreads();
        #pragma unroll
        for (int ks = 0; ks < 4; ks++) {
            int kb = ks * 8;
            int ra = (wm * 16 + g) * 36 + kb + tg;
            uint32_t a0 = __float_as_uint(sA[ra]);
            uint32_t a1 = __float_as_uint(sA[ra + 8 * 36]);
            uint32_t a2 = __float_as_uint(sA[ra + 4]);
            uint32_t a3 = __float_as_uint(sA[ra + 8 * 36 + 4]);
            #pragma unroll
            for (int j = 0; j < 8; j++) {
                int rb = (wn * 64 + j * 8 + g) * 36 + kb + tg;
                uint32_t b0 = __float_as_uint(sB[rb]);
                uint32_t b1 = __float_as_uint(sB[rb + 4]);
                mma_tf32(acc[j], a0, a1, a2, a3, b0, b1);
            }
        }
    }
    int m0 = mbase + wm * 16 + g;
    int m1 = m0 + 8;
    float bi0 = bias[m0], bi1 = bias[m1];
    #pragma unroll
    for (int j = 0; j < 8; j++) {
        long nc = n0 + wn * 64 + j * 8 + 2 * tg;       // NPOS even -> p, p+1 same batch
        int b = (int)(nc / NPOS), p = (int)(nc % NPOS);
        float* ob = outp + (size_t)b * 3072;
        ob[m0 * NPOS + p]     = fmaxf(acc[j][0] + bi0, 0.f);
        ob[m0 * NPOS + p + 1] = fmaxf(acc[j][1] + bi0, 0.f);
        ob[m1 * NPOS + p]     = fmaxf(acc[j][2] + bi1, 0.f);
        ob[m1 * NPOS + p + 1] = fmaxf(acc[j][3] + bi1, 0.f);
    }
}

// ---------------- fc1 via tf32 mma: [8192x3072]@[3072x128] -------------------
// M=128 features (8 warps x 16), N=batch rows (64/block), K=3072.
__global__ void __launch_bounds__(256, 3) k_fc1mma(const float* __restrict__ W,
                                                   const float* __restrict__ bias,
                                                   float* __restrict__ feat_out) {
    __shared__ float sA[32 * 132];   // [k][m] pad 132
    __shared__ float sB[64 * 36];    // [n][k] pad 36
    int t = threadIdx.x;
    int warp = t >> 5, lane = t & 31;
    int g = lane >> 2, tg = lane & 3;
    int wm = warp;
    long n0 = (long)blockIdx.x * 64;
    float acc[8][4] = {};

    for (int k0 = 0; k0 < 3072; k0 += 32) {
        __syncthreads();
        for (int i = t; i < 1024; i += 256) {          // A: W[k][m] -> sA[k][m]
            int k = i >> 5, m4 = i & 31;
            float4 v = *(const float4*)&W[(size_t)(k0 + k) * 128 + m4 * 4];
            v.x = tf32r(v.x); v.y = tf32r(v.y); v.z = tf32r(v.z); v.w = tf32r(v.w);
            *(float4*)&sA[k * 132 + m4 * 4] = v;
        }
        for (int i = t; i < 512; i += 256) {           // B: rows of conv3 output
            int n = i >> 3, k4 = i & 7;
            float4 v = *(const float4*)&g_buf1[(size_t)(n0 + n) * 3072 + k0 + k4 * 4];
            v.x = tf32r(v.x); v.y = tf32r(v.y); v.z = tf32r(v.z); v.w = tf32r(v.w);
            *(float4*)&sB[n * 36 + k4 * 4] = v;
        }
        __syncthreads();
        #pragma unroll
        for (int ks = 0; ks < 4; ks++) {
            int kb = ks * 8;
            uint32_t a0 = __float_as_uint(sA[(kb + tg) * 132 + wm * 16 + g]);
            uint32_t a1 = __float_as_uint(sA[(kb + tg) * 132 + wm * 16 + g + 8]);
            uint32_t a2 = __float_as_uint(sA[(kb + tg + 4) * 132 + wm * 16 + g]);
            uint32_t a3 = __float_as_uint(sA[(kb + tg + 4) * 132 + wm * 16 + g + 8]);
            #pragma unroll
            for (int j = 0; j < 8; j++) {
                int rb = (j * 8 + g) * 36 + kb + tg;
                uint32_t b0 = __float_as_uint(sB[rb]);
                uint32_t b1 = __float_as_uint(sB[rb + 4]);
                mma_tf32(acc[j], a0, a1, a2, a3, b0, b1);
            }
        }
    }
    int m0 = wm * 16 + g, m1 = m0 + 8;
    float bi0 = bias[m0], bi1 = bias[m1];
    #pragma unroll
    for (int j = 0; j < 8; j++) {
        long n = n0 + j * 8 + 2 * tg;
        float f00 = acc[j][0] + bi0, f01 = acc[j][1] + bi0;
        float f10 = acc[j][2] + bi1, f11 = acc[j][3] + bi1;
        feat_out[n * 128 + m0] = f00;       feat_out[(n + 1) * 128 + m0] = f01;
        feat_out[n * 128 + m1] = f10;       feat_out[(n + 1) * 128 + m1] = f11;
        g_buf2[n * 128 + m0] = fmaxf(f00, 0.f); g_buf2[(n + 1) * 128 + m0] = fmaxf(f01, 0.f);
        g_buf2[n * 128 + m1] = fmaxf(f10, 0.f); g_buf2[(n + 1) * 128 + m1] = fmaxf(f11, 0.f);
    }
}

// ---------------- cls1: relu([B,128]@[128,128]+b) ----------------------------
__global__ void k_cls1(const float* __restrict__ W, const float* __restrict__ bias) {
    extern __shared__ float sm[];
    float* sIn = sm;              // [64][129]
    float* sW  = sIn + 64 * 129;  // [128][128]
    int t = threadIdx.x;
    int b0 = blockIdx.x * 64;
    for (int i = t; i < 64 * 128; i += 256) {
        int r = i >> 7, k = i & 127;
        sIn[r * 129 + k] = tf32r(g_buf2[(size_t)(b0 + r) * 128 + k]);
    }
    for (int i = t; i < 128 * 128; i += 256) sW[i] = tf32r(W[i]);
    __syncthreads();
    for (int idx = t; idx < 64 * 128; idx += 256) {
        int r = idx >> 7, n = idx & 127;
        float acc = bias[n];
        #pragma unroll 8
        for (int k = 0; k < 128; k++) acc += sIn[r * 129 + k] * sW[k * 128 + n];
        g_buf1[(size_t)(b0 + r) * 128 + n] = fmaxf(acc, 0.f);
    }
}

// ---------------- cls2: [B,128]@[128,210]+b -> x -----------------------------
__global__ void k_cls2(const float* __restrict__ W, const float* __restrict__ bias,
                       float* __restrict__ out_x) {
    extern __shared__ float sm[];
    float* sIn = sm;              // [64][129]
    float* sW  = sIn + 64 * 129;  // [128][210]
    int t = threadIdx.x;
    int b0 = blockIdx.x * 64;
    for (int i = t; i < 64 * 128; i += 256) {
        int r = i >> 7, k = i & 127;
        sIn[r * 129 + k] = tf32r(g_buf1[(size_t)(b0 + r) * 128 + k]);
    }
    for (int i = t; i < 128 * 210; i += 256) sW[i] = tf32r(W[i]);
    __syncthreads();
    for (int idx = t; idx < 64 * 210; idx += 256) {
        int r = idx / 210, n = idx % 210;
        float acc = bias[n];
        #pragma unroll 8
        for (int k = 0; k < 128; k++) acc += sIn[r * 129 + k] * sW[k * 210 + n];
        out_x[(size_t)(b0 + r) * 210 + n] = acc;
    }
}

// ---------------- launch ------------------------------------------------------
extern "C" void kernel_launch(void* const* d_in, const int* in_sizes, int n_in,
                              void* d_out, int out_size) {
    const float* src     = (const float*)d_in[0];
    const int*   ei      = (const int*)d_in[1];
    const float* gcn1_w  = (const float*)d_in[2];
    const float* gcn1_b  = (const float*)d_in[3];
    const float* gcn2_w  = (const float*)d_in[4];
    const float* gcn2_b  = (const float*)d_in[5];
    const float* conv1_w = (const float*)d_in[6];
    const float* conv1_b = (const float*)d_in[7];
    const float* conv2_w = (const float*)d_in[8];
    const float* conv2_b = (const float*)d_in[9];
    const float* conv3_w = (const float*)d_in[10];
    const float* conv3_b = (const float*)d_in[11];
    const float* fc1_w   = (const float*)d_in[12];
    const float* fc1_b   = (const float*)d_in[13];
    const float* cls1_w  = (const float*)d_in[14];
    const float* cls1_b  = (const float*)d_in[15];
    const float* cls2_w  = (const float*)d_in[16];
    const float* cls2_b  = (const float*)d_in[17];

    int ne = in_sizes[1] / 2;

    float* out   = (float*)d_out;
    float* out_x = out;                          // [B,210]
    float* out_f = out + (size_t)BB * 210;       // [B,128]

    const int GCN_SMEM = (9216 + 1920 + 1536 + 1024 + 6144 + 2048 + 3072 + 96) * 4;
    cudaFuncSetAttribute(k_gcn,  cudaFuncAttributeMaxDynamicSharedMemorySize, GCN_SMEM);
    cudaFuncSetAttribute(k_cls1, cudaFuncAttributeMaxDynamicSharedMemorySize, 98560);
    cudaFuncSetAttribute(k_cls2, cudaFuncAttributeMaxDynamicSharedMemorySize, 140544);

    k_build_adj<<<1, 256>>>(ei, ne);
    k_gcn<<<BB, 256, GCN_SMEM>>>(src, gcn1_w, gcn1_b, gcn2_w, gcn2_b);

    // conv1: M=64, K=224, NPOS=48, LIN=96, pad 3;  N = 8192*48, N_BLK=128
    k_convmma<64, 4, 2, 224, 7, 48, 96, 3, 0><<<dim3(3072, 1), 256>>>(conv1_w, conv1_b);
    // conv2: M=128, K=320, NPOS=24, LIN=48, pad 2; N = 8192*24, N_BLK=64
    k_convmma<128, 8, 1, 320, 5, 24, 48, 2, 1><<<dim3(3072, 1), 256>>>(conv2_w, conv2_b);
    // conv3: M=256 (2 M-blocks), K=384, NPOS=12, LIN=24, pad 1; N = 8192*12
    k_convmma<128, 8, 1, 384, 3, 12, 24, 1, 0><<<dim3(1536, 2), 256>>>(conv3_w, conv3_b);

    k_fc1mma<<<128, 256>>>(fc1_w, fc1_b, out_f);
    k_cls1<<<BB / 64, 256, 98560>>>(cls1_w, cls1_b);
    k_cls2<<<BB / 64, 256, 140544>>>(cls2_w, cls2_b, out_x);
}

// round 9
// speedup vs baseline: 2.5299x; 1.0190x over previous
#include <cuda_runtime.h>
#include <cstdint>
#include <math.h>

#define BB 8192

// TF32 operand rounding (matches cuBLAS/cuDNN TF32)
__device__ __forceinline__ float tf32r(float x) {
    uint32_t u;
    asm("cvt.rna.tf32.f32 %0, %1;" : "=r"(u) : "f"(x));
    return __uint_as_float(u);
}

// m16n8k8 tf32 mma: D = A*B + D (fp32 accum)
__device__ __forceinline__ void mma_tf32(float c[4],
                                         uint32_t a0, uint32_t a1, uint32_t a2, uint32_t a3,
                                         uint32_t b0, uint32_t b1) {
    asm volatile(
        "mma.sync.aligned.m16n8k8.row.col.f32.tf32.tf32.f32 "
        "{%0,%1,%2,%3}, {%4,%5,%6,%7}, {%8,%9}, {%0,%1,%2,%3};"
        : "+f"(c[0]), "+f"(c[1]), "+f"(c[2]), "+f"(c[3])
        : "r"(a0), "r"(a1), "r"(a2), "r"(a3), "r"(b0), "r"(b1));
}

// ---------------- scratch ----------------------------------------------------
__device__ float g_At[96 * 96];                 // A^T: [m][n]
__device__ float g_buf1[(size_t)BB * 6144];     // gcn: Y at [0,B*1536), T at [B*1536,B*4608)
__device__ float g_buf2[(size_t)BB * 3072];

// ---------------- build dense normalized adjacency (transposed) --------------
__global__ void k_build_adj(const int* __restrict__ ei, int ne) {
    __shared__ float deg[96];
    __shared__ float dinv[96];
    int t = threadIdx.x;
    if (t < 96) deg[t] = 0.f;
    for (int i = t; i < 9216; i += 256) g_At[i] = 0.f;
    __syncthreads();
    for (int e = t; e < ne; e += 256) atomicAdd(&deg[ei[e]], 1.0f);
    if (t < 96) atomicAdd(&deg[t], 1.0f);
    __syncthreads();
    if (t < 96) dinv[t] = 1.0f / sqrtf(fmaxf(deg[t], 1e-12f));
    __syncthreads();
    for (int e = t; e < ne; e += 256) {
        int r = ei[e], c = ei[ne + e];
        atomicAdd(&g_At[c * 96 + r], dinv[r] * dinv[c]);   // [m][n]
    }
    if (t < 96) atomicAdd(&g_At[t * 96 + t], dinv[t] * dinv[t]);
}

// ---------------- gcnA: Y[b,n,c] = sum_m A[n][m] Xq[b,m,c] (exact) -----------
// 8 batches/block, A resident, 768 tiles = 3/thread.
__global__ void __launch_bounds__(256, 2) k_gcnA(const float* __restrict__ src) {
    extern __shared__ float sm[];
    float* sAt = sm;              // [m][n] 9216
    float* sX  = sAt + 9216;      // [bi][m*20+c] 8*1920
    int t = threadIdx.x;
    int b0 = blockIdx.x * 8;

    for (int i = t; i < 9216; i += 256) sAt[i] = g_At[i];
    for (int i = t; i < 8 * 1536; i += 256) {
        int bi = i / 1536, r = i % 1536, c = r / 96, m = r % 96;
        sX[bi * 1920 + m * 20 + c] = tf32r(src[(size_t)(b0 + bi) * 1536 + r]);
    }
    __syncthreads();

    for (int tile = t; tile < 768; tile += 256) {
        int bi = tile / 96, rem = tile % 96;
        int n0 = (rem % 24) * 4, c0 = (rem / 24) * 4;
        const float* X = sX + bi * 1920;
        float acc[4][4] = {};
        for (int m = 0; m < 96; m++) {
            float4 a4 = *(const float4*)&sAt[m * 96 + n0];
            float4 x4 = *(const float4*)&X[m * 20 + c0];
            float av[4] = {a4.x, a4.y, a4.z, a4.w};
            float xv[4] = {x4.x, x4.y, x4.z, x4.w};
            #pragma unroll
            for (int nj = 0; nj < 4; nj++)
                #pragma unroll
                for (int ci = 0; ci < 4; ci++) acc[nj][ci] += av[nj] * xv[ci];
        }
        float* yb = g_buf1 + (size_t)(b0 + bi) * 1536;
        #pragma unroll
        for (int nj = 0; nj < 4; nj++)
            *(float4*)&yb[(n0 + nj) * 16 + c0] =
                make_float4(acc[nj][0], acc[nj][1], acc[nj][2], acc[nj][3]);
    }
}

// ---------------- gcnB: per row: H = tf32r(relu(Y@W1q+b1)); T = Hq@W2q -------
__global__ void __launch_bounds__(256) k_gcnB(const float* __restrict__ W1,
                                              const float* __restrict__ b1,
                                              const float* __restrict__ W2) {
    __shared__ float sW1[1024];   // [c][f]
    __shared__ float sW2[2048];   // [f][g]
    __shared__ float sB1[64];
    int t = threadIdx.x;
    for (int i = t; i < 1024; i += 256) sW1[i] = tf32r(W1[i]);
    for (int i = t; i < 2048; i += 256) sW2[i] = tf32r(W2[i]);
    if (t < 64) sB1[t] = b1[t];
    __syncthreads();

    size_t row = (size_t)blockIdx.x * 256 + t;
    const float4* y4 = (const float4*)(g_buf1 + row * 16);
    float Y[16];
    #pragma unroll
    for (int i = 0; i < 4; i++) {
        float4 v = y4[i];
        Y[4 * i] = v.x; Y[4 * i + 1] = v.y; Y[4 * i + 2] = v.z; Y[4 * i + 3] = v.w;
    }
    float H[64];
    #pragma unroll
    for (int f = 0; f < 64; f++) H[f] = sB1[f];
    #pragma unroll
    for (int c = 0; c < 16; c++) {
        float yc = Y[c];
        #pragma unroll
        for (int f = 0; f < 64; f++) H[f] += yc * sW1[c * 64 + f];
    }
    #pragma unroll
    for (int f = 0; f < 64; f++) H[f] = tf32r(fmaxf(H[f], 0.f));
    float T[32] = {};
    #pragma unroll
    for (int f = 0; f < 64; f++) {
        float hf = H[f];
        #pragma unroll
        for (int g = 0; g < 32; g++) T[g] += hf * sW2[f * 32 + g];
    }
    float* tp = g_buf1 + (size_t)BB * 1536 + row * 32;
    #pragma unroll
    for (int g = 0; g < 32; g += 4)
        *(float4*)&tp[g] = make_float4(T[g], T[g + 1], T[g + 2], T[g + 3]);
}

// ---------------- gcnC: out[b][g][n] = tf32r(relu(A@T + b2)) -----------------
// 4 batches/block, 768 tiles = 3/thread; output pre-rounded for conv1.
__global__ void __launch_bounds__(256, 2) k_gcnC(const float* __restrict__ b2) {
    extern __shared__ float sm[];
    float* sAt = sm;              // 9216
    float* sT  = sAt + 9216;      // 4*3072
    __shared__ float sB2[32];
    int t = threadIdx.x;
    int b0 = blockIdx.x * 4;

    for (int i = t; i < 9216; i += 256) sAt[i] = g_At[i];
    const float* Tg = g_buf1 + (size_t)BB * 1536 + (size_t)b0 * 3072;
    for (int i = t; i < 4 * 3072; i += 256) sT[i] = Tg[i];
    if (t < 32) sB2[t] = b2[t];
    __syncthreads();

    for (int tile = t; tile < 768; tile += 256) {
        int bi = tile / 192, rem = tile % 192;
        int n0 = (rem % 24) * 4, g0 = (rem / 24) * 4;
        const float* Tb = sT + bi * 3072;
        float acc[4][4] = {};
        for (int m = 0; m < 96; m++) {
            float4 a4 = *(const float4*)&sAt[m * 96 + n0];
            float4 t4 = *(const float4*)&Tb[m * 32 + g0];
            float av[4] = {a4.x, a4.y, a4.z, a4.w};
            float tv[4] = {t4.x, t4.y, t4.z, t4.w};
            #pragma unroll
            for (int nj = 0; nj < 4; nj++)
                #pragma unroll
                for (int gi = 0; gi < 4; gi++) acc[nj][gi] += av[nj] * tv[gi];
        }
        float* ob = g_buf2 + (size_t)(b0 + bi) * 3072;
        #pragma unroll
        for (int gi = 0; gi < 4; gi++) {
            float bg = sB2[g0 + gi];
            *(float4*)&ob[(g0 + gi) * 96 + n0] = make_float4(
                tf32r(fmaxf(acc[0][gi] + bg, 0.f)), tf32r(fmaxf(acc[1][gi] + bg, 0.f)),
                tf32r(fmaxf(acc[2][gi] + bg, 0.f)), tf32r(fmaxf(acc[3][gi] + bg, 0.f)));
        }
    }
}

// ---------------- conv as implicit GEMM on tensor cores (tf32 mma) -----------
// Inputs are pre-rounded tf32 by the producer; outputs stored pre-rounded.
template<int M_BLK, int WM, int WN, int KTOT, int KK, int NPOS, int LIN, int PAD, int IO>
__global__ void __launch_bounds__(256, 3) k_convmma(const float* __restrict__ w,
                                                    const float* __restrict__ bias) {
    const float* in = (IO == 0) ? g_buf2 : g_buf1;
    float* outp     = (IO == 0) ? g_buf1 : g_buf2;
    constexpr int N_BLK = WN * 64;
    __shared__ float sA[M_BLK * 36];   // [m][k] pad 36
    __shared__ float sB[N_BLK * 36];   // [n][k] pad 36
    int t = threadIdx.x;
    int warp = t >> 5, lane = t & 31;
    int g = lane >> 2, tg = lane & 3;
    int wm = warp % WM, wn = warp / WM;
    int mbase = blockIdx.y * M_BLK;
    long n0 = (long)blockIdx.x * N_BLK;

    float acc[8][4] = {};

    for (int k0 = 0; k0 < KTOT; k0 += 32) {
        __syncthreads();
        for (int i = t; i < M_BLK * 8; i += 256) {
            int m = i >> 3, k4 = i & 7;
            float4 v = *(const float4*)&w[(size_t)(mbase + m) * KTOT + k0 + k4 * 4];
            v.x = tf32r(v.x); v.y = tf32r(v.y); v.z = tf32r(v.z); v.w = tf32r(v.w);
            *(float4*)&sA[m * 36 + k4 * 4] = v;
        }
        for (int i = t; i < N_BLK * 32; i += 256) {
            int n = i >> 5, k = i & 31;
            long ng = n0 + n;
            int b = (int)(ng / NPOS), p = (int)(ng % NPOS);
            int kg = k0 + k;
            int ic = kg / KK, kk = kg - ic * KK;
            int pos = p * 2 + kk - PAD;
            float v = 0.f;
            if (pos >= 0 && pos < LIN) v = in[(size_t)b * 3072 + ic * LIN + pos];
            sB[n * 36 + k] = v;
        }
        __syncthreads();
        #pragma unroll
        for (int ks = 0; ks < 4; ks++) {
            int kb = ks * 8;
            int ra = (wm * 16 + g) * 36 + kb + tg;
            uint32_t a0 = __float_as_uint(sA[ra]);
            uint32_t a1 = __float_as_uint(sA[ra + 8 * 36]);
            uint32_t a2 = __float_as_uint(sA[ra + 4]);
            uint32_t a3 = __float_as_uint(sA[ra + 8 * 36 + 4]);
            #pragma unroll
            for (int j = 0; j < 8; j++) {
                int rb = (wn * 64 + j * 8 + g) * 36 + kb + tg;
                uint32_t b0 = __float_as_uint(sB[rb]);
                uint32_t b1 = __float_as_uint(sB[rb + 4]);
                mma_tf32(acc[j], a0, a1, a2, a3, b0, b1);
            }
        }
    }
    int m0 = mbase + wm * 16 + g;
    int m1 = m0 + 8;
    float bi0 = bias[m0], bi1 = bias[m1];
    #pragma unroll
    for (int j = 0; j < 8; j++) {
        long nc = n0 + wn * 64 + j * 8 + 2 * tg;
        int b = (int)(nc / NPOS), p = (int)(nc % NPOS);
        float* ob = outp + (size_t)b * 3072;
        ob[m0 * NPOS + p]     = tf32r(fmaxf(acc[j][0] + bi0, 0.f));
        ob[m0 * NPOS + p + 1] = tf32r(fmaxf(acc[j][1] + bi0, 0.f));
        ob[m1 * NPOS + p]     = tf32r(fmaxf(acc[j][2] + bi1, 0.f));
        ob[m1 * NPOS + p + 1] = tf32r(fmaxf(acc[j][3] + bi1, 0.f));
    }
}

// ---------------- fc1 via tf32 mma: [8192x3072]@[3072x128] -------------------
__global__ void __launch_bounds__(256, 3) k_fc1mma(const float* __restrict__ W,
                                                   const float* __restrict__ bias,
                                                   float* __restrict__ feat_out) {
    __shared__ float sA[32 * 132];   // [k][m] pad 132
    __shared__ float sB[64 * 36];    // [n][k] pad 36
    int t = threadIdx.x;
    int warp = t >> 5, lane = t & 31;
    int g = lane >> 2, tg = lane & 3;
    int wm = warp;
    long n0 = (long)blockIdx.x * 64;
    float acc[8][4] = {};

    for (int k0 = 0; k0 < 3072; k0 += 32) {
        __syncthreads();
        for (int i = t; i < 1024; i += 256) {
            int k = i >> 5, m4 = i & 31;
            float4 v = *(const float4*)&W[(size_t)(k0 + k) * 128 + m4 * 4];
            v.x = tf32r(v.x); v.y = tf32r(v.y); v.z = tf32r(v.z); v.w = tf32r(v.w);
            *(float4*)&sA[k * 132 + m4 * 4] = v;
        }
        for (int i = t; i < 512; i += 256) {       // conv3 output is pre-rounded
            int n = i >> 3, k4 = i & 7;
            float4 v = *(const float4*)&g_buf1[(size_t)(n0 + n) * 3072 + k0 + k4 * 4];
            *(float4*)&sB[n * 36 + k4 * 4] = v;
        }
        __syncthreads();
        #pragma unroll
        for (int ks = 0; ks < 4; ks++) {
            int kb = ks * 8;
            uint32_t a0 = __float_as_uint(sA[(kb + tg) * 132 + wm * 16 + g]);
            uint32_t a1 = __float_as_uint(sA[(kb + tg) * 132 + wm * 16 + g + 8]);
            uint32_t a2 = __float_as_uint(sA[(kb + tg + 4) * 132 + wm * 16 + g]);
            uint32_t a3 = __float_as_uint(sA[(kb + tg + 4) * 132 + wm * 16 + g + 8]);
            #pragma unroll
            for (int j = 0; j < 8; j++) {
                int rb = (j * 8 + g) * 36 + kb + tg;
                uint32_t b0 = __float_as_uint(sB[rb]);
                uint32_t b1 = __float_as_uint(sB[rb + 4]);
                mma_tf32(acc[j], a0, a1, a2, a3, b0, b1);
            }
        }
    }
    int m0 = wm * 16 + g, m1 = m0 + 8;
    float bi0 = bias[m0], bi1 = bias[m1];
    #pragma unroll
    for (int j = 0; j < 8; j++) {
        long n = n0 + j * 8 + 2 * tg;
        float f00 = acc[j][0] + bi0, f01 = acc[j][1] + bi0;
        float f10 = acc[j][2] + bi1, f11 = acc[j][3] + bi1;
        feat_out[n * 128 + m0] = f00;       feat_out[(n + 1) * 128 + m0] = f01;
        feat_out[n * 128 + m1] = f10;       feat_out[(n + 1) * 128 + m1] = f11;
        g_buf2[n * 128 + m0] = tf32r(fmaxf(f00, 0.f));
        g_buf2[(n + 1) * 128 + m0] = tf32r(fmaxf(f01, 0.f));
        g_buf2[n * 128 + m1] = tf32r(fmaxf(f10, 0.f));
        g_buf2[(n + 1) * 128 + m1] = tf32r(fmaxf(f11, 0.f));
    }
}

// ---------------- cls1: relu([B,128]@[128,128]+b), pre-rounded out -----------
__global__ void k_cls1(const float* __restrict__ W, const float* __restrict__ bias) {
    extern __shared__ float sm[];
    float* sIn = sm;              // [64][129]
    float* sW  = sIn + 64 * 129;  // [128][128]
    int t = threadIdx.x;
    int b0 = blockIdx.x * 64;
    for (int i = t; i < 64 * 128; i += 256) {
        int r = i >> 7, k = i & 127;
        sIn[r * 129 + k] = g_buf2[(size_t)(b0 + r) * 128 + k];   // pre-rounded
    }
    for (int i = t; i < 128 * 128; i += 256) sW[i] = tf32r(W[i]);
    __syncthreads();
    for (int idx = t; idx < 64 * 128; idx += 256) {
        int r = idx >> 7, n = idx & 127;
        float acc = bias[n];
        #pragma unroll 8
        for (int k = 0; k < 128; k++) acc += sIn[r * 129 + k] * sW[k * 128 + n];
        g_buf1[(size_t)(b0 + r) * 128 + n] = tf32r(fmaxf(acc, 0.f));
    }
}

// ---------------- cls2: [B,128]@[128,210]+b -> x -----------------------------
__global__ void k_cls2(const float* __restrict__ W, const float* __restrict__ bias,
                       float* __restrict__ out_x) {
    extern __shared__ float sm[];
    float* sIn = sm;              // [64][129]
    float* sW  = sIn + 64 * 129;  // [128][210]
    int t = threadIdx.x;
    int b0 = blockIdx.x * 64;
    for (int i = t; i < 64 * 128; i += 256) {
        int r = i >> 7, k = i & 127;
        sIn[r * 129 + k] = g_buf1[(size_t)(b0 + r) * 128 + k];   // pre-rounded
    }
    for (int i = t; i < 128 * 210; i += 256) sW[i] = tf32r(W[i]);
    __syncthreads();
    for (int idx = t; idx < 64 * 210; idx += 256) {
        int r = idx / 210, n = idx % 210;
        float acc = bias[n];
        #pragma unroll 8
        for (int k = 0; k < 128; k++) acc += sIn[r * 129 + k] * sW[k * 210 + n];
        out_x[(size_t)(b0 + r) * 210 + n] = acc;
    }
}

// ---------------- launch ------------------------------------------------------
extern "C" void kernel_launch(void* const* d_in, const int* in_sizes, int n_in,
                              void* d_out, int out_size) {
    const float* src     = (const float*)d_in[0];
    const int*   ei      = (const int*)d_in[1];
    const float* gcn1_w  = (const float*)d_in[2];
    const float* gcn1_b  = (const float*)d_in[3];
    const float* gcn2_w  = (const float*)d_in[4];
    const float* gcn2_b  = (const float*)d_in[5];
    const float* conv1_w = (const float*)d_in[6];
    const float* conv1_b = (const float*)d_in[7];
    const float* conv2_w = (const float*)d_in[8];
    const float* conv2_b = (const float*)d_in[9];
    const float* conv3_w = (const float*)d_in[10];
    const float* conv3_b = (const float*)d_in[11];
    const float* fc1_w   = (const float*)d_in[12];
    const float* fc1_b   = (const float*)d_in[13];
    const float* cls1_w  = (const float*)d_in[14];
    const float* cls1_b  = (const float*)d_in[15];
    const float* cls2_w  = (const float*)d_in[16];
    const float* cls2_b  = (const float*)d_in[17];

    int ne = in_sizes[1] / 2;

    float* out   = (float*)d_out;
    float* out_x = out;                          // [B,210]
    float* out_f = out + (size_t)BB * 210;       // [B,128]

    const int GCNA_SMEM = (9216 + 8 * 1920) * 4;   // 98304
    const int GCNC_SMEM = (9216 + 4 * 3072) * 4;   // 86016

    cudaFuncSetAttribute(k_gcnA, cudaFuncAttributeMaxDynamicSharedMemorySize, GCNA_SMEM);
    cudaFuncSetAttribute(k_gcnC, cudaFuncAttributeMaxDynamicSharedMemorySize, GCNC_SMEM);
    cudaFuncSetAttribute(k_cls1, cudaFuncAttributeMaxDynamicSharedMemorySize, 98560);
    cudaFuncSetAttribute(k_cls2, cudaFuncAttributeMaxDynamicSharedMemorySize, 140544);

    k_build_adj<<<1, 256>>>(ei, ne);
    k_gcnA<<<BB / 8, 256, GCNA_SMEM>>>(src);
    k_gcnB<<<BB * 96 / 256, 256>>>(gcn1_w, gcn1_b, gcn2_w);
    k_gcnC<<<BB / 4, 256, GCNC_SMEM>>>(gcn2_b);

    // conv1: M=64, K=224, NPOS=48, LIN=96, pad 3
    k_convmma<64, 4, 2, 224, 7, 48, 96, 3, 0><<<dim3(3072, 1), 256>>>(conv1_w, conv1_b);
    // conv2: M=128, K=320, NPOS=24, LIN=48, pad 2
    k_convmma<128, 8, 1, 320, 5, 24, 48, 2, 1><<<dim3(3072, 1), 256>>>(conv2_w, conv2_b);
    // conv3: M=256 (2 M-blocks), K=384, NPOS=12, LIN=24, pad 1
    k_convmma<128, 8, 1, 384, 3, 12, 24, 1, 0><<<dim3(1536, 2), 256>>>(conv3_w, conv3_b);

    k_fc1mma<<<128, 256>>>(fc1_w, fc1_b, out_f);
    k_cls1<<<BB / 64, 256, 98560>>>(cls1_w, cls1_b);
    k_cls2<<<BB / 64, 256, 140544>>>(cls2_w, cls2_b, out_x);
}

// round 10
// speedup vs baseline: 2.9097x; 1.1501x over previous
#include <cuda_runtime.h>
#include <cstdint>
#include <math.h>

#define BB 8192

__device__ __forceinline__ float tf32r(float x) {
    uint32_t u;
    asm("cvt.rna.tf32.f32 %0, %1;" : "=r"(u) : "f"(x));
    return __uint_as_float(u);
}

__device__ __forceinline__ void mma_tf32(float c[4],
                                         uint32_t a0, uint32_t a1, uint32_t a2, uint32_t a3,
                                         uint32_t b0, uint32_t b1) {
    asm volatile(
        "mma.sync.aligned.m16n8k8.row.col.f32.tf32.tf32.f32 "
        "{%0,%1,%2,%3}, {%4,%5,%6,%7}, {%8,%9}, {%0,%1,%2,%3};"
        : "+f"(c[0]), "+f"(c[1]), "+f"(c[2]), "+f"(c[3])
        : "r"(a0), "r"(a1), "r"(a2), "r"(a3), "r"(b0), "r"(b1));
}

// ---------------- scratch ----------------------------------------------------
__device__ float g_A[96 * 96];                  // A: [n][m]
__device__ float g_buf1[(size_t)BB * 6144];     // Y | T | cls1-out
__device__ float g_buf2[(size_t)BB * 3072];

// ---------------- build dense normalized adjacency ---------------------------
__global__ void k_build_adj(const int* __restrict__ ei, int ne) {
    __shared__ float deg[96];
    __shared__ float dinv[96];
    int t = threadIdx.x;
    if (t < 96) deg[t] = 0.f;
    for (int i = t; i < 9216; i += 256) g_A[i] = 0.f;
    __syncthreads();
    for (int e = t; e < ne; e += 256) atomicAdd(&deg[ei[e]], 1.0f);
    if (t < 96) atomicAdd(&deg[t], 1.0f);
    __syncthreads();
    if (t < 96) dinv[t] = 1.0f / sqrtf(fmaxf(deg[t], 1e-12f));
    __syncthreads();
    for (int e = t; e < ne; e += 256) {
        int r = ei[e], c = ei[ne + e];
        atomicAdd(&g_A[r * 96 + c], dinv[r] * dinv[c]);
    }
    if (t < 96) atomicAdd(&g_A[t * 96 + t], dinv[t] * dinv[t]);
}

// ---------------- gcnA via mma: Y[n,(b,c)] = A@Xq ----------------------------
__global__ void __launch_bounds__(256, 3) k_gcnAmma(const float* __restrict__ src) {
    __shared__ float sA[128 * 36];
    __shared__ float sB[64 * 36];
    int t = threadIdx.x;
    int warp = t >> 5, lane = t & 31;
    int g = lane >> 2, tg = lane & 3;
    long n0 = (long)blockIdx.x * 64;
    float acc[8][4] = {};

    for (int k0 = 0; k0 < 96; k0 += 32) {
        __syncthreads();
        for (int i = t; i < 128 * 8; i += 256) {
            int m = i >> 3, k4 = i & 7;
            float4 v = make_float4(0.f, 0.f, 0.f, 0.f);
            if (m < 96) {
                v = *(const float4*)&g_A[m * 96 + k0 + k4 * 4];
                v.x = tf32r(v.x); v.y = tf32r(v.y); v.z = tf32r(v.z); v.w = tf32r(v.w);
            }
            *(float4*)&sA[m * 36 + k4 * 4] = v;
        }
        for (int i = t; i < 64 * 32; i += 256) {
            int n = i >> 5, k = i & 31;
            long col = n0 + n;
            int b = (int)(col >> 4), c = (int)(col & 15);
            sB[n * 36 + k] = tf32r(src[(size_t)b * 1536 + c * 96 + k0 + k]);
        }
        __syncthreads();
        #pragma unroll
        for (int ks = 0; ks < 4; ks++) {
            int kb = ks * 8;
            int ra = (warp * 16 + g) * 36 + kb + tg;
            uint32_t a0 = __float_as_uint(sA[ra]);
            uint32_t a1 = __float_as_uint(sA[ra + 8 * 36]);
            uint32_t a2 = __float_as_uint(sA[ra + 4]);
            uint32_t a3 = __float_as_uint(sA[ra + 8 * 36 + 4]);
            #pragma unroll
            for (int j = 0; j < 8; j++) {
                int rb = (j * 8 + g) * 36 + kb + tg;
                uint32_t b0 = __float_as_uint(sB[rb]);
                uint32_t b1 = __float_as_uint(sB[rb + 4]);
                mma_tf32(acc[j], a0, a1, a2, a3, b0, b1);
            }
        }
    }
    int m0 = warp * 16 + g, m1 = m0 + 8;
    if (m0 < 96) {
        #pragma unroll
        for (int j = 0; j < 8; j++) {
            long nc = n0 + j * 8 + 2 * tg;
            int b = (int)(nc >> 4), c = (int)(nc & 15);
            float* yb = g_buf1 + (size_t)b * 1536;
            yb[m0 * 16 + c]     = acc[j][0];
            yb[m0 * 16 + c + 1] = acc[j][1];
            yb[m1 * 16 + c]     = acc[j][2];
            yb[m1 * 16 + c + 1] = acc[j][3];
        }
    }
}

// ---------------- gcnB: per row: H = tf32r(relu(Y@W1q+b1)); T = Hq@W2q -------
__global__ void __launch_bounds__(256) k_gcnB(const float* __restrict__ W1,
                                              const float* __restrict__ b1,
                                              const float* __restrict__ W2) {
    __shared__ float sW1[1024];
    __shared__ float sW2[2048];
    __shared__ float sB1[64];
    int t = threadIdx.x;
    for (int i = t; i < 1024; i += 256) sW1[i] = tf32r(W1[i]);
    for (int i = t; i < 2048; i += 256) sW2[i] = tf32r(W2[i]);
    if (t < 64) sB1[t] = b1[t];
    __syncthreads();

    size_t row = (size_t)blockIdx.x * 256 + t;
    const float4* y4 = (const float4*)(g_buf1 + row * 16);
    float Y[16];
    #pragma unroll
    for (int i = 0; i < 4; i++) {
        float4 v = y4[i];
        Y[4 * i] = v.x; Y[4 * i + 1] = v.y; Y[4 * i + 2] = v.z; Y[4 * i + 3] = v.w;
    }
    float H[64];
    #pragma unroll
    for (int f = 0; f < 64; f++) H[f] = sB1[f];
    #pragma unroll
    for (int c = 0; c < 16; c++) {
        float yc = Y[c];
        #pragma unroll
        for (int f = 0; f < 64; f++) H[f] += yc * sW1[c * 64 + f];
    }
    #pragma unroll
    for (int f = 0; f < 64; f++) H[f] = tf32r(fmaxf(H[f], 0.f));
    float T[32] = {};
    #pragma unroll
    for (int f = 0; f < 64; f++) {
        float hf = H[f];
        #pragma unroll
        for (int g = 0; g < 32; g++) T[g] += hf * sW2[f * 32 + g];
    }
    float* tp = g_buf1 + (size_t)BB * 1536 + row * 32;
    #pragma unroll
    for (int g = 0; g < 32; g += 4)
        *(float4*)&tp[g] = make_float4(T[g], T[g + 1], T[g + 2], T[g + 3]);
}

// ---------------- gcnC via mma: out[n,(b,g)] = relu(A@Tq + b2) ---------------
__global__ void __launch_bounds__(256, 3) k_gcnCmma(const float* __restrict__ b2) {
    __shared__ float sA[128 * 36];
    __shared__ float sB[64 * 36];
    int t = threadIdx.x;
    int warp = t >> 5, lane = t & 31;
    int g = lane >> 2, tg = lane & 3;
    long n0 = (long)blockIdx.x * 64;
    int b0 = blockIdx.x * 2;
    const float* T = g_buf1 + (size_t)BB * 1536;
    float acc[8][4] = {};

    for (int k0 = 0; k0 < 96; k0 += 32) {
        __syncthreads();
        for (int i = t; i < 128 * 8; i += 256) {
            int m = i >> 3, k4 = i & 7;
            float4 v = make_float4(0.f, 0.f, 0.f, 0.f);
            if (m < 96) {
                v = *(const float4*)&g_A[m * 96 + k0 + k4 * 4];
                v.x = tf32r(v.x); v.y = tf32r(v.y); v.z = tf32r(v.z); v.w = tf32r(v.w);
            }
            *(float4*)&sA[m * 36 + k4 * 4] = v;
        }
        for (int i = t; i < 2048; i += 256) {      // T[b][m][g] -> sB[(bi*32+g)][m]
            int bi = i >> 10, rem = i & 1023, m = rem >> 5, gg = rem & 31;
            sB[(bi * 32 + gg) * 36 + m] =
                tf32r(T[(size_t)(b0 + bi) * 3072 + (k0 + m) * 32 + gg]);
        }
        __syncthreads();
        #pragma unroll
        for (int ks = 0; ks < 4; ks++) {
            int kb = ks * 8;
            int ra = (warp * 16 + g) * 36 + kb + tg;
            uint32_t a0 = __float_as_uint(sA[ra]);
            uint32_t a1 = __float_as_uint(sA[ra + 8 * 36]);
            uint32_t a2 = __float_as_uint(sA[ra + 4]);
            uint32_t a3 = __float_as_uint(sA[ra + 8 * 36 + 4]);
            #pragma unroll
            for (int j = 0; j < 8; j++) {
                int rb = (j * 8 + g) * 36 + kb + tg;
                uint32_t b0f = __float_as_uint(sB[rb]);
                uint32_t b1f = __float_as_uint(sB[rb + 4]);
                mma_tf32(acc[j], a0, a1, a2, a3, b0f, b1f);
            }
        }
    }
    int m0 = warp * 16 + g, m1 = m0 + 8;
    if (m0 < 96) {
        #pragma unroll
        for (int j = 0; j < 8; j++) {
            long nc = n0 + j * 8 + 2 * tg;
            int b = (int)(nc >> 5), gg = (int)(nc & 31);
            float bg0 = b2[gg], bg1 = b2[gg + 1];
            float* ob = g_buf2 + (size_t)b * 3072;
            ob[gg * 96 + m0]       = tf32r(fmaxf(acc[j][0] + bg0, 0.f));
            ob[(gg + 1) * 96 + m0] = tf32r(fmaxf(acc[j][1] + bg1, 0.f));
            ob[gg * 96 + m1]       = tf32r(fmaxf(acc[j][2] + bg0, 0.f));
            ob[(gg + 1) * 96 + m1] = tf32r(fmaxf(acc[j][3] + bg1, 0.f));
        }
    }
}

// ---------------- conv as implicit GEMM on tensor cores ----------------------
template<int M_BLK, int WM, int WN, int KTOT, int KK, int NPOS, int LIN, int PAD, int IO>
__global__ void __launch_bounds__(256, 3) k_convmma(const float* __restrict__ w,
                                                    const float* __restrict__ bias) {
    const float* in = (IO == 0) ? g_buf2 : g_buf1;
    float* outp     = (IO == 0) ? g_buf1 : g_buf2;
    constexpr int N_BLK = WN * 64;
    __shared__ float sA[M_BLK * 36];
    __shared__ float sB[N_BLK * 36];
    int t = threadIdx.x;
    int warp = t >> 5, lane = t & 31;
    int g = lane >> 2, tg = lane & 3;
    int wm = warp % WM, wn = warp / WM;
    int mbase = blockIdx.y * M_BLK;
    long n0 = (long)blockIdx.x * N_BLK;

    float acc[8][4] = {};

    for (int k0 = 0; k0 < KTOT; k0 += 32) {
        __syncthreads();
        for (int i = t; i < M_BLK * 8; i += 256) {
            int m = i >> 3, k4 = i & 7;
            float4 v = *(const float4*)&w[(size_t)(mbase + m) * KTOT + k0 + k4 * 4];
            v.x = tf32r(v.x); v.y = tf32r(v.y); v.z = tf32r(v.z); v.w = tf32r(v.w);
            *(float4*)&sA[m * 36 + k4 * 4] = v;
        }
        for (int i = t; i < N_BLK * 32; i += 256) {
            int n = i >> 5, k = i & 31;
            long ng = n0 + n;
            int b = (int)(ng / NPOS), p = (int)(ng % NPOS);
            int kg = k0 + k;
            int ic = kg / KK, kk = kg - ic * KK;
            int pos = p * 2 + kk - PAD;
            float v = 0.f;
            if (pos >= 0 && pos < LIN) v = in[(size_t)b * 3072 + ic * LIN + pos];
            sB[n * 36 + k] = v;
        }
        __syncthreads();
        #pragma unroll
        for (int ks = 0; ks < 4; ks++) {
            int kb = ks * 8;
            int ra = (wm * 16 + g) * 36 + kb + tg;
            uint32_t a0 = __float_as_uint(sA[ra]);
            uint32_t a1 = __float_as_uint(sA[ra + 8 * 36]);
            uint32_t a2 = __float_as_uint(sA[ra + 4]);
            uint32_t a3 = __float_as_uint(sA[ra + 8 * 36 + 4]);
            #pragma unroll
            for (int j = 0; j < 8; j++) {
                int rb = (wn * 64 + j * 8 + g) * 36 + kb + tg;
                uint32_t b0 = __float_as_uint(sB[rb]);
                uint32_t b1 = __float_as_uint(sB[rb + 4]);
                mma_tf32(acc[j], a0, a1, a2, a3, b0, b1);
            }
        }
    }
    int m0 = mbase + wm * 16 + g;
    int m1 = m0 + 8;
    float bi0 = bias[m0], bi1 = bias[m1];
    #pragma unroll
    for (int j = 0; j < 8; j++) {
        long nc = n0 + wn * 64 + j * 8 + 2 * tg;
        int b = (int)(nc / NPOS), p = (int)(nc % NPOS);
        float* ob = outp + (size_t)b * 3072;
        ob[m0 * NPOS + p]     = tf32r(fmaxf(acc[j][0] + bi0, 0.f));
        ob[m0 * NPOS + p + 1] = tf32r(fmaxf(acc[j][1] + bi0, 0.f));
        ob[m1 * NPOS + p]     = tf32r(fmaxf(acc[j][2] + bi1, 0.f));
        ob[m1 * NPOS + p + 1] = tf32r(fmaxf(acc[j][3] + bi1, 0.f));
    }
}

// ---------------- fc1 via tf32 mma: [8192x3072]@[3072x128] -------------------
__global__ void __launch_bounds__(256, 3) k_fc1mma(const float* __restrict__ W,
                                                   const float* __restrict__ bias,
                                                   float* __restrict__ feat_out) {
    __shared__ float sA[32 * 132];
    __shared__ float sB[64 * 36];
    int t = threadIdx.x;
    int warp = t >> 5, lane = t & 31;
    int g = lane >> 2, tg = lane & 3;
    int wm = warp;
    long n0 = (long)blockIdx.x * 64;
    float acc[8][4] = {};

    for (int k0 = 0; k0 < 3072; k0 += 32) {
        __syncthreads();
        for (int i = t; i < 1024; i += 256) {
            int k = i >> 5, m4 = i & 31;
            float4 v = *(const float4*)&W[(size_t)(k0 + k) * 128 + m4 * 4];
            v.x = tf32r(v.x); v.y = tf32r(v.y); v.z = tf32r(v.z); v.w = tf32r(v.w);
            *(float4*)&sA[k * 132 + m4 * 4] = v;
        }
        for (int i = t; i < 512; i += 256) {
            int n = i >> 3, k4 = i & 7;
            float4 v = *(const float4*)&g_buf1[(size_t)(n0 + n) * 3072 + k0 + k4 * 4];
            *(float4*)&sB[n * 36 + k4 * 4] = v;
        }
        __syncthreads();
        #pragma unroll
        for (int ks = 0; ks < 4; ks++) {
            int kb = ks * 8;
            uint32_t a0 = __float_as_uint(sA[(kb + tg) * 132 + wm * 16 + g]);
            uint32_t a1 = __float_as_uint(sA[(kb + tg) * 132 + wm * 16 + g + 8]);
            uint32_t a2 = __float_as_uint(sA[(kb + tg + 4) * 132 + wm * 16 + g]);
            uint32_t a3 = __float_as_uint(sA[(kb + tg + 4) * 132 + wm * 16 + g + 8]);
            #pragma unroll
            for (int j = 0; j < 8; j++) {
                int rb = (j * 8 + g) * 36 + kb + tg;
                uint32_t b0 = __float_as_uint(sB[rb]);
                uint32_t b1 = __float_as_uint(sB[rb + 4]);
                mma_tf32(acc[j], a0, a1, a2, a3, b0, b1);
            }
        }
    }
    int m0 = wm * 16 + g, m1 = m0 + 8;
    float bi0 = bias[m0], bi1 = bias[m1];
    #pragma unroll
    for (int j = 0; j < 8; j++) {
        long n = n0 + j * 8 + 2 * tg;
        float f00 = acc[j][0] + bi0, f01 = acc[j][1] + bi0;
        float f10 = acc[j][2] + bi1, f11 = acc[j][3] + bi1;
        feat_out[n * 128 + m0] = f00;       feat_out[(n + 1) * 128 + m0] = f01;
        feat_out[n * 128 + m1] = f10;       feat_out[(n + 1) * 128 + m1] = f11;
        g_buf2[n * 128 + m0] = tf32r(fmaxf(f00, 0.f));
        g_buf2[(n + 1) * 128 + m0] = tf32r(fmaxf(f01, 0.f));
        g_buf2[n * 128 + m1] = tf32r(fmaxf(f10, 0.f));
        g_buf2[(n + 1) * 128 + m1] = tf32r(fmaxf(f11, 0.f));
    }
}

// ---------------- cls via mma: C[feat, batch], K=128 -------------------------
// STAGE=1: in g_buf2[:B*128], out g_buf1[:B*128], relu+tf32r, M=128
// STAGE=2: in g_buf1[:B*128], out = out_x param, plain, M=210
template<int MTOT, int STAGE>
__global__ void __launch_bounds__(256, 3) k_clsmma(const float* __restrict__ W,
                                                   const float* __restrict__ bias,
                                                   float* __restrict__ outx) {
    const float* inb = (STAGE == 1) ? g_buf2 : g_buf1;
    __shared__ float sA[128 * 36];
    __shared__ float sB[64 * 36];
    int t = threadIdx.x;
    int warp = t >> 5, lane = t & 31;
    int g = lane >> 2, tg = lane & 3;
    int mbase = blockIdx.y * 128;
    long n0 = (long)blockIdx.x * 64;
    float acc[8][4] = {};

    for (int k0 = 0; k0 < 128; k0 += 32) {
        __syncthreads();
        for (int i = t; i < 128 * 32; i += 256) {
            int n = i & 127, k = i >> 7;
            int gn = mbase + n;
            sA[n * 36 + k] = (gn < MTOT) ? tf32r(W[(size_t)(k0 + k) * MTOT + gn]) : 0.f;
        }
        for (int i = t; i < 512; i += 256) {
            int n = i >> 3, k4 = i & 7;
            float4 v = *(const float4*)&inb[(size_t)(n0 + n) * 128 + k0 + k4 * 4];
            *(float4*)&sB[n * 36 + k4 * 4] = v;
        }
        __syncthreads();
        #pragma unroll
        for (int ks = 0; ks < 4; ks++) {
            int kb = ks * 8;
            int ra = (warp * 16 + g) * 36 + kb + tg;
            uint32_t a0 = __float_as_uint(sA[ra]);
            uint32_t a1 = __float_as_uint(sA[ra + 8 * 36]);
            uint32_t a2 = __float_as_uint(sA[ra + 4]);
            uint32_t a3 = __float_as_uint(sA[ra + 8 * 36 + 4]);
            #pragma unroll
            for (int j = 0; j < 8; j++) {
                int rb = (j * 8 + g) * 36 + kb + tg;
                uint32_t b0 = __float_as_uint(sB[rb]);
                uint32_t b1 = __float_as_uint(sB[rb + 4]);
                mma_tf32(acc[j], a0, a1, a2, a3, b0, b1);
            }
        }
    }
    int m0 = mbase + warp * 16 + g, m1 = m0 + 8;
    float bi0 = (m0 < MTOT) ? bias[m0] : 0.f;
    float bi1 = (m1 < MTOT) ? bias[m1] : 0.f;
    #pragma unroll
    for (int j = 0; j < 8; j++) {
        long b = n0 + j * 8 + 2 * tg;
        float f00 = acc[j][0] + bi0, f01 = acc[j][1] + bi0;
        float f10 = acc[j][2] + bi1, f11 = acc[j][3] + bi1;
        if (STAGE == 1) {
            f00 = tf32r(fmaxf(f00, 0.f)); f01 = tf32r(fmaxf(f01, 0.f));
            f10 = tf32r(fmaxf(f10, 0.f)); f11 = tf32r(fmaxf(f11, 0.f));
            g_buf1[b * 128 + m0] = f00; g_buf1[(b + 1) * 128 + m0] = f01;
            g_buf1[b * 128 + m1] = f10; g_buf1[(b + 1) * 128 + m1] = f11;
        } else {
            if (m0 < MTOT) { outx[b * MTOT + m0] = f00; outx[(b + 1) * MTOT + m0] = f01; }
            if (m1 < MTOT) { outx[b * MTOT + m1] = f10; outx[(b + 1) * MTOT + m1] = f11; }
        }
    }
}

// ---------------- launch ------------------------------------------------------
extern "C" void kernel_launch(void* const* d_in, const int* in_sizes, int n_in,
                              void* d_out, int out_size) {
    const float* src     = (const float*)d_in[0];
    const int*   ei      = (const int*)d_in[1];
    const float* gcn1_w  = (const float*)d_in[2];
    const float* gcn1_b  = (const float*)d_in[3];
    const float* gcn2_w  = (const float*)d_in[4];
    const float* gcn2_b  = (const float*)d_in[5];
    const float* conv1_w = (const float*)d_in[6];
    const float* conv1_b = (const float*)d_in[7];
    const float* conv2_w = (const float*)d_in[8];
    const float* conv2_b = (const float*)d_in[9];
    const float* conv3_w = (const float*)d_in[10];
    const float* conv3_b = (const float*)d_in[11];
    const float* fc1_w   = (const float*)d_in[12];
    const float* fc1_b   = (const float*)d_in[13];
    const float* cls1_w  = (const float*)d_in[14];
    const float* cls1_b  = (const float*)d_in[15];
    const float* cls2_w  = (const float*)d_in[16];
    const float* cls2_b  = (const float*)d_in[17];

    int ne = in_sizes[1] / 2;

    float* out   = (float*)d_out;
    float* out_x = out;                          // [B,210]
    float* out_f = out + (size_t)BB * 210;       // [B,128]

    k_build_adj<<<1, 256>>>(ei, ne);
    k_gcnAmma<<<2048, 256>>>(src);
    k_gcnB<<<BB * 96 / 256, 256>>>(gcn1_w, gcn1_b, gcn2_w);
    k_gcnCmma<<<4096, 256>>>(gcn2_b);

    k_convmma<64, 4, 2, 224, 7, 48, 96, 3, 0><<<dim3(3072, 1), 256>>>(conv1_w, conv1_b);
    k_convmma<128, 8, 1, 320, 5, 24, 48, 2, 1><<<dim3(3072, 1), 256>>>(conv2_w, conv2_b);
    k_convmma<128, 8, 1, 384, 3, 12, 24, 1, 0><<<dim3(1536, 2), 256>>>(conv3_w, conv3_b);

    k_fc1mma<<<128, 256>>>(fc1_w, fc1_b, out_f);
    k_clsmma<128, 1><<<dim3(128, 1), 256>>>(cls1_w, cls1_b, nullptr);
    k_clsmma<210, 2><<<dim3(128, 2), 256>>>(cls2_w, cls2_b, out_x);
}

// round 11
// speedup vs baseline: 3.0139x; 1.0358x over previous
#include <cuda_runtime.h>
#include <cstdint>
#include <math.h>

#define BB 8192

__device__ __forceinline__ float tf32r(float x) {
    uint32_t u;
    asm("cvt.rna.tf32.f32 %0, %1;" : "=r"(u) : "f"(x));
    return __uint_as_float(u);
}

__device__ __forceinline__ void mma_tf32(float c[4],
                                         uint32_t a0, uint32_t a1, uint32_t a2, uint32_t a3,
                                         uint32_t b0, uint32_t b1) {
    asm volatile(
        "mma.sync.aligned.m16n8k8.row.col.f32.tf32.tf32.f32 "
        "{%0,%1,%2,%3}, {%4,%5,%6,%7}, {%8,%9}, {%0,%1,%2,%3};"
        : "+f"(c[0]), "+f"(c[1]), "+f"(c[2]), "+f"(c[3])
        : "r"(a0), "r"(a1), "r"(a2), "r"(a3), "r"(b0), "r"(b1));
}

__device__ __forceinline__ void ldsm_x4(uint32_t& r0, uint32_t& r1, uint32_t& r2, uint32_t& r3,
                                        uint32_t addr) {
    asm volatile("ldmatrix.sync.aligned.m8n8.x4.shared.b16 {%0,%1,%2,%3}, [%4];"
                 : "=r"(r0), "=r"(r1), "=r"(r2), "=r"(r3) : "r"(addr));
}

__device__ __forceinline__ uint32_t smem_u32(const void* p) {
    return (uint32_t)__cvta_generic_to_shared(p);
}

// ---------------- scratch ----------------------------------------------------
// g_buf1 regions: Y [0, B*1536) | T [B*1536, B*4608) | Wt (fc1) [B*4608, +393216)
// conv1/conv3 outputs use [0, B*3072) after T is consumed; cls1-out reuses [0, B*128).
__device__ float g_A[96 * 96];                  // A: [n][m]
__device__ float g_buf1[(size_t)BB * 6144];
__device__ float g_buf2[(size_t)BB * 3072];

// ---------------- build dense normalized adjacency ---------------------------
__global__ void k_build_adj(const int* __restrict__ ei, int ne) {
    __shared__ float deg[96];
    __shared__ float dinv[96];
    int t = threadIdx.x;
    if (t < 96) deg[t] = 0.f;
    for (int i = t; i < 9216; i += 256) g_A[i] = 0.f;
    __syncthreads();
    for (int e = t; e < ne; e += 256) atomicAdd(&deg[ei[e]], 1.0f);
    if (t < 96) atomicAdd(&deg[t], 1.0f);
    __syncthreads();
    if (t < 96) dinv[t] = 1.0f / sqrtf(fmaxf(deg[t], 1e-12f));
    __syncthreads();
    for (int e = t; e < ne; e += 256) {
        int r = ei[e], c = ei[ne + e];
        atomicAdd(&g_A[r * 96 + c], dinv[r] * dinv[c]);
    }
    if (t < 96) atomicAdd(&g_A[t * 96 + t], dinv[t] * dinv[t]);
}

// ---------------- one-time fc1 weight transpose: W[3072][128] -> Wt[128][3072]
__global__ void k_trW(const float* __restrict__ W) {
    __shared__ float tile[32][33];
    float* Wt = g_buf1 + (size_t)BB * 4608;
    int bx = blockIdx.x;   // k tile (96)
    int by = blockIdx.y;   // m tile (4)
    int tx = threadIdx.x & 31, ty = threadIdx.x >> 5;
    for (int r = 0; r < 32; r += 8)
        tile[ty + r][tx] = W[(size_t)(bx * 32 + ty + r) * 128 + by * 32 + tx];
    __syncthreads();
    for (int r = 0; r < 32; r += 8)
        Wt[(size_t)(by * 32 + ty + r) * 3072 + bx * 32 + tx] = tf32r(tile[tx][ty + r]);
}

// ---------------- gcnA via mma: Y[n,(b,c)] = A@Xq ----------------------------
__global__ void __launch_bounds__(256, 3) k_gcnAmma(const float* __restrict__ src) {
    __shared__ float sA[128 * 36];
    __shared__ float sB[64 * 36];
    int t = threadIdx.x;
    int warp = t >> 5, lane = t & 31;
    int g = lane >> 2, tg = lane & 3;
    long n0 = (long)blockIdx.x * 64;
    float acc[8][4] = {};

    int atile = lane >> 3;
    int arow = warp * 16 + (lane & 7) + ((atile & 1) << 3);
    uint32_t aaddr = smem_u32(sA) + (uint32_t)(arow * 36 + (atile >> 1) * 4) * 4u;
    int brow = ((lane >> 4) << 3) + (lane & 7);
    uint32_t baddr = smem_u32(sB) + (uint32_t)(brow * 36 + ((lane >> 3) & 1) * 4) * 4u;

    for (int k0 = 0; k0 < 96; k0 += 32) {
        __syncthreads();
        for (int i = t; i < 128 * 8; i += 256) {
            int m = i >> 3, k4 = i & 7;
            float4 v = make_float4(0.f, 0.f, 0.f, 0.f);
            if (m < 96) {
                v = *(const float4*)&g_A[m * 96 + k0 + k4 * 4];
                v.x = tf32r(v.x); v.y = tf32r(v.y); v.z = tf32r(v.z); v.w = tf32r(v.w);
            }
            *(float4*)&sA[m * 36 + k4 * 4] = v;
        }
        for (int i = t; i < 64 * 32; i += 256) {
            int n = i >> 5, k = i & 31;
            long col = n0 + n;
            int b = (int)(col >> 4), c = (int)(col & 15);
            sB[n * 36 + k] = tf32r(src[(size_t)b * 1536 + c * 96 + k0 + k]);
        }
        __syncthreads();
        #pragma unroll
        for (int ks = 0; ks < 4; ks++) {
            int kb = ks * 8;
            uint32_t a0, a1, a2, a3;
            ldsm_x4(a0, a1, a2, a3, aaddr + kb * 4);
            #pragma unroll
            for (int p = 0; p < 4; p++) {
                uint32_t b0, b1, b2, b3;
                ldsm_x4(b0, b1, b2, b3, baddr + (p * 16 * 36 + kb) * 4);
                mma_tf32(acc[2 * p],     a0, a1, a2, a3, b0, b1);
                mma_tf32(acc[2 * p + 1], a0, a1, a2, a3, b2, b3);
            }
        }
    }
    int m0 = warp * 16 + g, m1 = m0 + 8;
    if (m0 < 96) {
        #pragma unroll
        for (int j = 0; j < 8; j++) {
            long nc = n0 + j * 8 + 2 * tg;
            int b = (int)(nc >> 4), c = (int)(nc & 15);
            float* yb = g_buf1 + (size_t)b * 1536;
            yb[m0 * 16 + c]     = acc[j][0];
            yb[m0 * 16 + c + 1] = acc[j][1];
            yb[m1 * 16 + c]     = acc[j][2];
            yb[m1 * 16 + c + 1] = acc[j][3];
        }
    }
}

// ---------------- gcnB: per row: H = tf32r(relu(Y@W1q+b1)); T = Hq@W2q -------
__global__ void __launch_bounds__(256) k_gcnB(const float* __restrict__ W1,
                                              const float* __restrict__ b1,
                                              const float* __restrict__ W2) {
    __shared__ float sW1[1024];
    __shared__ float sW2[2048];
    __shared__ float sB1[64];
    int t = threadIdx.x;
    for (int i = t; i < 1024; i += 256) sW1[i] = tf32r(W1[i]);
    for (int i = t; i < 2048; i += 256) sW2[i] = tf32r(W2[i]);
    if (t < 64) sB1[t] = b1[t];
    __syncthreads();

    size_t row = (size_t)blockIdx.x * 256 + t;
    const float4* y4 = (const float4*)(g_buf1 + row * 16);
    float Y[16];
    #pragma unroll
    for (int i = 0; i < 4; i++) {
        float4 v = y4[i];
        Y[4 * i] = v.x; Y[4 * i + 1] = v.y; Y[4 * i + 2] = v.z; Y[4 * i + 3] = v.w;
    }
    float H[64];
    #pragma unroll
    for (int f = 0; f < 64; f++) H[f] = sB1[f];
    #pragma unroll
    for (int c = 0; c < 16; c++) {
        float yc = Y[c];
        #pragma unroll
        for (int f = 0; f < 64; f++) H[f] += yc * sW1[c * 64 + f];
    }
    #pragma unroll
    for (int f = 0; f < 64; f++) H[f] = tf32r(fmaxf(H[f], 0.f));
    float T[32] = {};
    #pragma unroll
    for (int f = 0; f < 64; f++) {
        float hf = H[f];
        #pragma unroll
        for (int g = 0; g < 32; g++) T[g] += hf * sW2[f * 32 + g];
    }
    float* tp = g_buf1 + (size_t)BB * 1536 + row * 32;
    #pragma unroll
    for (int g = 0; g < 32; g += 4)
        *(float4*)&tp[g] = make_float4(T[g], T[g + 1], T[g + 2], T[g + 3]);
}

// ---------------- gcnC via mma: out[n,(b,g)] = relu(A@Tq + b2) ---------------
__global__ void __launch_bounds__(256, 3) k_gcnCmma(const float* __restrict__ b2) {
    __shared__ float sA[128 * 36];
    __shared__ float sB[64 * 36];
    int t = threadIdx.x;
    int warp = t >> 5, lane = t & 31;
    int g = lane >> 2, tg = lane & 3;
    long n0 = (long)blockIdx.x * 64;
    int b0 = blockIdx.x * 2;
    const float* T = g_buf1 + (size_t)BB * 1536;
    float acc[8][4] = {};

    int atile = lane >> 3;
    int arow = warp * 16 + (lane & 7) + ((atile & 1) << 3);
    uint32_t aaddr = smem_u32(sA) + (uint32_t)(arow * 36 + (atile >> 1) * 4) * 4u;
    int brow = ((lane >> 4) << 3) + (lane & 7);
    uint32_t baddr = smem_u32(sB) + (uint32_t)(brow * 36 + ((lane >> 3) & 1) * 4) * 4u;

    for (int k0 = 0; k0 < 96; k0 += 32) {
        __syncthreads();
        for (int i = t; i < 128 * 8; i += 256) {
            int m = i >> 3, k4 = i & 7;
            float4 v = make_float4(0.f, 0.f, 0.f, 0.f);
            if (m < 96) {
                v = *(const float4*)&g_A[m * 96 + k0 + k4 * 4];
                v.x = tf32r(v.x); v.y = tf32r(v.y); v.z = tf32r(v.z); v.w = tf32r(v.w);
            }
            *(float4*)&sA[m * 36 + k4 * 4] = v;
        }
        for (int i = t; i < 2048; i += 256) {      // T[b][m][g] -> sB[(bi*32+g)][m]
            int bi = i >> 10, rem = i & 1023, m = rem >> 5, gg = rem & 31;
            sB[(bi * 32 + gg) * 36 + m] =
                tf32r(T[(size_t)(b0 + bi) * 3072 + (k0 + m) * 32 + gg]);
        }
        __syncthreads();
        #pragma unroll
        for (int ks = 0; ks < 4; ks++) {
            int kb = ks * 8;
            uint32_t a0, a1, a2, a3;
            ldsm_x4(a0, a1, a2, a3, aaddr + kb * 4);
            #pragma unroll
            for (int p = 0; p < 4; p++) {
                uint32_t b0f, b1f, b2f, b3f;
                ldsm_x4(b0f, b1f, b2f, b3f, baddr + (p * 16 * 36 + kb) * 4);
                mma_tf32(acc[2 * p],     a0, a1, a2, a3, b0f, b1f);
                mma_tf32(acc[2 * p + 1], a0, a1, a2, a3, b2f, b3f);
            }
        }
    }
    int m0 = warp * 16 + g, m1 = m0 + 8;
    if (m0 < 96) {
        #pragma unroll
        for (int j = 0; j < 8; j++) {
            long nc = n0 + j * 8 + 2 * tg;
            int b = (int)(nc >> 5), gg = (int)(nc & 31);
            float bg0 = b2[gg], bg1 = b2[gg + 1];
            float* ob = g_buf2 + (size_t)b * 3072;
            ob[gg * 96 + m0]       = tf32r(fmaxf(acc[j][0] + bg0, 0.f));
            ob[(gg + 1) * 96 + m0] = tf32r(fmaxf(acc[j][1] + bg1, 0.f));
            ob[gg * 96 + m1]       = tf32r(fmaxf(acc[j][2] + bg0, 0.f));
            ob[(gg + 1) * 96 + m1] = tf32r(fmaxf(acc[j][3] + bg1, 0.f));
        }
    }
}

// ---------------- conv as implicit GEMM on tensor cores ----------------------
template<int M_BLK, int WM, int WN, int KTOT, int KK, int NPOS, int LIN, int PAD, int IO>
__global__ void __launch_bounds__(256, 3) k_convmma(const float* __restrict__ w,
                                                    const float* __restrict__ bias) {
    const float* in = (IO == 0) ? g_buf2 : g_buf1;
    float* outp     = (IO == 0) ? g_buf1 : g_buf2;
    constexpr int N_BLK = WN * 64;
    __shared__ float sA[M_BLK * 36];
    __shared__ float sB[N_BLK * 36];
    int t = threadIdx.x;
    int warp = t >> 5, lane = t & 31;
    int g = lane >> 2, tg = lane & 3;
    int wm = warp % WM, wn = warp / WM;
    int mbase = blockIdx.y * M_BLK;
    long n0 = (long)blockIdx.x * N_BLK;

    float acc[8][4] = {};

    int atile = lane >> 3;
    int arow = wm * 16 + (lane & 7) + ((atile & 1) << 3);
    uint32_t aaddr = smem_u32(sA) + (uint32_t)(arow * 36 + (atile >> 1) * 4) * 4u;
    int brow = wn * 64 + ((lane >> 4) << 3) + (lane & 7);
    uint32_t baddr = smem_u32(sB) + (uint32_t)(brow * 36 + ((lane >> 3) & 1) * 4) * 4u;

    for (int k0 = 0; k0 < KTOT; k0 += 32) {
        __syncthreads();
        for (int i = t; i < M_BLK * 8; i += 256) {
            int m = i >> 3, k4 = i & 7;
            float4 v = *(const float4*)&w[(size_t)(mbase + m) * KTOT + k0 + k4 * 4];
            v.x = tf32r(v.x); v.y = tf32r(v.y); v.z = tf32r(v.z); v.w = tf32r(v.w);
            *(float4*)&sA[m * 36 + k4 * 4] = v;
        }
        for (int i = t; i < N_BLK * 32; i += 256) {
            int n = i >> 5, k = i & 31;
            long ng = n0 + n;
            int b = (int)(ng / NPOS), p = (int)(ng % NPOS);
            int kg = k0 + k;
            int ic = kg / KK, kk = kg - ic * KK;
            int pos = p * 2 + kk - PAD;
            float v = 0.f;
            if (pos >= 0 && pos < LIN) v = in[(size_t)b * 3072 + ic * LIN + pos];
            sB[n * 36 + k] = v;
        }
        __syncthreads();
        #pragma unroll
        for (int ks = 0; ks < 4; ks++) {
            int kb = ks * 8;
            uint32_t a0, a1, a2, a3;
            ldsm_x4(a0, a1, a2, a3, aaddr + kb * 4);
            #pragma unroll
            for (int p = 0; p < 4; p++) {
                uint32_t b0, b1, b2, b3;
                ldsm_x4(b0, b1, b2, b3, baddr + (p * 16 * 36 + kb) * 4);
                mma_tf32(acc[2 * p],     a0, a1, a2, a3, b0, b1);
                mma_tf32(acc[2 * p + 1], a0, a1, a2, a3, b2, b3);
            }
        }
    }
    int m0 = mbase + wm * 16 + g;
    int m1 = m0 + 8;
    float bi0 = bias[m0], bi1 = bias[m1];
    #pragma unroll
    for (int j = 0; j < 8; j++) {
        long nc = n0 + wn * 64 + j * 8 + 2 * tg;
        int b = (int)(nc / NPOS), p = (int)(nc % NPOS);
        float* ob = outp + (size_t)b * 3072;
        ob[m0 * NPOS + p]     = tf32r(fmaxf(acc[j][0] + bi0, 0.f));
        ob[m0 * NPOS + p + 1] = tf32r(fmaxf(acc[j][1] + bi0, 0.f));
        ob[m1 * NPOS + p]     = tf32r(fmaxf(acc[j][2] + bi1, 0.f));
        ob[m1 * NPOS + p + 1] = tf32r(fmaxf(acc[j][3] + bi1, 0.f));
    }
}

// ---------------- fc1 via tf32 mma: Wt[128][3072] (pre-rounded), N_BLK=32 ----
__global__ void __launch_bounds__(256, 3) k_fc1mma(const float* __restrict__ bias,
                                                   float* __restrict__ feat_out) {
    const float* Wt = g_buf1 + (size_t)BB * 4608;
    __shared__ float sA[128 * 36];
    __shared__ float sB[32 * 36];
    int t = threadIdx.x;
    int warp = t >> 5, lane = t & 31;
    int g = lane >> 2, tg = lane & 3;
    long n0 = (long)blockIdx.x * 32;
    float acc[4][4] = {};

    int atile = lane >> 3;
    int arow = warp * 16 + (lane & 7) + ((atile & 1) << 3);
    uint32_t aaddr = smem_u32(sA) + (uint32_t)(arow * 36 + (atile >> 1) * 4) * 4u;
    int brow = ((lane >> 4) << 3) + (lane & 7);
    uint32_t baddr = smem_u32(sB) + (uint32_t)(brow * 36 + ((lane >> 3) & 1) * 4) * 4u;

    for (int k0 = 0; k0 < 3072; k0 += 32) {
        __syncthreads();
        for (int i = t; i < 1024; i += 256) {
            int m = i >> 3, k4 = i & 7;
            *(float4*)&sA[m * 36 + k4 * 4] =
                *(const float4*)&Wt[(size_t)m * 3072 + k0 + k4 * 4];
        }
        for (int i = t; i < 256; i += 256) {
            int n = i >> 3, k4 = i & 7;
            *(float4*)&sB[n * 36 + k4 * 4] =
                *(const float4*)&g_buf1[(size_t)(n0 + n) * 3072 + k0 + k4 * 4];
        }
        __syncthreads();
        #pragma unroll
        for (int ks = 0; ks < 4; ks++) {
            int kb = ks * 8;
            uint32_t a0, a1, a2, a3;
            ldsm_x4(a0, a1, a2, a3, aaddr + kb * 4);
            #pragma unroll
            for (int p = 0; p < 2; p++) {
                uint32_t b0, b1, b2, b3;
                ldsm_x4(b0, b1, b2, b3, baddr + (p * 16 * 36 + kb) * 4);
                mma_tf32(acc[2 * p],     a0, a1, a2, a3, b0, b1);
                mma_tf32(acc[2 * p + 1], a0, a1, a2, a3, b2, b3);
            }
        }
    }
    int m0 = warp * 16 + g, m1 = m0 + 8;
    float bi0 = bias[m0], bi1 = bias[m1];
    #pragma unroll
    for (int j = 0; j < 4; j++) {
        long n = n0 + j * 8 + 2 * tg;
        float f00 = acc[j][0] + bi0, f01 = acc[j][1] + bi0;
        float f10 = acc[j][2] + bi1, f11 = acc[j][3] + bi1;
        feat_out[n * 128 + m0] = f00;       feat_out[(n + 1) * 128 + m0] = f01;
        feat_out[n * 128 + m1] = f10;       feat_out[(n + 1) * 128 + m1] = f11;
        g_buf2[n * 128 + m0] = tf32r(fmaxf(f00, 0.f));
        g_buf2[(n + 1) * 128 + m0] = tf32r(fmaxf(f01, 0.f));
        g_buf2[n * 128 + m1] = tf32r(fmaxf(f10, 0.f));
        g_buf2[(n + 1) * 128 + m1] = tf32r(fmaxf(f11, 0.f));
    }
}

// ---------------- cls via mma: C[feat, batch], K=128 -------------------------
template<int MTOT, int STAGE>
__global__ void __launch_bounds__(256, 3) k_clsmma(const float* __restrict__ W,
                                                   const float* __restrict__ bias,
                                                   float* __restrict__ outx) {
    const float* inb = (STAGE == 1) ? g_buf2 : g_buf1;
    __shared__ float sA[128 * 36];
    __shared__ float sB[64 * 36];
    int t = threadIdx.x;
    int warp = t >> 5, lane = t & 31;
    int g = lane >> 2, tg = lane & 3;
    int mbase = blockIdx.y * 128;
    long n0 = (long)blockIdx.x * 64;
    float acc[8][4] = {};

    int atile = lane >> 3;
    int arow = warp * 16 + (lane & 7) + ((atile & 1) << 3);
    uint32_t aaddr = smem_u32(sA) + (uint32_t)(arow * 36 + (atile >> 1) * 4) * 4u;
    int brow = ((lane >> 4) << 3) + (lane & 7);
    uint32_t baddr = smem_u32(sB) + (uint32_t)(brow * 36 + ((lane >> 3) & 1) * 4) * 4u;

    for (int k0 = 0; k0 < 128; k0 += 32) {
        __syncthreads();
        for (int i = t; i < 128 * 32; i += 256) {
            int n = i & 127, k = i >> 7;
            int gn = mbase + n;
            sA[n * 36 + k] = (gn < MTOT) ? tf32r(W[(size_t)(k0 + k) * MTOT + gn]) : 0.f;
        }
        for (int i = t; i < 512; i += 256) {
            int n = i >> 3, k4 = i & 7;
            float4 v = *(const float4*)&inb[(size_t)(n0 + n) * 128 + k0 + k4 * 4];
            *(float4*)&sB[n * 36 + k4 * 4] = v;
        }
        __syncthreads();
        #pragma unroll
        for (int ks = 0; ks < 4; ks++) {
            int kb = ks * 8;
            uint32_t a0, a1, a2, a3;
            ldsm_x4(a0, a1, a2, a3, aaddr + kb * 4);
            #pragma unroll
            for (int p = 0; p < 4; p++) {
                uint32_t b0, b1, b2, b3;
                ldsm_x4(b0, b1, b2, b3, baddr + (p * 16 * 36 + kb) * 4);
                mma_tf32(acc[2 * p],     a0, a1, a2, a3, b0, b1);
                mma_tf32(acc[2 * p + 1], a0, a1, a2, a3, b2, b3);
            }
        }
    }
    int m0 = mbase + warp * 16 + g, m1 = m0 + 8;
    float bi0 = (m0 < MTOT) ? bias[m0] : 0.f;
    float bi1 = (m1 < MTOT) ? bias[m1] : 0.f;
    #pragma unroll
    for (int j = 0; j < 8; j++) {
        long b = n0 + j * 8 + 2 * tg;
        float f00 = acc[j][0] + bi0, f01 = acc[j][1] + bi0;
        float f10 = acc[j][2] + bi1, f11 = acc[j][3] + bi1;
        if (STAGE == 1) {
            f00 = tf32r(fmaxf(f00, 0.f)); f01 = tf32r(fmaxf(f01, 0.f));
            f10 = tf32r(fmaxf(f10, 0.f)); f11 = tf32r(fmaxf(f11, 0.f));
            g_buf1[b * 128 + m0] = f00; g_buf1[(b + 1) * 128 + m0] = f01;
            g_buf1[b * 128 + m1] = f10; g_buf1[(b + 1) * 128 + m1] = f11;
        } else {
            if (m0 < MTOT) { outx[b * MTOT + m0] = f00; outx[(b + 1) * MTOT + m0] = f01; }
            if (m1 < MTOT) { outx[b * MTOT + m1] = f10; outx[(b + 1) * MTOT + m1] = f11; }
        }
    }
}

// ---------------- launch ------------------------------------------------------
extern "C" void kernel_launch(void* const* d_in, const int* in_sizes, int n_in,
                              void* d_out, int out_size) {
    const float* src     = (const float*)d_in[0];
    const int*   ei      = (const int*)d_in[1];
    const float* gcn1_w  = (const float*)d_in[2];
    const float* gcn1_b  = (const float*)d_in[3];
    const float* gcn2_w  = (const float*)d_in[4];
    const float* gcn2_b  = (const float*)d_in[5];
    const float* conv1_w = (const float*)d_in[6];
    const float* conv1_b = (const float*)d_in[7];
    const float* conv2_w = (const float*)d_in[8];
    const float* conv2_b = (const float*)d_in[9];
    const float* conv3_w = (const float*)d_in[10];
    const float* conv3_b = (const float*)d_in[11];
    const float* fc1_w   = (const float*)d_in[12];
    const float* fc1_b   = (const float*)d_in[13];
    const float* cls1_w  = (const float*)d_in[14];
    const float* cls1_b  = (const float*)d_in[15];
    const float* cls2_w  = (const float*)d_in[16];
    const float* cls2_b  = (const float*)d_in[17];

    int ne = in_sizes[1] / 2;

    float* out   = (float*)d_out;
    float* out_x = out;                          // [B,210]
    float* out_f = out + (size_t)BB * 210;       // [B,128]

    k_build_adj<<<1, 256>>>(ei, ne);
    k_trW<<<dim3(96, 4), 256>>>(fc1_w);

    k_gcnAmma<<<2048, 256>>>(src);
    k_gcnB<<<BB * 96 / 256, 256>>>(gcn1_w, gcn1_b, gcn2_w);
    k_gcnCmma<<<4096, 256>>>(gcn2_b);

    k_convmma<64, 4, 2, 224, 7, 48, 96, 3, 0><<<dim3(3072, 1), 256>>>(conv1_w, conv1_b);
    k_convmma<128, 8, 1, 320, 5, 24, 48, 2, 1><<<dim3(3072, 1), 256>>>(conv2_w, conv2_b);
    k_convmma<128, 8, 1, 384, 3, 12, 24, 1, 0><<<dim3(1536, 2), 256>>>(conv3_w, conv3_b);

    k_fc1mma<<<256, 256>>>(fc1_b, out_f);
    k_clsmma<128, 1><<<dim3(128, 1), 256>>>(cls1_w, cls1_b, nullptr);
    k_clsmma<210, 2><<<dim3(128, 2), 256>>>(cls2_w, cls2_b, out_x);
}

// round 12
// speedup vs baseline: 3.2670x; 1.0840x over previous
#include <cuda_runtime.h>
#include <cstdint>
#include <math.h>

#define BB 8192

__device__ __forceinline__ float tf32r(float x) {
    uint32_t u;
    asm("cvt.rna.tf32.f32 %0, %1;" : "=r"(u) : "f"(x));
    return __uint_as_float(u);
}

__device__ __forceinline__ void mma_tf32(float c[4],
                                         uint32_t a0, uint32_t a1, uint32_t a2, uint32_t a3,
                                         uint32_t b0, uint32_t b1) {
    asm volatile(
        "mma.sync.aligned.m16n8k8.row.col.f32.tf32.tf32.f32 "
        "{%0,%1,%2,%3}, {%4,%5,%6,%7}, {%8,%9}, {%0,%1,%2,%3};"
        : "+f"(c[0]), "+f"(c[1]), "+f"(c[2]), "+f"(c[3])
        : "r"(a0), "r"(a1), "r"(a2), "r"(a3), "r"(b0), "r"(b1));
}

__device__ __forceinline__ void ldsm_x4(uint32_t& r0, uint32_t& r1, uint32_t& r2, uint32_t& r3,
                                        uint32_t addr) {
    asm volatile("ldmatrix.sync.aligned.m8n8.x4.shared.b16 {%0,%1,%2,%3}, [%4];"
                 : "=r"(r0), "=r"(r1), "=r"(r2), "=r"(r3) : "r"(addr));
}

__device__ __forceinline__ uint32_t smem_u32(const void* p) {
    return (uint32_t)__cvta_generic_to_shared(p);
}

// ---------------- scratch ----------------------------------------------------
// g_buf1 regions: Y [0, B*1536) | T [B*1536, B*4608) | Wt (fc1) [B*4608, +393216)
__device__ float g_A[96 * 96];                  // A: [n][m]
__device__ float g_buf1[(size_t)BB * 6144];
__device__ float g_buf2[(size_t)BB * 3072];

// ---------------- build dense normalized adjacency ---------------------------
__global__ void k_build_adj(const int* __restrict__ ei, int ne) {
    __shared__ float deg[96];
    __shared__ float dinv[96];
    int t = threadIdx.x;
    if (t < 96) deg[t] = 0.f;
    for (int i = t; i < 9216; i += 256) g_A[i] = 0.f;
    __syncthreads();
    for (int e = t; e < ne; e += 256) atomicAdd(&deg[ei[e]], 1.0f);
    if (t < 96) atomicAdd(&deg[t], 1.0f);
    __syncthreads();
    if (t < 96) dinv[t] = 1.0f / sqrtf(fmaxf(deg[t], 1e-12f));
    __syncthreads();
    for (int e = t; e < ne; e += 256) {
        int r = ei[e], c = ei[ne + e];
        atomicAdd(&g_A[r * 96 + c], dinv[r] * dinv[c]);
    }
    if (t < 96) atomicAdd(&g_A[t * 96 + t], dinv[t] * dinv[t]);
}

// ---------------- one-time fc1 weight transpose: W[3072][128] -> Wt[128][3072]
__global__ void k_trW(const float* __restrict__ W) {
    __shared__ float tile[32][33];
    float* Wt = g_buf1 + (size_t)BB * 4608;
    int bx = blockIdx.x;   // k tile (96)
    int by = blockIdx.y;   // m tile (4)
    int tx = threadIdx.x & 31, ty = threadIdx.x >> 5;
    for (int r = 0; r < 32; r += 8)
        tile[ty + r][tx] = W[(size_t)(bx * 32 + ty + r) * 128 + by * 32 + tx];
    __syncthreads();
    for (int r = 0; r < 32; r += 8)
        Wt[(size_t)(by * 32 + ty + r) * 3072 + bx * 32 + tx] = tf32r(tile[tx][ty + r]);
}

// ---------------- gcnA via mma: Y[n,(b,c)] = A@Xq ----------------------------
__global__ void __launch_bounds__(256, 3) k_gcnAmma(const float* __restrict__ src) {
    __shared__ float sA[128 * 36];
    __shared__ float sB[64 * 36];
    int t = threadIdx.x;
    int warp = t >> 5, lane = t & 31;
    int g = lane >> 2, tg = lane & 3;
    long n0 = (long)blockIdx.x * 64;
    float acc[8][4] = {};

    int atile = lane >> 3;
    int arow = warp * 16 + (lane & 7) + ((atile & 1) << 3);
    uint32_t aaddr = smem_u32(sA) + (uint32_t)(arow * 36 + (atile >> 1) * 4) * 4u;
    int brow = ((lane >> 4) << 3) + (lane & 7);
    uint32_t baddr = smem_u32(sB) + (uint32_t)(brow * 36 + ((lane >> 3) & 1) * 4) * 4u;

    for (int k0 = 0; k0 < 96; k0 += 32) {
        __syncthreads();
        for (int i = t; i < 128 * 8; i += 256) {
            int m = i >> 3, k4 = i & 7;
            float4 v = make_float4(0.f, 0.f, 0.f, 0.f);
            if (m < 96) {
                v = *(const float4*)&g_A[m * 96 + k0 + k4 * 4];
                v.x = tf32r(v.x); v.y = tf32r(v.y); v.z = tf32r(v.z); v.w = tf32r(v.w);
            }
            *(float4*)&sA[m * 36 + k4 * 4] = v;
        }
        for (int i = t; i < 64 * 32; i += 256) {
            int n = i >> 5, k = i & 31;
            long col = n0 + n;
            int b = (int)(col >> 4), c = (int)(col & 15);
            sB[n * 36 + k] = tf32r(src[(size_t)b * 1536 + c * 96 + k0 + k]);
        }
        __syncthreads();
        #pragma unroll
        for (int ks = 0; ks < 4; ks++) {
            int kb = ks * 8;
            uint32_t a0, a1, a2, a3;
            ldsm_x4(a0, a1, a2, a3, aaddr + kb * 4);
            #pragma unroll
            for (int p = 0; p < 4; p++) {
                uint32_t b0, b1, b2, b3;
                ldsm_x4(b0, b1, b2, b3, baddr + (p * 16 * 36 + kb) * 4);
                mma_tf32(acc[2 * p],     a0, a1, a2, a3, b0, b1);
                mma_tf32(acc[2 * p + 1], a0, a1, a2, a3, b2, b3);
            }
        }
    }
    int m0 = warp * 16 + g, m1 = m0 + 8;
    if (m0 < 96) {
        #pragma unroll
        for (int j = 0; j < 8; j++) {
            long nc = n0 + j * 8 + 2 * tg;
            int b = (int)(nc >> 4), c = (int)(nc & 15);
            float* yb = g_buf1 + (size_t)b * 1536;
            yb[m0 * 16 + c]     = acc[j][0];
            yb[m0 * 16 + c + 1] = acc[j][1];
            yb[m1 * 16 + c]     = acc[j][2];
            yb[m1 * 16 + c + 1] = acc[j][3];
        }
    }
}

// ---------------- gcnB via fused 2-stage mma ---------------------------------
// Stage 1: H[64f x 128rows] = W1^T @ Yq + b1, relu, tf32 -> sH[row][f]
// Stage 2: T[32g x 128rows] = W2^T @ H -> g_buf1 T region
__global__ void __launch_bounds__(256, 3) k_gcnBmma(const float* __restrict__ W1,
                                                    const float* __restrict__ b1,
                                                    const float* __restrict__ W2) {
    extern __shared__ float sm[];
    float* sW1 = sm;                  // [64 f][20] (k=c 16 + pad)
    float* sW2 = sW1 + 64 * 20;       // [32 g][68] (k=f 64 + pad)
    float* sY  = sW2 + 32 * 68;       // [128 row][20]
    float* sH  = sY + 128 * 20;       // [128 row][68]
    float* sB1 = sH + 128 * 68;       // [64]
    int t = threadIdx.x;
    int warp = t >> 5, lane = t & 31;
    int g = lane >> 2, tg = lane & 3;
    size_t row0 = (size_t)blockIdx.x * 128;

    // loads
    for (int i = t; i < 1024; i += 256) {             // W1[c][f] -> sW1[f][c]
        int c = i >> 6, f = i & 63;
        sW1[f * 20 + c] = tf32r(W1[i]);
    }
    for (int i = t; i < 2048; i += 256) {             // W2[f][g] -> sW2[g][f]
        int f = i >> 5, gg = i & 31;
        sW2[gg * 68 + f] = tf32r(W2[i]);
    }
    if (t < 64) sB1[t] = b1[t];
    for (int i = t; i < 128 * 4; i += 256) {          // Y rows (quantize)
        int r = i >> 2, c4 = i & 3;
        float4 v = *(const float4*)&g_buf1[(row0 + r) * 16 + c4 * 4];
        v.x = tf32r(v.x); v.y = tf32r(v.y); v.z = tf32r(v.z); v.w = tf32r(v.w);
        *(float4*)&sY[r * 20 + c4 * 4] = v;
    }
    __syncthreads();

    // ---- stage 1: M=64 (4 tiles), N=128 (2 halves of 64), K=16 (2 steps)
    {
        int wm = warp & 3, wn = warp >> 2;
        int atile = lane >> 3;
        int arow = wm * 16 + (lane & 7) + ((atile & 1) << 3);
        uint32_t aaddr = smem_u32(sW1) + (uint32_t)(arow * 20 + (atile >> 1) * 4) * 4u;
        int brow = wn * 64 + ((lane >> 4) << 3) + (lane & 7);
        uint32_t baddr = smem_u32(sY) + (uint32_t)(brow * 20 + ((lane >> 3) & 1) * 4) * 4u;

        float acc[8][4] = {};
        #pragma unroll
        for (int ks = 0; ks < 2; ks++) {
            int kb = ks * 8;
            uint32_t a0, a1, a2, a3;
            ldsm_x4(a0, a1, a2, a3, aaddr + kb * 4);
            #pragma unroll
            for (int p = 0; p < 4; p++) {
                uint32_t b0, b1, b2, b3;
                ldsm_x4(b0, b1, b2, b3, baddr + (p * 16 * 20 + kb) * 4);
                mma_tf32(acc[2 * p],     a0, a1, a2, a3, b0, b1);
                mma_tf32(acc[2 * p + 1], a0, a1, a2, a3, b2, b3);
            }
        }
        int m0 = wm * 16 + g, m1 = m0 + 8;
        float bi0 = sB1[m0], bi1 = sB1[m1];
        #pragma unroll
        for (int j = 0; j < 8; j++) {
            int r = wn * 64 + j * 8 + 2 * tg;
            sH[r * 68 + m0]       = tf32r(fmaxf(acc[j][0] + bi0, 0.f));
            sH[(r + 1) * 68 + m0] = tf32r(fmaxf(acc[j][1] + bi0, 0.f));
            sH[r * 68 + m1]       = tf32r(fmaxf(acc[j][2] + bi1, 0.f));
            sH[(r + 1) * 68 + m1] = tf32r(fmaxf(acc[j][3] + bi1, 0.f));
        }
    }
    __syncthreads();

    // ---- stage 2: M=32 (2 tiles), N=128 (4 quarters of 32), K=64 (8 steps)
    {
        int wm = warp & 1, wn = warp >> 1;
        int atile = lane >> 3;
        int arow = wm * 16 + (lane & 7) + ((atile & 1) << 3);
        uint32_t aaddr = smem_u32(sW2) + (uint32_t)(arow * 68 + (atile >> 1) * 4) * 4u;
        int brow = wn * 32 + ((lane >> 4) << 3) + (lane & 7);
        uint32_t baddr = smem_u32(sH) + (uint32_t)(brow * 68 + ((lane >> 3) & 1) * 4) * 4u;

        float acc[4][4] = {};
        #pragma unroll
        for (int ks = 0; ks < 8; ks++) {
            int kb = ks * 8;
            uint32_t a0, a1, a2, a3;
            ldsm_x4(a0, a1, a2, a3, aaddr + kb * 4);
            #pragma unroll
            for (int p = 0; p < 2; p++) {
                uint32_t b0, b1, b2, b3;
                ldsm_x4(b0, b1, b2, b3, baddr + (p * 16 * 68 + kb) * 4);
                mma_tf32(acc[2 * p],     a0, a1, a2, a3, b0, b1);
                mma_tf32(acc[2 * p + 1], a0, a1, a2, a3, b2, b3);
            }
        }
        int m0 = wm * 16 + g, m1 = m0 + 8;
        float* tp = g_buf1 + (size_t)BB * 1536 + row0 * 32;
        #pragma unroll
        for (int j = 0; j < 4; j++) {
            int r = wn * 32 + j * 8 + 2 * tg;
            tp[r * 32 + m0]       = acc[j][0];
            tp[(r + 1) * 32 + m0] = acc[j][1];
            tp[r * 32 + m1]       = acc[j][2];
            tp[(r + 1) * 32 + m1] = acc[j][3];
        }
    }
}

// ---------------- gcnC via mma: out[n,(b,g)] = relu(A@Tq + b2) ---------------
__global__ void __launch_bounds__(256, 3) k_gcnCmma(const float* __restrict__ b2) {
    __shared__ float sA[128 * 36];
    __shared__ float sB[64 * 36];
    int t = threadIdx.x;
    int warp = t >> 5, lane = t & 31;
    int g = lane >> 2, tg = lane & 3;
    long n0 = (long)blockIdx.x * 64;
    int b0 = blockIdx.x * 2;
    const float* T = g_buf1 + (size_t)BB * 1536;
    float acc[8][4] = {};

    int atile = lane >> 3;
    int arow = warp * 16 + (lane & 7) + ((atile & 1) << 3);
    uint32_t aaddr = smem_u32(sA) + (uint32_t)(arow * 36 + (atile >> 1) * 4) * 4u;
    int brow = ((lane >> 4) << 3) + (lane & 7);
    uint32_t baddr = smem_u32(sB) + (uint32_t)(brow * 36 + ((lane >> 3) & 1) * 4) * 4u;

    for (int k0 = 0; k0 < 96; k0 += 32) {
        __syncthreads();
        for (int i = t; i < 128 * 8; i += 256) {
            int m = i >> 3, k4 = i & 7;
            float4 v = make_float4(0.f, 0.f, 0.f, 0.f);
            if (m < 96) {
                v = *(const float4*)&g_A[m * 96 + k0 + k4 * 4];
                v.x = tf32r(v.x); v.y = tf32r(v.y); v.z = tf32r(v.z); v.w = tf32r(v.w);
            }
            *(float4*)&sA[m * 36 + k4 * 4] = v;
        }
        for (int i = t; i < 2048; i += 256) {      // T[b][m][g] -> sB[(bi*32+g)][m]
            int bi = i >> 10, rem = i & 1023, m = rem >> 5, gg = rem & 31;
            sB[(bi * 32 + gg) * 36 + m] =
                tf32r(T[(size_t)(b0 + bi) * 3072 + (k0 + m) * 32 + gg]);
        }
        __syncthreads();
        #pragma unroll
        for (int ks = 0; ks < 4; ks++) {
            int kb = ks * 8;
            uint32_t a0, a1, a2, a3;
            ldsm_x4(a0, a1, a2, a3, aaddr + kb * 4);
            #pragma unroll
            for (int p = 0; p < 4; p++) {
                uint32_t b0f, b1f, b2f, b3f;
                ldsm_x4(b0f, b1f, b2f, b3f, baddr + (p * 16 * 36 + kb) * 4);
                mma_tf32(acc[2 * p],     a0, a1, a2, a3, b0f, b1f);
                mma_tf32(acc[2 * p + 1], a0, a1, a2, a3, b2f, b3f);
            }
        }
    }
    int m0 = warp * 16 + g, m1 = m0 + 8;
    if (m0 < 96) {
        #pragma unroll
        for (int j = 0; j < 8; j++) {
            long nc = n0 + j * 8 + 2 * tg;
            int b = (int)(nc >> 5), gg = (int)(nc & 31);
            float bg0 = b2[gg], bg1 = b2[gg + 1];
            float* ob = g_buf2 + (size_t)b * 3072;
            ob[gg * 96 + m0]       = tf32r(fmaxf(acc[j][0] + bg0, 0.f));
            ob[(gg + 1) * 96 + m0] = tf32r(fmaxf(acc[j][1] + bg1, 0.f));
            ob[gg * 96 + m1]       = tf32r(fmaxf(acc[j][2] + bg0, 0.f));
            ob[(gg + 1) * 96 + m1] = tf32r(fmaxf(acc[j][3] + bg1, 0.f));
        }
    }
}

// ---------------- conv as implicit GEMM on tensor cores ----------------------
template<int M_BLK, int WM, int WN, int KTOT, int KK, int NPOS, int LIN, int PAD, int IO>
__global__ void __launch_bounds__(256, 3) k_convmma(const float* __restrict__ w,
                                                    const float* __restrict__ bias) {
    const float* in = (IO == 0) ? g_buf2 : g_buf1;
    float* outp     = (IO == 0) ? g_buf1 : g_buf2;
    constexpr int N_BLK = WN * 64;
    __shared__ float sA[M_BLK * 36];
    __shared__ float sB[N_BLK * 36];
    int t = threadIdx.x;
    int warp = t >> 5, lane = t & 31;
    int g = lane >> 2, tg = lane & 3;
    int wm = warp % WM, wn = warp / WM;
    int mbase = blockIdx.y * M_BLK;
    long n0 = (long)blockIdx.x * N_BLK;

    float acc[8][4] = {};

    int atile = lane >> 3;
    int arow = wm * 16 + (lane & 7) + ((atile & 1) << 3);
    uint32_t aaddr = smem_u32(sA) + (uint32_t)(arow * 36 + (atile >> 1) * 4) * 4u;
    int brow = wn * 64 + ((lane >> 4) << 3) + (lane & 7);
    uint32_t baddr = smem_u32(sB) + (uint32_t)(brow * 36 + ((lane >> 3) & 1) * 4) * 4u;

    for (int k0 = 0; k0 < KTOT; k0 += 32) {
        __syncthreads();
        for (int i = t; i < M_BLK * 8; i += 256) {
            int m = i >> 3, k4 = i & 7;
            float4 v = *(const float4*)&w[(size_t)(mbase + m) * KTOT + k0 + k4 * 4];
            v.x = tf32r(v.x); v.y = tf32r(v.y); v.z = tf32r(v.z); v.w = tf32r(v.w);
            *(float4*)&sA[m * 36 + k4 * 4] = v;
        }
        for (int i = t; i < N_BLK * 32; i += 256) {
            int n = i >> 5, k = i & 31;
            long ng = n0 + n;
            int b = (int)(ng / NPOS), p = (int)(ng % NPOS);
            int kg = k0 + k;
            int ic = kg / KK, kk = kg - ic * KK;
            int pos = p * 2 + kk - PAD;
            float v = 0.f;
            if (pos >= 0 && pos < LIN) v = in[(size_t)b * 3072 + ic * LIN + pos];
            sB[n * 36 + k] = v;
        }
        __syncthreads();
        #pragma unroll
        for (int ks = 0; ks < 4; ks++) {
            int kb = ks * 8;
            uint32_t a0, a1, a2, a3;
            ldsm_x4(a0, a1, a2, a3, aaddr + kb * 4);
            #pragma unroll
            for (int p = 0; p < 4; p++) {
                uint32_t b0, b1, b2, b3;
                ldsm_x4(b0, b1, b2, b3, baddr + (p * 16 * 36 + kb) * 4);
                mma_tf32(acc[2 * p],     a0, a1, a2, a3, b0, b1);
                mma_tf32(acc[2 * p + 1], a0, a1, a2, a3, b2, b3);
            }
        }
    }
    int m0 = mbase + wm * 16 + g;
    int m1 = m0 + 8;
    float bi0 = bias[m0], bi1 = bias[m1];
    #pragma unroll
    for (int j = 0; j < 8; j++) {
        long nc = n0 + wn * 64 + j * 8 + 2 * tg;
        int b = (int)(nc / NPOS), p = (int)(nc % NPOS);
        float* ob = outp + (size_t)b * 3072;
        ob[m0 * NPOS + p]     = tf32r(fmaxf(acc[j][0] + bi0, 0.f));
        ob[m0 * NPOS + p + 1] = tf32r(fmaxf(acc[j][1] + bi0, 0.f));
        ob[m1 * NPOS + p]     = tf32r(fmaxf(acc[j][2] + bi1, 0.f));
        ob[m1 * NPOS + p + 1] = tf32r(fmaxf(acc[j][3] + bi1, 0.f));
    }
}

// ---------------- fc1 via tf32 mma: Wt[128][3072] (pre-rounded), N_BLK=32 ----
__global__ void __launch_bounds__(256, 3) k_fc1mma(const float* __restrict__ bias,
                                                   float* __restrict__ feat_out) {
    const float* Wt = g_buf1 + (size_t)BB * 4608;
    __shared__ float sA[128 * 36];
    __shared__ float sB[32 * 36];
    int t = threadIdx.x;
    int warp = t >> 5, lane = t & 31;
    int g = lane >> 2, tg = lane & 3;
    long n0 = (long)blockIdx.x * 32;
    float acc[4][4] = {};

    int atile = lane >> 3;
    int arow = warp * 16 + (lane & 7) + ((atile & 1) << 3);
    uint32_t aaddr = smem_u32(sA) + (uint32_t)(arow * 36 + (atile >> 1) * 4) * 4u;
    int brow = ((lane >> 4) << 3) + (lane & 7);
    uint32_t baddr = smem_u32(sB) + (uint32_t)(brow * 36 + ((lane >> 3) & 1) * 4) * 4u;

    for (int k0 = 0; k0 < 3072; k0 += 32) {
        __syncthreads();
        for (int i = t; i < 1024; i += 256) {
            int m = i >> 3, k4 = i & 7;
            *(float4*)&sA[m * 36 + k4 * 4] =
                *(const float4*)&Wt[(size_t)m * 3072 + k0 + k4 * 4];
        }
        for (int i = t; i < 256; i += 256) {
            int n = i >> 3, k4 = i & 7;
            *(float4*)&sB[n * 36 + k4 * 4] =
                *(const float4*)&g_buf1[(size_t)(n0 + n) * 3072 + k0 + k4 * 4];
        }
        __syncthreads();
        #pragma unroll
        for (int ks = 0; ks < 4; ks++) {
            int kb = ks * 8;
            uint32_t a0, a1, a2, a3;
            ldsm_x4(a0, a1, a2, a3, aaddr + kb * 4);
            #pragma unroll
            for (int p = 0; p < 2; p++) {
                uint32_t b0, b1, b2, b3;
                ldsm_x4(b0, b1, b2, b3, baddr + (p * 16 * 36 + kb) * 4);
                mma_tf32(acc[2 * p],     a0, a1, a2, a3, b0, b1);
                mma_tf32(acc[2 * p + 1], a0, a1, a2, a3, b2, b3);
            }
        }
    }
    int m0 = warp * 16 + g, m1 = m0 + 8;
    float bi0 = bias[m0], bi1 = bias[m1];
    #pragma unroll
    for (int j = 0; j < 4; j++) {
        long n = n0 + j * 8 + 2 * tg;
        float f00 = acc[j][0] + bi0, f01 = acc[j][1] + bi0;
        float f10 = acc[j][2] + bi1, f11 = acc[j][3] + bi1;
        feat_out[n * 128 + m0] = f00;       feat_out[(n + 1) * 128 + m0] = f01;
        feat_out[n * 128 + m1] = f10;       feat_out[(n + 1) * 128 + m1] = f11;
        g_buf2[n * 128 + m0] = tf32r(fmaxf(f00, 0.f));
        g_buf2[(n + 1) * 128 + m0] = tf32r(fmaxf(f01, 0.f));
        g_buf2[n * 128 + m1] = tf32r(fmaxf(f10, 0.f));
        g_buf2[(n + 1) * 128 + m1] = tf32r(fmaxf(f11, 0.f));
    }
}

// ---------------- cls via mma: C[feat, batch], K=128 -------------------------
template<int MTOT, int STAGE>
__global__ void __launch_bounds__(256, 3) k_clsmma(const float* __restrict__ W,
                                                   const float* __restrict__ bias,
                                                   float* __restrict__ outx) {
    const float* inb = (STAGE == 1) ? g_buf2 : g_buf1;
    __shared__ float sA[128 * 36];
    __shared__ float sB[64 * 36];
    int t = threadIdx.x;
    int warp = t >> 5, lane = t & 31;
    int g = lane >> 2, tg = lane & 3;
    int mbase = blockIdx.y * 128;
    long n0 = (long)blockIdx.x * 64;
    float acc[8][4] = {};

    int atile = lane >> 3;
    int arow = warp * 16 + (lane & 7) + ((atile & 1) << 3);
    uint32_t aaddr = smem_u32(sA) + (uint32_t)(arow * 36 + (atile >> 1) * 4) * 4u;
    int brow = ((lane >> 4) << 3) + (lane & 7);
    uint32_t baddr = smem_u32(sB) + (uint32_t)(brow * 36 + ((lane >> 3) & 1) * 4) * 4u;

    for (int k0 = 0; k0 < 128; k0 += 32) {
        __syncthreads();
        for (int i = t; i < 128 * 32; i += 256) {
            int n = i & 127, k = i >> 7;
            int gn = mbase + n;
            sA[n * 36 + k] = (gn < MTOT) ? tf32r(W[(size_t)(k0 + k) * MTOT + gn]) : 0.f;
        }
        for (int i = t; i < 512; i += 256) {
            int n = i >> 3, k4 = i & 7;
            float4 v = *(const float4*)&inb[(size_t)(n0 + n) * 128 + k0 + k4 * 4];
            *(float4*)&sB[n * 36 + k4 * 4] = v;
        }
        __syncthreads();
        #pragma unroll
        for (int ks = 0; ks < 4; ks++) {
            int kb = ks * 8;
            uint32_t a0, a1, a2, a3;
            ldsm_x4(a0, a1, a2, a3, aaddr + kb * 4);
            #pragma unroll
            for (int p = 0; p < 4; p++) {
                uint32_t b0, b1, b2, b3;
                ldsm_x4(b0, b1, b2, b3, baddr + (p * 16 * 36 + kb) * 4);
                mma_tf32(acc[2 * p],     a0, a1, a2, a3, b0, b1);
                mma_tf32(acc[2 * p + 1], a0, a1, a2, a3, b2, b3);
            }
        }
    }
    int m0 = mbase + warp * 16 + g, m1 = m0 + 8;
    float bi0 = (m0 < MTOT) ? bias[m0] : 0.f;
    float bi1 = (m1 < MTOT) ? bias[m1] : 0.f;
    #pragma unroll
    for (int j = 0; j < 8; j++) {
        long b = n0 + j * 8 + 2 * tg;
        float f00 = acc[j][0] + bi0, f01 = acc[j][1] + bi0;
        float f10 = acc[j][2] + bi1, f11 = acc[j][3] + bi1;
        if (STAGE == 1) {
            f00 = tf32r(fmaxf(f00, 0.f)); f01 = tf32r(fmaxf(f01, 0.f));
            f10 = tf32r(fmaxf(f10, 0.f)); f11 = tf32r(fmaxf(f11, 0.f));
            g_buf1[b * 128 + m0] = f00; g_buf1[(b + 1) * 128 + m0] = f01;
            g_buf1[b * 128 + m1] = f10; g_buf1[(b + 1) * 128 + m1] = f11;
        } else {
            if (m0 < MTOT) { outx[b * MTOT + m0] = f00; outx[(b + 1) * MTOT + m0] = f01; }
            if (m1 < MTOT) { outx[b * MTOT + m1] = f10; outx[(b + 1) * MTOT + m1] = f11; }
        }
    }
}

// ---------------- launch ------------------------------------------------------
extern "C" void kernel_launch(void* const* d_in, const int* in_sizes, int n_in,
                              void* d_out, int out_size) {
    const float* src     = (const float*)d_in[0];
    const int*   ei      = (const int*)d_in[1];
    const float* gcn1_w  = (const float*)d_in[2];
    const float* gcn1_b  = (const float*)d_in[3];
    const float* gcn2_w  = (const float*)d_in[4];
    const float* gcn2_b  = (const float*)d_in[5];
    const float* conv1_w = (const float*)d_in[6];
    const float* conv1_b = (const float*)d_in[7];
    const float* conv2_w = (const float*)d_in[8];
    const float* conv2_b = (const float*)d_in[9];
    const float* conv3_w = (const float*)d_in[10];
    const float* conv3_b = (const float*)d_in[11];
    const float* fc1_w   = (const float*)d_in[12];
    const float* fc1_b   = (const float*)d_in[13];
    const float* cls1_w  = (const float*)d_in[14];
    const float* cls1_b  = (const float*)d_in[15];
    const float* cls2_w  = (const float*)d_in[16];
    const float* cls2_b  = (const float*)d_in[17];

    int ne = in_sizes[1] / 2;

    float* out   = (float*)d_out;
    float* out_x = out;                          // [B,210]
    float* out_f = out + (size_t)BB * 210;       // [B,128]

    const int GCNB_SMEM = (64 * 20 + 32 * 68 + 128 * 20 + 128 * 68 + 64) * 4; // 59392
    cudaFuncSetAttribute(k_gcnBmma, cudaFuncAttributeMaxDynamicSharedMemorySize, GCNB_SMEM);

    k_build_adj<<<1, 256>>>(ei, ne);
    k_trW<<<dim3(96, 4), 256>>>(fc1_w);

    k_gcnAmma<<<2048, 256>>>(src);
    k_gcnBmma<<<BB * 96 / 128, 256, GCNB_SMEM>>>(gcn1_w, gcn1_b, gcn2_w);
    k_gcnCmma<<<4096, 256>>>(gcn2_b);

    k_convmma<64, 4, 2, 224, 7, 48, 96, 3, 0><<<dim3(3072, 1), 256>>>(conv1_w, conv1_b);
    k_convmma<128, 8, 1, 320, 5, 24, 48, 2, 1><<<dim3(3072, 1), 256>>>(conv2_w, conv2_b);
    k_convmma<128, 8, 1, 384, 3, 12, 24, 1, 0><<<dim3(1536, 2), 256>>>(conv3_w, conv3_b);

    k_fc1mma<<<256, 256>>>(fc1_b, out_f);
    k_clsmma<128, 1><<<dim3(128, 1), 256>>>(cls1_w, cls1_b, nullptr);
    k_clsmma<210, 2><<<dim3(128, 2), 256>>>(cls2_w, cls2_b, out_x);
}

// round 13
// speedup vs baseline: 4.0611x; 1.2431x over previous
#include <cuda_runtime.h>
#include <cstdint>
#include <math.h>

#define BB 8192

__device__ __forceinline__ float tf32r(float x) {
    uint32_t u;
    asm("cvt.rna.tf32.f32 %0, %1;" : "=r"(u) : "f"(x));
    return __uint_as_float(u);
}

__device__ __forceinline__ void mma_tf32(float c[4],
                                         uint32_t a0, uint32_t a1, uint32_t a2, uint32_t a3,
                                         uint32_t b0, uint32_t b1) {
    asm volatile(
        "mma.sync.aligned.m16n8k8.row.col.f32.tf32.tf32.f32 "
        "{%0,%1,%2,%3}, {%4,%5,%6,%7}, {%8,%9}, {%0,%1,%2,%3};"
        : "+f"(c[0]), "+f"(c[1]), "+f"(c[2]), "+f"(c[3])
        : "r"(a0), "r"(a1), "r"(a2), "r"(a3), "r"(b0), "r"(b1));
}

__device__ __forceinline__ void ldsm_x4(uint32_t& r0, uint32_t& r1, uint32_t& r2, uint32_t& r3,
                                        uint32_t addr) {
    asm volatile("ldmatrix.sync.aligned.m8n8.x4.shared.b16 {%0,%1,%2,%3}, [%4];"
                 : "=r"(r0), "=r"(r1), "=r"(r2), "=r"(r3) : "r"(addr));
}

__device__ __forceinline__ uint32_t smem_u32(const void* p) {
    return (uint32_t)__cvta_generic_to_shared(p);
}

__device__ __forceinline__ void cp_async16(uint32_t dst, const void* src) {
    asm volatile("cp.async.cg.shared.global [%0], [%1], 16;" :: "r"(dst), "l"(src));
}
__device__ __forceinline__ void cp_async4(uint32_t dst, const void* src, bool valid) {
    int sz = valid ? 4 : 0;
    asm volatile("cp.async.ca.shared.global [%0], [%1], 4, %2;"
                 :: "r"(dst), "l"(src), "r"(sz));
}
__device__ __forceinline__ void cp_commit() {
    asm volatile("cp.async.commit_group;");
}
template<int N>
__device__ __forceinline__ void cp_wait() {
    asm volatile("cp.async.wait_group %0;" :: "n"(N));
}

// ---------------- scratch ----------------------------------------------------
// g_buf1: Y [0,B*1536) | T [B*1536,B*4608) | Wt [B*4608,+393216) | conv w scratch
__device__ float g_A[96 * 96];
__device__ float g_buf1[(size_t)BB * 6144];
__device__ float g_buf2[(size_t)BB * 3072];

constexpr size_t WT_OFF  = (size_t)BB * 4608;
constexpr size_t CW1_OFF = WT_OFF + 393216;          // 64*224   = 14336
constexpr size_t CW2_OFF = CW1_OFF + 14336;          // 128*320  = 40960
constexpr size_t CW3_OFF = CW2_OFF + 40960;          // 256*384  = 98304

// ---------------- build dense normalized adjacency ---------------------------
__global__ void k_build_adj(const int* __restrict__ ei, int ne) {
    __shared__ float deg[96];
    __shared__ float dinv[96];
    int t = threadIdx.x;
    if (t < 96) deg[t] = 0.f;
    for (int i = t; i < 9216; i += 256) g_A[i] = 0.f;
    __syncthreads();
    for (int e = t; e < ne; e += 256) atomicAdd(&deg[ei[e]], 1.0f);
    if (t < 96) atomicAdd(&deg[t], 1.0f);
    __syncthreads();
    if (t < 96) dinv[t] = 1.0f / sqrtf(fmaxf(deg[t], 1e-12f));
    __syncthreads();
    for (int e = t; e < ne; e += 256) {
        int r = ei[e], c = ei[ne + e];
        atomicAdd(&g_A[r * 96 + c], dinv[r] * dinv[c]);
    }
    if (t < 96) atomicAdd(&g_A[t * 96 + t], dinv[t] * dinv[t]);
}

// ---------------- one-time weight prep ---------------------------------------
__global__ void k_trW(const float* __restrict__ W) {
    __shared__ float tile[32][33];
    float* Wt = g_buf1 + WT_OFF;
    int bx = blockIdx.x, by = blockIdx.y;
    int tx = threadIdx.x & 31, ty = threadIdx.x >> 5;
    for (int r = 0; r < 32; r += 8)
        tile[ty + r][tx] = W[(size_t)(bx * 32 + ty + r) * 128 + by * 32 + tx];
    __syncthreads();
    for (int r = 0; r < 32; r += 8)
        Wt[(size_t)(by * 32 + ty + r) * 3072 + bx * 32 + tx] = tf32r(tile[tx][ty + r]);
}

__global__ void k_prew(const float* __restrict__ w1, const float* __restrict__ w2,
                       const float* __restrict__ w3) {
    int i = blockIdx.x * 256 + threadIdx.x;
    if (i < 14336) g_buf1[CW1_OFF + i] = tf32r(w1[i]);
    if (i < 40960) g_buf1[CW2_OFF + i] = tf32r(w2[i]);
    if (i < 98304) g_buf1[CW3_OFF + i] = tf32r(w3[i]);
}

// ---------------- gcnA via mma: Y[n,(b,c)] = A@Xq ----------------------------
__global__ void __launch_bounds__(256, 3) k_gcnAmma(const float* __restrict__ src) {
    __shared__ float sA[128 * 36];
    __shared__ float sB[64 * 36];
    int t = threadIdx.x;
    int warp = t >> 5, lane = t & 31;
    int g = lane >> 2, tg = lane & 3;
    long n0 = (long)blockIdx.x * 64;
    float acc[8][4] = {};

    int atile = lane >> 3;
    int arow = warp * 16 + (lane & 7) + ((atile & 1) << 3);
    uint32_t aaddr = smem_u32(sA) + (uint32_t)(arow * 36 + (atile >> 1) * 4) * 4u;
    int brow = ((lane >> 4) << 3) + (lane & 7);
    uint32_t baddr = smem_u32(sB) + (uint32_t)(brow * 36 + ((lane >> 3) & 1) * 4) * 4u;

    for (int k0 = 0; k0 < 96; k0 += 32) {
        __syncthreads();
        for (int i = t; i < 128 * 8; i += 256) {
            int m = i >> 3, k4 = i & 7;
            float4 v = make_float4(0.f, 0.f, 0.f, 0.f);
            if (m < 96) {
                v = *(const float4*)&g_A[m * 96 + k0 + k4 * 4];
                v.x = tf32r(v.x); v.y = tf32r(v.y); v.z = tf32r(v.z); v.w = tf32r(v.w);
            }
            *(float4*)&sA[m * 36 + k4 * 4] = v;
        }
        for (int i = t; i < 64 * 32; i += 256) {
            int n = i >> 5, k = i & 31;
            long col = n0 + n;
            int b = (int)(col >> 4), c = (int)(col & 15);
            sB[n * 36 + k] = tf32r(src[(size_t)b * 1536 + c * 96 + k0 + k]);
        }
        __syncthreads();
        #pragma unroll
        for (int ks = 0; ks < 4; ks++) {
            int kb = ks * 8;
            uint32_t a0, a1, a2, a3;
            ldsm_x4(a0, a1, a2, a3, aaddr + kb * 4);
            #pragma unroll
            for (int p = 0; p < 4; p++) {
                uint32_t b0, b1, b2, b3;
                ldsm_x4(b0, b1, b2, b3, baddr + (p * 16 * 36 + kb) * 4);
                mma_tf32(acc[2 * p],     a0, a1, a2, a3, b0, b1);
                mma_tf32(acc[2 * p + 1], a0, a1, a2, a3, b2, b3);
            }
        }
    }
    int m0 = warp * 16 + g, m1 = m0 + 8;
    if (m0 < 96) {
        #pragma unroll
        for (int j = 0; j < 8; j++) {
            long nc = n0 + j * 8 + 2 * tg;
            int b = (int)(nc >> 4), c = (int)(nc & 15);
            float* yb = g_buf1 + (size_t)b * 1536;
            yb[m0 * 16 + c]     = acc[j][0];
            yb[m0 * 16 + c + 1] = acc[j][1];
            yb[m1 * 16 + c]     = acc[j][2];
            yb[m1 * 16 + c + 1] = acc[j][3];
        }
    }
}

// ---------------- gcnB via fused 2-stage mma (T stored pre-rounded) ----------
__global__ void __launch_bounds__(256, 3) k_gcnBmma(const float* __restrict__ W1,
                                                    const float* __restrict__ b1,
                                                    const float* __restrict__ W2) {
    extern __shared__ float sm[];
    float* sW1 = sm;                  // [64 f][20]
    float* sW2 = sW1 + 64 * 20;       // [32 g][68]
    float* sY  = sW2 + 32 * 68;       // [128 row][20]
    float* sH  = sY + 128 * 20;       // [128 row][68]
    float* sB1 = sH + 128 * 68;       // [64]
    int t = threadIdx.x;
    int warp = t >> 5, lane = t & 31;
    int g = lane >> 2, tg = lane & 3;
    size_t row0 = (size_t)blockIdx.x * 128;

    for (int i = t; i < 1024; i += 256) {
        int c = i >> 6, f = i & 63;
        sW1[f * 20 + c] = tf32r(W1[i]);
    }
    for (int i = t; i < 2048; i += 256) {
        int f = i >> 5, gg = i & 31;
        sW2[gg * 68 + f] = tf32r(W2[i]);
    }
    if (t < 64) sB1[t] = b1[t];
    for (int i = t; i < 128 * 4; i += 256) {
        int r = i >> 2, c4 = i & 3;
        float4 v = *(const float4*)&g_buf1[(row0 + r) * 16 + c4 * 4];
        v.x = tf32r(v.x); v.y = tf32r(v.y); v.z = tf32r(v.z); v.w = tf32r(v.w);
        *(float4*)&sY[r * 20 + c4 * 4] = v;
    }
    __syncthreads();

    {   // stage 1
        int wm = warp & 3, wn = warp >> 2;
        int atile = lane >> 3;
        int arow = wm * 16 + (lane & 7) + ((atile & 1) << 3);
        uint32_t aaddr = smem_u32(sW1) + (uint32_t)(arow * 20 + (atile >> 1) * 4) * 4u;
        int brow = wn * 64 + ((lane >> 4) << 3) + (lane & 7);
        uint32_t baddr = smem_u32(sY) + (uint32_t)(brow * 20 + ((lane >> 3) & 1) * 4) * 4u;

        float acc[8][4] = {};
        #pragma unroll
        for (int ks = 0; ks < 2; ks++) {
            int kb = ks * 8;
            uint32_t a0, a1, a2, a3;
            ldsm_x4(a0, a1, a2, a3, aaddr + kb * 4);
            #pragma unroll
            for (int p = 0; p < 4; p++) {
                uint32_t b0, b1, b2, b3;
                ldsm_x4(b0, b1, b2, b3, baddr + (p * 16 * 20 + kb) * 4);
                mma_tf32(acc[2 * p],     a0, a1, a2, a3, b0, b1);
                mma_tf32(acc[2 * p + 1], a0, a1, a2, a3, b2, b3);
            }
        }
        int m0 = wm * 16 + g, m1 = m0 + 8;
        float bi0 = sB1[m0], bi1 = sB1[m1];
        #pragma unroll
        for (int j = 0; j < 8; j++) {
            int r = wn * 64 + j * 8 + 2 * tg;
            sH[r * 68 + m0]       = tf32r(fmaxf(acc[j][0] + bi0, 0.f));
            sH[(r + 1) * 68 + m0] = tf32r(fmaxf(acc[j][1] + bi0, 0.f));
            sH[r * 68 + m1]       = tf32r(fmaxf(acc[j][2] + bi1, 0.f));
            sH[(r + 1) * 68 + m1] = tf32r(fmaxf(acc[j][3] + bi1, 0.f));
        }
    }
    __syncthreads();

    {   // stage 2
        int wm = warp & 1, wn = warp >> 1;
        int atile = lane >> 3;
        int arow = wm * 16 + (lane & 7) + ((atile & 1) << 3);
        uint32_t aaddr = smem_u32(sW2) + (uint32_t)(arow * 68 + (atile >> 1) * 4) * 4u;
        int brow = wn * 32 + ((lane >> 4) << 3) + (lane & 7);
        uint32_t baddr = smem_u32(sH) + (uint32_t)(brow * 68 + ((lane >> 3) & 1) * 4) * 4u;

        float acc[4][4] = {};
        #pragma unroll
        for (int ks = 0; ks < 8; ks++) {
            int kb = ks * 8;
            uint32_t a0, a1, a2, a3;
            ldsm_x4(a0, a1, a2, a3, aaddr + kb * 4);
            #pragma unroll
            for (int p = 0; p < 2; p++) {
                uint32_t b0, b1, b2, b3;
                ldsm_x4(b0, b1, b2, b3, baddr + (p * 16 * 68 + kb) * 4);
                mma_tf32(acc[2 * p],     a0, a1, a2, a3, b0, b1);
                mma_tf32(acc[2 * p + 1], a0, a1, a2, a3, b2, b3);
            }
        }
        int m0 = wm * 16 + g, m1 = m0 + 8;
        float* tp = g_buf1 + (size_t)BB * 1536 + row0 * 32;
        #pragma unroll
        for (int j = 0; j < 4; j++) {
            int r = wn * 32 + j * 8 + 2 * tg;
            tp[r * 32 + m0]       = tf32r(acc[j][0]);
            tp[(r + 1) * 32 + m0] = tf32r(acc[j][1]);
            tp[r * 32 + m1]       = tf32r(acc[j][2]);
            tp[(r + 1) * 32 + m1] = tf32r(acc[j][3]);
        }
    }
}

// ---------------- gcnC via mma: out[n,(b,g)] = relu(A@Tq + b2) ---------------
__global__ void __launch_bounds__(256, 3) k_gcnCmma(const float* __restrict__ b2) {
    __shared__ float sA[128 * 36];
    __shared__ float sB[64 * 36];
    int t = threadIdx.x;
    int warp = t >> 5, lane = t & 31;
    int g = lane >> 2, tg = lane & 3;
    long n0 = (long)blockIdx.x * 64;
    int b0 = blockIdx.x * 2;
    const float* T = g_buf1 + (size_t)BB * 1536;
    float acc[8][4] = {};

    int atile = lane >> 3;
    int arow = warp * 16 + (lane & 7) + ((atile & 1) << 3);
    uint32_t aaddr = smem_u32(sA) + (uint32_t)(arow * 36 + (atile >> 1) * 4) * 4u;
    int brow = ((lane >> 4) << 3) + (lane & 7);
    uint32_t baddr = smem_u32(sB) + (uint32_t)(brow * 36 + ((lane >> 3) & 1) * 4) * 4u;

    for (int k0 = 0; k0 < 96; k0 += 32) {
        __syncthreads();
        for (int i = t; i < 128 * 8; i += 256) {
            int m = i >> 3, k4 = i & 7;
            float4 v = make_float4(0.f, 0.f, 0.f, 0.f);
            if (m < 96) {
                v = *(const float4*)&g_A[m * 96 + k0 + k4 * 4];
                v.x = tf32r(v.x); v.y = tf32r(v.y); v.z = tf32r(v.z); v.w = tf32r(v.w);
            }
            *(float4*)&sA[m * 36 + k4 * 4] = v;
        }
        for (int i = t; i < 2048; i += 256) {      // T pre-rounded
            int bi = i >> 10, rem = i & 1023, m = rem >> 5, gg = rem & 31;
            sB[(bi * 32 + gg) * 36 + m] =
                T[(size_t)(b0 + bi) * 3072 + (k0 + m) * 32 + gg];
        }
        __syncthreads();
        #pragma unroll
        for (int ks = 0; ks < 4; ks++) {
            int kb = ks * 8;
            uint32_t a0, a1, a2, a3;
            ldsm_x4(a0, a1, a2, a3, aaddr + kb * 4);
            #pragma unroll
            for (int p = 0; p < 4; p++) {
                uint32_t b0f, b1f, b2f, b3f;
                ldsm_x4(b0f, b1f, b2f, b3f, baddr + (p * 16 * 36 + kb) * 4);
                mma_tf32(acc[2 * p],     a0, a1, a2, a3, b0f, b1f);
                mma_tf32(acc[2 * p + 1], a0, a1, a2, a3, b2f, b3f);
            }
        }
    }
    int m0 = warp * 16 + g, m1 = m0 + 8;
    if (m0 < 96) {
        #pragma unroll
        for (int j = 0; j < 8; j++) {
            long nc = n0 + j * 8 + 2 * tg;
            int b = (int)(nc >> 5), gg = (int)(nc & 31);
            float bg0 = b2[gg], bg1 = b2[gg + 1];
            float* ob = g_buf2 + (size_t)b * 3072;
            ob[gg * 96 + m0]       = tf32r(fmaxf(acc[j][0] + bg0, 0.f));
            ob[(gg + 1) * 96 + m0] = tf32r(fmaxf(acc[j][1] + bg1, 0.f));
            ob[gg * 96 + m1]       = tf32r(fmaxf(acc[j][2] + bg0, 0.f));
            ob[(gg + 1) * 96 + m1] = tf32r(fmaxf(acc[j][3] + bg1, 0.f));
        }
    }
}

// ---------------- conv implicit GEMM, cp.async double-buffered ---------------
template<int M_BLK, int WM, int WN, int KTOT, int KK, int NPOS, int LIN, int PAD,
         int IO, size_t WOFF>
__global__ void __launch_bounds__(256, 3) k_convmma(const float* __restrict__ bias) {
    const float* w  = g_buf1 + WOFF;               // pre-rounded weights
    const float* in = (IO == 0) ? g_buf2 : g_buf1;
    float* outp     = (IO == 0) ? g_buf1 : g_buf2;
    constexpr int N_BLK = WN * 64;
    extern __shared__ float smd[];
    float* sA = smd;                               // [2][M_BLK*36]
    float* sB = smd + 2 * M_BLK * 36;              // [2][N_BLK*36]
    int t = threadIdx.x;
    int warp = t >> 5, lane = t & 31;
    int g = lane >> 2, tg = lane & 3;
    int wm = warp % WM, wn = warp / WM;
    int mbase = blockIdx.y * M_BLK;
    long n0 = (long)blockIdx.x * N_BLK;

    float acc[8][4] = {};

    int atile = lane >> 3;
    int arow = wm * 16 + (lane & 7) + ((atile & 1) << 3);
    uint32_t aaddr = smem_u32(sA) + (uint32_t)(arow * 36 + (atile >> 1) * 4) * 4u;
    int brow = wn * 64 + ((lane >> 4) << 3) + (lane & 7);
    uint32_t baddr = smem_u32(sB) + (uint32_t)(brow * 36 + ((lane >> 3) & 1) * 4) * 4u;

    auto prefetch = [&](int k0, int s) {
        float* dA = sA + s * M_BLK * 36;
        for (int i = t; i < M_BLK * 8; i += 256) {
            int m = i >> 3, k4 = i & 7;
            cp_async16(smem_u32(&dA[m * 36 + k4 * 4]),
                       &w[(size_t)(mbase + m) * KTOT + k0 + k4 * 4]);
        }
        float* dB = sB + s * N_BLK * 36;
        for (int i = t; i < N_BLK * 32; i += 256) {
            int n = i >> 5, k = i & 31;
            long ng = n0 + n;
            int b = (int)(ng / NPOS), p = (int)(ng % NPOS);
            int kg = k0 + k;
            int ic = kg / KK, kk = kg - ic * KK;
            int pos = p * 2 + kk - PAD;
            bool valid = (pos >= 0 && pos < LIN);
            const float* sp = valid ? &in[(size_t)b * 3072 + ic * LIN + pos] : in;
            cp_async4(smem_u32(&dB[n * 36 + k]), sp, valid);
        }
    };

    constexpr int NCH = KTOT / 32;
    prefetch(0, 0);
    cp_commit();
    for (int i = 0; i < NCH; i++) {
        int cur = i & 1;
        if (i + 1 < NCH) {
            prefetch((i + 1) * 32, cur ^ 1);
            cp_commit();
            cp_wait<1>();
        } else {
            cp_wait<0>();
        }
        __syncthreads();
        uint32_t aS = (uint32_t)cur * (M_BLK * 36 * 4);
        uint32_t bS = (uint32_t)cur * (N_BLK * 36 * 4);
        #pragma unroll
        for (int ks = 0; ks < 4; ks++) {
            int kb = ks * 8;
            uint32_t a0, a1, a2, a3;
            ldsm_x4(a0, a1, a2, a3, aaddr + aS + kb * 4);
            #pragma unroll
            for (int p = 0; p < 4; p++) {
                uint32_t b0, b1, b2, b3;
                ldsm_x4(b0, b1, b2, b3, baddr + bS + (p * 16 * 36 + kb) * 4);
                mma_tf32(acc[2 * p],     a0, a1, a2, a3, b0, b1);
                mma_tf32(acc[2 * p + 1], a0, a1, a2, a3, b2, b3);
            }
        }
        __syncthreads();
    }
    int m0 = mbase + wm * 16 + g;
    int m1 = m0 + 8;
    float bi0 = bias[m0], bi1 = bias[m1];
    #pragma unroll
    for (int j = 0; j < 8; j++) {
        long nc = n0 + wn * 64 + j * 8 + 2 * tg;
        int b = (int)(nc / NPOS), p = (int)(nc % NPOS);
        float* ob = outp + (size_t)b * 3072;
        ob[m0 * NPOS + p]     = tf32r(fmaxf(acc[j][0] + bi0, 0.f));
        ob[m0 * NPOS + p + 1] = tf32r(fmaxf(acc[j][1] + bi0, 0.f));
        ob[m1 * NPOS + p]     = tf32r(fmaxf(acc[j][2] + bi1, 0.f));
        ob[m1 * NPOS + p + 1] = tf32r(fmaxf(acc[j][3] + bi1, 0.f));
    }
}

// ---------------- fc1 via mma, cp.async double-buffered ----------------------
__global__ void __launch_bounds__(256, 3) k_fc1mma(const float* __restrict__ bias,
                                                   float* __restrict__ feat_out) {
    const float* Wt = g_buf1 + WT_OFF;
    extern __shared__ float smd[];
    float* sA = smd;                   // [2][128*36]
    float* sB = smd + 2 * 128 * 36;    // [2][32*36]
    int t = threadIdx.x;
    int warp = t >> 5, lane = t & 31;
    int g = lane >> 2, tg = lane & 3;
    long n0 = (long)blockIdx.x * 32;
    float acc[4][4] = {};

    int atile = lane >> 3;
    int arow = warp * 16 + (lane & 7) + ((atile & 1) << 3);
    uint32_t aaddr = smem_u32(sA) + (uint32_t)(arow * 36 + (atile >> 1) * 4) * 4u;
    int brow = ((lane >> 4) << 3) + (lane & 7);
    uint32_t baddr = smem_u32(sB) + (uint32_t)(brow * 36 + ((lane >> 3) & 1) * 4) * 4u;

    auto prefetch = [&](int k0, int s) {
        float* dA = sA + s * 128 * 36;
        for (int i = t; i < 1024; i += 256) {
            int m = i >> 3, k4 = i & 7;
            cp_async16(smem_u32(&dA[m * 36 + k4 * 4]),
                       &Wt[(size_t)m * 3072 + k0 + k4 * 4]);
        }
        float* dB = sB + s * 32 * 36;
        for (int i = t; i < 256; i += 256) {
            int n = i >> 3, k4 = i & 7;
            cp_async16(smem_u32(&dB[n * 36 + k4 * 4]),
                       &g_buf1[(size_t)(n0 + n) * 3072 + k0 + k4 * 4]);
        }
    };

    prefetch(0, 0);
    cp_commit();
    for (int i = 0; i < 96; i++) {
        int cur = i & 1;
        if (i + 1 < 96) {
            prefetch((i + 1) * 32, cur ^ 1);
            cp_commit();
            cp_wait<1>();
        } else {
            cp_wait<0>();
        }
        __syncthreads();
        uint32_t aS = (uint32_t)cur * (128 * 36 * 4);
        uint32_t bS = (uint32_t)cur * (32 * 36 * 4);
        #pragma unroll
        for (int ks = 0; ks < 4; ks++) {
            int kb = ks * 8;
            uint32_t a0, a1, a2, a3;
            ldsm_x4(a0, a1, a2, a3, aaddr + aS + kb * 4);
            #pragma unroll
            for (int p = 0; p < 2; p++) {
                uint32_t b0, b1, b2, b3;
                ldsm_x4(b0, b1, b2, b3, baddr + bS + (p * 16 * 36 + kb) * 4);
                mma_tf32(acc[2 * p],     a0, a1, a2, a3, b0, b1);
                mma_tf32(acc[2 * p + 1], a0, a1, a2, a3, b2, b3);
            }
        }
        __syncthreads();
    }
    int m0 = warp * 16 + g, m1 = m0 + 8;
    float bi0 = bias[m0], bi1 = bias[m1];
    #pragma unroll
    for (int j = 0; j < 4; j++) {
        long n = n0 + j * 8 + 2 * tg;
        float f00 = acc[j][0] + bi0, f01 = acc[j][1] + bi0;
        float f10 = acc[j][2] + bi1, f11 = acc[j][3] + bi1;
        feat_out[n * 128 + m0] = f00;       feat_out[(n + 1) * 128 + m0] = f01;
        feat_out[n * 128 + m1] = f10;       feat_out[(n + 1) * 128 + m1] = f11;
        g_buf2[n * 128 + m0] = tf32r(fmaxf(f00, 0.f));
        g_buf2[(n + 1) * 128 + m0] = tf32r(fmaxf(f01, 0.f));
        g_buf2[n * 128 + m1] = tf32r(fmaxf(f10, 0.f));
        g_buf2[(n + 1) * 128 + m1] = tf32r(fmaxf(f11, 0.f));
    }
}

// ---------------- cls via mma: C[feat, batch], K=128 -------------------------
template<int MTOT, int STAGE>
__global__ void __launch_bounds__(256, 3) k_clsmma(const float* __restrict__ W,
                                                   const float* __restrict__ bias,
                                                   float* __restrict__ outx) {
    const float* inb = (STAGE == 1) ? g_buf2 : g_buf1;
    __shared__ float sA[128 * 36];
    __shared__ float sB[64 * 36];
    int t = threadIdx.x;
    int warp = t >> 5, lane = t & 31;
    int g = lane >> 2, tg = lane & 3;
    int mbase = blockIdx.y * 128;
    long n0 = (long)blockIdx.x * 64;
    float acc[8][4] = {};

    int atile = lane >> 3;
    int arow = warp * 16 + (lane & 7) + ((atile & 1) << 3);
    uint32_t aaddr = smem_u32(sA) + (uint32_t)(arow * 36 + (atile >> 1) * 4) * 4u;
    int brow = ((lane >> 4) << 3) + (lane & 7);
    uint32_t baddr = smem_u32(sB) + (uint32_t)(brow * 36 + ((lane >> 3) & 1) * 4) * 4u;

    for (int k0 = 0; k0 < 128; k0 += 32) {
        __syncthreads();
        for (int i = t; i < 128 * 32; i += 256) {
            int n = i & 127, k = i >> 7;
            int gn = mbase + n;
            sA[n * 36 + k] = (gn < MTOT) ? tf32r(W[(size_t)(k0 + k) * MTOT + gn]) : 0.f;
        }
        for (int i = t; i < 512; i += 256) {
            int n = i >> 3, k4 = i & 7;
            float4 v = *(const float4*)&inb[(size_t)(n0 + n) * 128 + k0 + k4 * 4];
            *(float4*)&sB[n * 36 + k4 * 4] = v;
        }
        __syncthreads();
        #pragma unroll
        for (int ks = 0; ks < 4; ks++) {
            int kb = ks * 8;
            uint32_t a0, a1, a2, a3;
            ldsm_x4(a0, a1, a2, a3, aaddr + kb * 4);
            #pragma unroll
            for (int p = 0; p < 4; p++) {
                uint32_t b0, b1, b2, b3;
                ldsm_x4(b0, b1, b2, b3, baddr + (p * 16 * 36 + kb) * 4);
                mma_tf32(acc[2 * p],     a0, a1, a2, a3, b0, b1);
                mma_tf32(acc[2 * p + 1], a0, a1, a2, a3, b2, b3);
            }
        }
    }
    int m0 = mbase + warp * 16 + g, m1 = m0 + 8;
    float bi0 = (m0 < MTOT) ? bias[m0] : 0.f;
    float bi1 = (m1 < MTOT) ? bias[m1] : 0.f;
    #pragma unroll
    for (int j = 0; j < 8; j++) {
        long b = n0 + j * 8 + 2 * tg;
        float f00 = acc[j][0] + bi0, f01 = acc[j][1] + bi0;
        float f10 = acc[j][2] + bi1, f11 = acc[j][3] + bi1;
        if (STAGE == 1) {
            f00 = tf32r(fmaxf(f00, 0.f)); f01 = tf32r(fmaxf(f01, 0.f));
            f10 = tf32r(fmaxf(f10, 0.f)); f11 = tf32r(fmaxf(f11, 0.f));
            g_buf1[b * 128 + m0] = f00; g_buf1[(b + 1) * 128 + m0] = f01;
            g_buf1[b * 128 + m1] = f10; g_buf1[(b + 1) * 128 + m1] = f11;
        } else {
            if (m0 < MTOT) { outx[b * MTOT + m0] = f00; outx[(b + 1) * MTOT + m0] = f01; }
            if (m1 < MTOT) { outx[b * MTOT + m1] = f10; outx[(b + 1) * MTOT + m1] = f11; }
        }
    }
}

// ---------------- launch ------------------------------------------------------
extern "C" void kernel_launch(void* const* d_in, const int* in_sizes, int n_in,
                              void* d_out, int out_size) {
    const float* src     = (const float*)d_in[0];
    const int*   ei      = (const int*)d_in[1];
    const float* gcn1_w  = (const float*)d_in[2];
    const float* gcn1_b  = (const float*)d_in[3];
    const float* gcn2_w  = (const float*)d_in[4];
    const float* gcn2_b  = (const float*)d_in[5];
    const float* conv1_w = (const float*)d_in[6];
    const float* conv1_b = (const float*)d_in[7];
    const float* conv2_w = (const float*)d_in[8];
    const float* conv2_b = (const float*)d_in[9];
    const float* conv3_w = (const float*)d_in[10];
    const float* conv3_b = (const float*)d_in[11];
    const float* fc1_w   = (const float*)d_in[12];
    const float* fc1_b   = (const float*)d_in[13];
    const float* cls1_w  = (const float*)d_in[14];
    const float* cls1_b  = (const float*)d_in[15];
    const float* cls2_w  = (const float*)d_in[16];
    const float* cls2_b  = (const float*)d_in[17];

    int ne = in_sizes[1] / 2;

    float* out   = (float*)d_out;
    float* out_x = out;                          // [B,210]
    float* out_f = out + (size_t)BB * 210;       // [B,128]

    const int GCNB_SMEM  = (64 * 20 + 32 * 68 + 128 * 20 + 128 * 68 + 64) * 4;
    const int CONV_SMEM  = 2 * (192) * 36 * 4;   // (M_BLK+N_BLK)=192 for all convs: 55296
    const int FC1_SMEM   = 2 * (160) * 36 * 4;   // 46080

    cudaFuncSetAttribute(k_gcnBmma, cudaFuncAttributeMaxDynamicSharedMemorySize, GCNB_SMEM);
    cudaFuncSetAttribute(k_convmma<64, 4, 2, 224, 7, 48, 96, 3, 0, CW1_OFF>,
                         cudaFuncAttributeMaxDynamicSharedMemorySize, CONV_SMEM);
    cudaFuncSetAttribute(k_convmma<128, 8, 1, 320, 5, 24, 48, 2, 1, CW2_OFF>,
                         cudaFuncAttributeMaxDynamicSharedMemorySize, CONV_SMEM);
    cudaFuncSetAttribute(k_convmma<128, 8, 1, 384, 3, 12, 24, 1, 0, CW3_OFF>,
                         cudaFuncAttributeMaxDynamicSharedMemorySize, CONV_SMEM);
    cudaFuncSetAttribute(k_fc1mma, cudaFuncAttributeMaxDynamicSharedMemorySize, FC1_SMEM);

    k_build_adj<<<1, 256>>>(ei, ne);
    k_trW<<<dim3(96, 4), 256>>>(fc1_w);
    k_prew<<<384, 256>>>(conv1_w, conv2_w, conv3_w);

    k_gcnAmma<<<2048, 256>>>(src);
    k_gcnBmma<<<BB * 96 / 128, 256, GCNB_SMEM>>>(gcn1_w, gcn1_b, gcn2_w);
    k_gcnCmma<<<4096, 256>>>(gcn2_b);

    k_convmma<64, 4, 2, 224, 7, 48, 96, 3, 0, CW1_OFF>
        <<<dim3(3072, 1), 256, CONV_SMEM>>>(conv1_b);
    k_convmma<128, 8, 1, 320, 5, 24, 48, 2, 1, CW2_OFF>
        <<<dim3(3072, 1), 256, CONV_SMEM>>>(conv2_b);
    k_convmma<128, 8, 1, 384, 3, 12, 24, 1, 0, CW3_OFF>
        <<<dim3(1536, 2), 256, CONV_SMEM>>>(conv3_b);

    k_fc1mma<<<256, 256, FC1_SMEM>>>(fc1_b, out_f);
    k_clsmma<128, 1><<<dim3(128, 1), 256>>>(cls1_w, cls1_b, nullptr);
    k_clsmma<210, 2><<<dim3(128, 2), 256>>>(cls2_w, cls2_b, out_x);
}

// round 14
// speedup vs baseline: 5.5271x; 1.3610x over previous
#include <cuda_runtime.h>
#include <cstdint>
#include <math.h>

#define BB 8192

__device__ __forceinline__ float tf32r(float x) {
    uint32_t u;
    asm("cvt.rna.tf32.f32 %0, %1;" : "=r"(u) : "f"(x));
    return __uint_as_float(u);
}

__device__ __forceinline__ void mma_tf32(float c[4],
                                         uint32_t a0, uint32_t a1, uint32_t a2, uint32_t a3,
                                         uint32_t b0, uint32_t b1) {
    asm volatile(
        "mma.sync.aligned.m16n8k8.row.col.f32.tf32.tf32.f32 "
        "{%0,%1,%2,%3}, {%4,%5,%6,%7}, {%8,%9}, {%0,%1,%2,%3};"
        : "+f"(c[0]), "+f"(c[1]), "+f"(c[2]), "+f"(c[3])
        : "r"(a0), "r"(a1), "r"(a2), "r"(a3), "r"(b0), "r"(b1));
}

__device__ __forceinline__ void ldsm_x4(uint32_t& r0, uint32_t& r1, uint32_t& r2, uint32_t& r3,
                                        uint32_t addr) {
    asm volatile("ldmatrix.sync.aligned.m8n8.x4.shared.b16 {%0,%1,%2,%3}, [%4];"
                 : "=r"(r0), "=r"(r1), "=r"(r2), "=r"(r3) : "r"(addr));
}

__device__ __forceinline__ uint32_t smem_u32(const void* p) {
    return (uint32_t)__cvta_generic_to_shared(p);
}

__device__ __forceinline__ void cp_async16(uint32_t dst, const void* src) {
    asm volatile("cp.async.cg.shared.global [%0], [%1], 16;" :: "r"(dst), "l"(src));
}
__device__ __forceinline__ void cp_async16z(uint32_t dst, const void* src, bool valid) {
    int sz = valid ? 16 : 0;
    asm volatile("cp.async.cg.shared.global [%0], [%1], 16, %2;"
                 :: "r"(dst), "l"(src), "r"(sz));
}
__device__ __forceinline__ void cp_commit() {
    asm volatile("cp.async.commit_group;");
}
template<int N>
__device__ __forceinline__ void cp_wait() {
    asm volatile("cp.async.wait_group %0;" :: "n"(N));
}

// ---------------- scratch ----------------------------------------------------
// g_buf1: Y [0,B*1536) | T [B*1536,B*4608) | Wt | CW1 | CW2 | CW3 | CWC1 | CWC2
__device__ float g_A[96 * 96];
__device__ float g_Aq[128 * 96];                 // tf32-rounded, rows 96..127 zero
__device__ float g_buf1[(size_t)BB * 6144];
__device__ float g_buf2[(size_t)BB * 3072];

constexpr size_t WT_OFF   = (size_t)BB * 4608;
constexpr size_t CW1_OFF  = WT_OFF + 393216;     // 64*224  = 14336
constexpr size_t CW2_OFF  = CW1_OFF + 14336;     // 128*320 = 40960
constexpr size_t CW3_OFF  = CW2_OFF + 40960;     // 256*384 = 98304
constexpr size_t CWC1_OFF = CW3_OFF + 98304;     // 128*128 = 16384
constexpr size_t CWC2_OFF = CWC1_OFF + 16384;    // 256*128 = 32768 (rows>=210 zero)

// ---------------- build dense normalized adjacency ---------------------------
__global__ void k_build_adj(const int* __restrict__ ei, int ne) {
    __shared__ float deg[96];
    __shared__ float dinv[96];
    int t = threadIdx.x;
    if (t < 96) deg[t] = 0.f;
    for (int i = t; i < 9216; i += 256) g_A[i] = 0.f;
    __syncthreads();
    for (int e = t; e < ne; e += 256) atomicAdd(&deg[ei[e]], 1.0f);
    if (t < 96) atomicAdd(&deg[t], 1.0f);
    __syncthreads();
    if (t < 96) dinv[t] = 1.0f / sqrtf(fmaxf(deg[t], 1e-12f));
    __syncthreads();
    for (int e = t; e < ne; e += 256) {
        int r = ei[e], c = ei[ne + e];
        atomicAdd(&g_A[r * 96 + c], dinv[r] * dinv[c]);
    }
    if (t < 96) atomicAdd(&g_A[t * 96 + t], dinv[t] * dinv[t]);
}

__global__ void k_prea() {                        // rounded, zero-padded A
    int i = blockIdx.x * 256 + threadIdx.x;       // 12288
    if (i < 128 * 96) g_Aq[i] = (i < 9216) ? tf32r(g_A[i]) : 0.f;
}

// ---------------- one-time weight prep ---------------------------------------
// fc1: Wt[m][k_new], k_new = p*256+c  <->  k_orig = c*12+p
__global__ void k_trW(const float* __restrict__ W) {
    float* Wt = g_buf1 + WT_OFF;
    int i = blockIdx.x * 256 + threadIdx.x;       // 128*3072
    if (i < 393216) {
        int m = i / 3072, kn = i % 3072;
        int p = kn >> 8, c = kn & 255;
        Wt[i] = tf32r(W[(size_t)(c * 12 + p) * 128 + m]);
    }
}

// conv weights reordered tap-major: cw[o][kk*IC+ic] = w[o][ic][kk]; cls transposed
__global__ void k_prew(const float* __restrict__ w1, const float* __restrict__ w2,
                       const float* __restrict__ w3, const float* __restrict__ c1,
                       const float* __restrict__ c2) {
    int i = blockIdx.x * 256 + threadIdx.x;
    if (i < 14336) {                               // conv1: IC=32, KK=7
        int o = i / 224, r = i % 224, ic = r / 7, kk = r % 7;
        g_buf1[CW1_OFF + o * 224 + kk * 32 + ic] = tf32r(w1[i]);
    }
    if (i < 40960) {                               // conv2: IC=64, KK=5
        int o = i / 320, r = i % 320, ic = r / 5, kk = r % 5;
        g_buf1[CW2_OFF + o * 320 + kk * 64 + ic] = tf32r(w2[i]);
    }
    if (i < 98304) {                               // conv3: IC=128, KK=3
        int o = i / 384, r = i % 384, ic = r / 3, kk = r % 3;
        g_buf1[CW3_OFF + o * 384 + kk * 128 + ic] = tf32r(w3[i]);
    }
    if (i < 16384) {                               // cls1: [m][k] from [k][m]
        int m = i >> 7, k = i & 127;
        g_buf1[CWC1_OFF + i] = tf32r(c1[(size_t)k * 128 + m]);
    }
    if (i < 32768) {                               // cls2: [m][k], rows>=210 zero
        int m = i >> 7, k = i & 127;
        g_buf1[CWC2_OFF + i] = (m < 210) ? tf32r(c2[(size_t)k * 210 + m]) : 0.f;
    }
}

// ---------------- gcnA via mma: Y[n,(b,c)] = A@Xq ----------------------------
__global__ void __launch_bounds__(256, 3) k_gcnAmma(const float* __restrict__ src) {
    __shared__ float sA[128 * 36];
    __shared__ float sB[64 * 36];
    int t = threadIdx.x;
    int warp = t >> 5, lane = t & 31;
    int g = lane >> 2, tg = lane & 3;
    long n0 = (long)blockIdx.x * 64;
    float acc[8][4] = {};

    int atile = lane >> 3;
    int arow = warp * 16 + (lane & 7) + ((atile & 1) << 3);
    uint32_t aaddr = smem_u32(sA) + (uint32_t)(arow * 36 + (atile >> 1) * 4) * 4u;
    int brow = ((lane >> 4) << 3) + (lane & 7);
    uint32_t baddr = smem_u32(sB) + (uint32_t)(brow * 36 + ((lane >> 3) & 1) * 4) * 4u;

    for (int k0 = 0; k0 < 96; k0 += 32) {
        __syncthreads();
        for (int i = t; i < 128 * 8; i += 256) {
            int m = i >> 3, k4 = i & 7;
            *(float4*)&sA[m * 36 + k4 * 4] = *(const float4*)&g_Aq[m * 96 + k0 + k4 * 4];
        }
        for (int i = t; i < 64 * 32; i += 256) {
            int n = i >> 5, k = i & 31;
            long col = n0 + n;
            int b = (int)(col >> 4), c = (int)(col & 15);
            sB[n * 36 + k] = tf32r(src[(size_t)b * 1536 + c * 96 + k0 + k]);
        }
        __syncthreads();
        #pragma unroll
        for (int ks = 0; ks < 4; ks++) {
            int kb = ks * 8;
            uint32_t a0, a1, a2, a3;
            ldsm_x4(a0, a1, a2, a3, aaddr + kb * 4);
            #pragma unroll
            for (int p = 0; p < 4; p++) {
                uint32_t b0, b1, b2, b3;
                ldsm_x4(b0, b1, b2, b3, baddr + (p * 16 * 36 + kb) * 4);
                mma_tf32(acc[2 * p],     a0, a1, a2, a3, b0, b1);
                mma_tf32(acc[2 * p + 1], a0, a1, a2, a3, b2, b3);
            }
        }
    }
    int m0 = warp * 16 + g, m1 = m0 + 8;
    if (m0 < 96) {
        #pragma unroll
        for (int j = 0; j < 8; j++) {
            long nc = n0 + j * 8 + 2 * tg;
            int b = (int)(nc >> 4), c = (int)(nc & 15);
            float* yb = g_buf1 + (size_t)b * 1536;
            yb[m0 * 16 + c]     = acc[j][0];
            yb[m0 * 16 + c + 1] = acc[j][1];
            yb[m1 * 16 + c]     = acc[j][2];
            yb[m1 * 16 + c + 1] = acc[j][3];
        }
    }
}

// ---------------- gcnB via fused 2-stage mma (T stored pre-rounded) ----------
__global__ void __launch_bounds__(256, 3) k_gcnBmma(const float* __restrict__ W1,
                                                    const float* __restrict__ b1,
                                                    const float* __restrict__ W2) {
    extern __shared__ float sm[];
    float* sW1 = sm;                  // [64 f][20]
    float* sW2 = sW1 + 64 * 20;       // [32 g][68]
    float* sY  = sW2 + 32 * 68;       // [128 row][20]
    float* sH  = sY + 128 * 20;       // [128 row][68]
    float* sB1 = sH + 128 * 68;       // [64]
    int t = threadIdx.x;
    int warp = t >> 5, lane = t & 31;
    int g = lane >> 2, tg = lane & 3;
    size_t row0 = (size_t)blockIdx.x * 128;

    for (int i = t; i < 1024; i += 256) {
        int c = i >> 6, f = i & 63;
        sW1[f * 20 + c] = tf32r(W1[i]);
    }
    for (int i = t; i < 2048; i += 256) {
        int f = i >> 5, gg = i & 31;
        sW2[gg * 68 + f] = tf32r(W2[i]);
    }
    if (t < 64) sB1[t] = b1[t];
    for (int i = t; i < 128 * 4; i += 256) {
        int r = i >> 2, c4 = i & 3;
        float4 v = *(const float4*)&g_buf1[(row0 + r) * 16 + c4 * 4];
        v.x = tf32r(v.x); v.y = tf32r(v.y); v.z = tf32r(v.z); v.w = tf32r(v.w);
        *(float4*)&sY[r * 20 + c4 * 4] = v;
    }
    __syncthreads();

    {   // stage 1
        int wm = warp & 3, wn = warp >> 2;
        int atile = lane >> 3;
        int arow = wm * 16 + (lane & 7) + ((atile & 1) << 3);
        uint32_t aaddr = smem_u32(sW1) + (uint32_t)(arow * 20 + (atile >> 1) * 4) * 4u;
        int brow = wn * 64 + ((lane >> 4) << 3) + (lane & 7);
        uint32_t baddr = smem_u32(sY) + (uint32_t)(brow * 20 + ((lane >> 3) & 1) * 4) * 4u;

        float acc[8][4] = {};
        #pragma unroll
        for (int ks = 0; ks < 2; ks++) {
            int kb = ks * 8;
            uint32_t a0, a1, a2, a3;
            ldsm_x4(a0, a1, a2, a3, aaddr + kb * 4);
            #pragma unroll
            for (int p = 0; p < 4; p++) {
                uint32_t b0, b1, b2, b3;
                ldsm_x4(b0, b1, b2, b3, baddr + (p * 16 * 20 + kb) * 4);
                mma_tf32(acc[2 * p],     a0, a1, a2, a3, b0, b1);
                mma_tf32(acc[2 * p + 1], a0, a1, a2, a3, b2, b3);
            }
        }
        int m0 = wm * 16 + g, m1 = m0 + 8;
        float bi0 = sB1[m0], bi1 = sB1[m1];
        #pragma unroll
        for (int j = 0; j < 8; j++) {
            int r = wn * 64 + j * 8 + 2 * tg;
            sH[r * 68 + m0]       = tf32r(fmaxf(acc[j][0] + bi0, 0.f));
            sH[(r + 1) * 68 + m0] = tf32r(fmaxf(acc[j][1] + bi0, 0.f));
            sH[r * 68 + m1]       = tf32r(fmaxf(acc[j][2] + bi1, 0.f));
            sH[(r + 1) * 68 + m1] = tf32r(fmaxf(acc[j][3] + bi1, 0.f));
        }
    }
    __syncthreads();

    {   // stage 2
        int wm = warp & 1, wn = warp >> 1;
        int atile = lane >> 3;
        int arow = wm * 16 + (lane & 7) + ((atile & 1) << 3);
        uint32_t aaddr = smem_u32(sW2) + (uint32_t)(arow * 68 + (atile >> 1) * 4) * 4u;
        int brow = wn * 32 + ((lane >> 4) << 3) + (lane & 7);
        uint32_t baddr = smem_u32(sH) + (uint32_t)(brow * 68 + ((lane >> 3) & 1) * 4) * 4u;

        float acc[4][4] = {};
        #pragma unroll
        for (int ks = 0; ks < 8; ks++) {
            int kb = ks * 8;
            uint32_t a0, a1, a2, a3;
            ldsm_x4(a0, a1, a2, a3, aaddr + kb * 4);
            #pragma unroll
            for (int p = 0; p < 2; p++) {
                uint32_t b0, b1, b2, b3;
                ldsm_x4(b0, b1, b2, b3, baddr + (p * 16 * 68 + kb) * 4);
                mma_tf32(acc[2 * p],     a0, a1, a2, a3, b0, b1);
                mma_tf32(acc[2 * p + 1], a0, a1, a2, a3, b2, b3);
            }
        }
        int m0 = wm * 16 + g, m1 = m0 + 8;
        float* tp = g_buf1 + (size_t)BB * 1536 + row0 * 32;
        #pragma unroll
        for (int j = 0; j < 4; j++) {
            int r = wn * 32 + j * 8 + 2 * tg;
            tp[r * 32 + m0]       = tf32r(acc[j][0]);
            tp[(r + 1) * 32 + m0] = tf32r(acc[j][1]);
            tp[r * 32 + m1]       = tf32r(acc[j][2]);
            tp[(r + 1) * 32 + m1] = tf32r(acc[j][3]);
        }
    }
}

// ---------------- gcnC via mma: out[b][pos][32ch] = relu(A@Tq + b2) ----------
__global__ void __launch_bounds__(256, 3) k_gcnCmma(const float* __restrict__ b2) {
    __shared__ float sA[128 * 36];
    __shared__ float sB[64 * 36];
    int t = threadIdx.x;
    int warp = t >> 5, lane = t & 31;
    int g = lane >> 2, tg = lane & 3;
    long n0 = (long)blockIdx.x * 64;
    int b0 = blockIdx.x * 2;
    const float* T = g_buf1 + (size_t)BB * 1536;
    float acc[8][4] = {};

    int atile = lane >> 3;
    int arow = warp * 16 + (lane & 7) + ((atile & 1) << 3);
    uint32_t aaddr = smem_u32(sA) + (uint32_t)(arow * 36 + (atile >> 1) * 4) * 4u;
    int brow = ((lane >> 4) << 3) + (lane & 7);
    uint32_t baddr = smem_u32(sB) + (uint32_t)(brow * 36 + ((lane >> 3) & 1) * 4) * 4u;

    for (int k0 = 0; k0 < 96; k0 += 32) {
        __syncthreads();
        for (int i = t; i < 128 * 8; i += 256) {
            int m = i >> 3, k4 = i & 7;
            *(float4*)&sA[m * 36 + k4 * 4] = *(const float4*)&g_Aq[m * 96 + k0 + k4 * 4];
        }
        for (int i = t; i < 2048; i += 256) {      // T pre-rounded, transpose gather
            int bi = i >> 10, rem = i & 1023, m = rem >> 5, gg = rem & 31;
            sB[(bi * 32 + gg) * 36 + m] =
                T[(size_t)(b0 + bi) * 3072 + (k0 + m) * 32 + gg];
        }
        __syncthreads();
        #pragma unroll
        for (int ks = 0; ks < 4; ks++) {
            int kb = ks * 8;
            uint32_t a0, a1, a2, a3;
            ldsm_x4(a0, a1, a2, a3, aaddr + kb * 4);
            #pragma unroll
            for (int p = 0; p < 4; p++) {
                uint32_t b0f, b1f, b2f, b3f;
                ldsm_x4(b0f, b1f, b2f, b3f, baddr + (p * 16 * 36 + kb) * 4);
                mma_tf32(acc[2 * p],     a0, a1, a2, a3, b0f, b1f);
                mma_tf32(acc[2 * p + 1], a0, a1, a2, a3, b2f, b3f);
            }
        }
    }
    int m0 = warp * 16 + g, m1 = m0 + 8;
    if (m0 < 96) {
        #pragma unroll
        for (int j = 0; j < 8; j++) {
            long nc = n0 + j * 8 + 2 * tg;
            int b = (int)(nc >> 5), gg = (int)(nc & 31);
            float bg0 = b2[gg], bg1 = b2[gg + 1];
            float* ob = g_buf2 + (size_t)b * 3072;        // [pos][32ch]
            ob[m0 * 32 + gg]     = tf32r(fmaxf(acc[j][0] + bg0, 0.f));
            ob[m0 * 32 + gg + 1] = tf32r(fmaxf(acc[j][1] + bg1, 0.f));
            ob[m1 * 32 + gg]     = tf32r(fmaxf(acc[j][2] + bg0, 0.f));
            ob[m1 * 32 + gg + 1] = tf32r(fmaxf(acc[j][3] + bg1, 0.f));
        }
    }
}

// ---------------- conv implicit GEMM, channel-last, cp.async 16B -------------
// K tap-major: k = kk*IC + ic. in: [b][pos][IC]. out: [b][pos][OC].
template<int M_BLK, int WM, int WN, int KTOT, int IC, int NPOS, int LIN, int PAD,
         int OC, int IO, size_t WOFF>
__global__ void __launch_bounds__(256, 3) k_convmma(const float* __restrict__ bias) {
    const float* w  = g_buf1 + WOFF;
    const float* in = (IO == 0) ? g_buf2 : g_buf1;
    float* outp     = (IO == 0) ? g_buf1 : g_buf2;
    constexpr int N_BLK = WN * 64;
    extern __shared__ float smd[];
    float* sA = smd;                               // [2][M_BLK*36]
    float* sB = smd + 2 * M_BLK * 36;              // [2][N_BLK*36]
    int t = threadIdx.x;
    int warp = t >> 5, lane = t & 31;
    int g = lane >> 2, tg = lane & 3;
    int wm = warp % WM, wn = warp / WM;
    int mbase = blockIdx.y * M_BLK;
    long n0 = (long)blockIdx.x * N_BLK;

    float acc[8][4] = {};

    int atile = lane >> 3;
    int arow = wm * 16 + (lane & 7) + ((atile & 1) << 3);
    uint32_t aaddr = smem_u32(sA) + (uint32_t)(arow * 36 + (atile >> 1) * 4) * 4u;
    int brow = wn * 64 + ((lane >> 4) << 3) + (lane & 7);
    uint32_t baddr = smem_u32(sB) + (uint32_t)(brow * 36 + ((lane >> 3) & 1) * 4) * 4u;

    auto prefetch = [&](int k0, int s) {
        float* dA = sA + s * M_BLK * 36;
        for (int i = t; i < M_BLK * 8; i += 256) {
            int m = i >> 3, k4 = i & 7;
            cp_async16(smem_u32(&dA[m * 36 + k4 * 4]),
                       &w[(size_t)(mbase + m) * KTOT + k0 + k4 * 4]);
        }
        int kk = k0 / IC, ic0 = k0 % IC;
        float* dB = sB + s * N_BLK * 36;
        for (int i = t; i < N_BLK * 8; i += 256) {
            int n = i >> 3, q = i & 7;
            long ng = n0 + n;
            int b = (int)(ng / NPOS), p = (int)(ng % NPOS);
            int pos = p * 2 + kk - PAD;
            bool valid = (pos >= 0 && pos < LIN);
            const float* sp = &in[(size_t)b * 3072 + (valid ? pos : 0) * IC + ic0 + q * 4];
            cp_async16z(smem_u32(&dB[n * 36 + q * 4]), sp, valid);
        }
    };

    constexpr int NCH = KTOT / 32;
    prefetch(0, 0);
    cp_commit();
    for (int i = 0; i < NCH; i++) {
        int cur = i & 1;
        if (i + 1 < NCH) {
            prefetch((i + 1) * 32, cur ^ 1);
            cp_commit();
            cp_wait<1>();
        } else {
            cp_wait<0>();
        }
        __syncthreads();
        uint32_t aS = (uint32_t)cur * (M_BLK * 36 * 4);
        uint32_t bS = (uint32_t)cur * (N_BLK * 36 * 4);
        #pragma unroll
        for (int ks = 0; ks < 4; ks++) {
            int kb = ks * 8;
            uint32_t a0, a1, a2, a3;
            ldsm_x4(a0, a1, a2, a3, aaddr + aS + kb * 4);
            #pragma unroll
            for (int p = 0; p < 4; p++) {
                uint32_t b0, b1, b2, b3;
                ldsm_x4(b0, b1, b2, b3, baddr + bS + (p * 16 * 36 + kb) * 4);
                mma_tf32(acc[2 * p],     a0, a1, a2, a3, b0, b1);
                mma_tf32(acc[2 * p + 1], a0, a1, a2, a3, b2, b3);
            }
        }
        __syncthreads();
    }
    int m0 = mbase + wm * 16 + g;
    int m1 = m0 + 8;
    float bi0 = bias[m0], bi1 = bias[m1];
    #pragma unroll
    for (int j = 0; j < 8; j++) {
        long nc = n0 + wn * 64 + j * 8 + 2 * tg;
        int b = (int)(nc / NPOS), p = (int)(nc % NPOS);
        float* ob = outp + (size_t)b * 3072;        // [pos][OC]
        ob[p * OC + m0]       = tf32r(fmaxf(acc[j][0] + bi0, 0.f));
        ob[(p + 1) * OC + m0] = tf32r(fmaxf(acc[j][1] + bi0, 0.f));
        ob[p * OC + m1]       = tf32r(fmaxf(acc[j][2] + bi1, 0.f));
        ob[(p + 1) * OC + m1] = tf32r(fmaxf(acc[j][3] + bi1, 0.f));
    }
}

// ---------------- fc1 via mma, cp.async double-buffered ----------------------
__global__ void __launch_bounds__(256, 3) k_fc1mma(const float* __restrict__ bias,
                                                   float* __restrict__ feat_out) {
    const float* Wt = g_buf1 + WT_OFF;
    extern __shared__ float smd[];
    float* sA = smd;                   // [2][128*36]
    float* sB = smd + 2 * 128 * 36;    // [2][32*36]
    int t = threadIdx.x;
    int warp = t >> 5, lane = t & 31;
    int g = lane >> 2, tg = lane & 3;
    long n0 = (long)blockIdx.x * 32;
    float acc[4][4] = {};

    int atile = lane >> 3;
    int arow = warp * 16 + (lane & 7) + ((atile & 1) << 3);
    uint32_t aaddr = smem_u32(sA) + (uint32_t)(arow * 36 + (atile >> 1) * 4) * 4u;
    int brow = ((lane >> 4) << 3) + (lane & 7);
    uint32_t baddr = smem_u32(sB) + (uint32_t)(brow * 36 + ((lane >> 3) & 1) * 4) * 4u;

    auto prefetch = [&](int k0, int s) {
        float* dA = sA + s * 128 * 36;
        for (int i = t; i < 1024; i += 256) {
            int m = i >> 3, k4 = i & 7;
            cp_async16(smem_u32(&dA[m * 36 + k4 * 4]),
                       &Wt[(size_t)m * 3072 + k0 + k4 * 4]);
        }
        float* dB = sB + s * 32 * 36;
        for (int i = t; i < 256; i += 256) {
            int n = i >> 3, k4 = i & 7;
            cp_async16(smem_u32(&dB[n * 36 + k4 * 4]),
                       &g_buf1[(size_t)(n0 + n) * 3072 + k0 + k4 * 4]);
        }
    };

    prefetch(0, 0);
    cp_commit();
    for (int i = 0; i < 96; i++) {
        int cur = i & 1;
        if (i + 1 < 96) {
            prefetch((i + 1) * 32, cur ^ 1);
            cp_commit();
            cp_wait<1>();
        } else {
            cp_wait<0>();
        }
        __syncthreads();
        uint32_t aS = (uint32_t)cur * (128 * 36 * 4);
        uint32_t bS = (uint32_t)cur * (32 * 36 * 4);
        #pragma unroll
        for (int ks = 0; ks < 4; ks++) {
            int kb = ks * 8;
            uint32_t a0, a1, a2, a3;
            ldsm_x4(a0, a1, a2, a3, aaddr + aS + kb * 4);
            #pragma unroll
            for (int p = 0; p < 2; p++) {
                uint32_t b0, b1, b2, b3;
                ldsm_x4(b0, b1, b2, b3, baddr + bS + (p * 16 * 36 + kb) * 4);
                mma_tf32(acc[2 * p],     a0, a1, a2, a3, b0, b1);
                mma_tf32(acc[2 * p + 1], a0, a1, a2, a3, b2, b3);
            }
        }
        __syncthreads();
    }
    int m0 = warp * 16 + g, m1 = m0 + 8;
    float bi0 = bias[m0], bi1 = bias[m1];
    #pragma unroll
    for (int j = 0; j < 4; j++) {
        long n = n0 + j * 8 + 2 * tg;
        float f00 = acc[j][0] + bi0, f01 = acc[j][1] + bi0;
        float f10 = acc[j][2] + bi1, f11 = acc[j][3] + bi1;
        feat_out[n * 128 + m0] = f00;       feat_out[(n + 1) * 128 + m0] = f01;
        feat_out[n * 128 + m1] = f10;       feat_out[(n + 1) * 128 + m1] = f11;
        g_buf2[n * 128 + m0] = tf32r(fmaxf(f00, 0.f));
        g_buf2[(n + 1) * 128 + m0] = tf32r(fmaxf(f01, 0.f));
        g_buf2[n * 128 + m1] = tf32r(fmaxf(f10, 0.f));
        g_buf2[(n + 1) * 128 + m1] = tf32r(fmaxf(f11, 0.f));
    }
}

// ---------------- cls via mma: pre-rounded transposed weights ----------------
template<int MTOT, int STAGE, size_t CWOFF>
__global__ void __launch_bounds__(256, 3) k_clsmma(const float* __restrict__ bias,
                                                   float* __restrict__ outx) {
    const float* inb = (STAGE == 1) ? g_buf2 : g_buf1;
    const float* Wm  = g_buf1 + CWOFF;             // [m][128], pre-rounded
    __shared__ float sA[128 * 36];
    __shared__ float sB[64 * 36];
    int t = threadIdx.x;
    int warp = t >> 5, lane = t & 31;
    int g = lane >> 2, tg = lane & 3;
    int mbase = blockIdx.y * 128;
    long n0 = (long)blockIdx.x * 64;
    float acc[8][4] = {};

    int atile = lane >> 3;
    int arow = warp * 16 + (lane & 7) + ((atile & 1) << 3);
    uint32_t aaddr = smem_u32(sA) + (uint32_t)(arow * 36 + (atile >> 1) * 4) * 4u;
    int brow = ((lane >> 4) << 3) + (lane & 7);
    uint32_t baddr = smem_u32(sB) + (uint32_t)(brow * 36 + ((lane >> 3) & 1) * 4) * 4u;

    for (int k0 = 0; k0 < 128; k0 += 32) {
        __syncthreads();
        for (int i = t; i < 128 * 8; i += 256) {
            int n = i >> 3, k4 = i & 7;
            *(float4*)&sA[n * 36 + k4 * 4] =
                *(const float4*)&Wm[(size_t)(mbase + n) * 128 + k0 + k4 * 4];
        }
        for (int i = t; i < 512; i += 256) {
            int n = i >> 3, k4 = i & 7;
            float4 v = *(const float4*)&inb[(size_t)(n0 + n) * 128 + k0 + k4 * 4];
            *(float4*)&sB[n * 36 + k4 * 4] = v;
        }
        __syncthreads();
        #pragma unroll
        for (int ks = 0; ks < 4; ks++) {
            int kb = ks * 8;
            uint32_t a0, a1, a2, a3;
            ldsm_x4(a0, a1, a2, a3, aaddr + kb * 4);
            #pragma unroll
            for (int p = 0; p < 4; p++) {
                uint32_t b0, b1, b2, b3;
                ldsm_x4(b0, b1, b2, b3, baddr + (p * 16 * 36 + kb) * 4);
                mma_tf32(acc[2 * p],     a0, a1, a2, a3, b0, b1);
                mma_tf32(acc[2 * p + 1], a0, a1, a2, a3, b2, b3);
            }
        }
    }
    int m0 = mbase + warp * 16 + g, m1 = m0 + 8;
    float bi0 = (m0 < MTOT) ? bias[m0] : 0.f;
    float bi1 = (m1 < MTOT) ? bias[m1] : 0.f;
    #pragma unroll
    for (int j = 0; j < 8; j++) {
        long b = n0 + j * 8 + 2 * tg;
        float f00 = acc[j][0] + bi0, f01 = acc[j][1] + bi0;
        float f10 = acc[j][2] + bi1, f11 = acc[j][3] + bi1;
        if (STAGE == 1) {
            f00 = tf32r(fmaxf(f00, 0.f)); f01 = tf32r(fmaxf(f01, 0.f));
            f10 = tf32r(fmaxf(f10, 0.f)); f11 = tf32r(fmaxf(f11, 0.f));
            g_buf1[b * 128 + m0] = f00; g_buf1[(b + 1) * 128 + m0] = f01;
            g_buf1[b * 128 + m1] = f10; g_buf1[(b + 1) * 128 + m1] = f11;
        } else {
            if (m0 < MTOT) { outx[b * MTOT + m0] = f00; outx[(b + 1) * MTOT + m0] = f01; }
            if (m1 < MTOT) { outx[b * MTOT + m1] = f10; outx[(b + 1) * MTOT + m1] = f11; }
        }
    }
}

// ---------------- launch ------------------------------------------------------
extern "C" void kernel_launch(void* const* d_in, const int* in_sizes, int n_in,
                              void* d_out, int out_size) {
    const float* src     = (const float*)d_in[0];
    const int*   ei      = (const int*)d_in[1];
    const float* gcn1_w  = (const float*)d_in[2];
    const float* gcn1_b  = (const float*)d_in[3];
    const float* gcn2_w  = (const float*)d_in[4];
    const float* gcn2_b  = (const float*)d_in[5];
    const float* conv1_w = (const float*)d_in[6];
    const float* conv1_b = (const float*)d_in[7];
    const float* conv2_w = (const float*)d_in[8];
    const float* conv2_b = (const float*)d_in[9];
    const float* conv3_w = (const float*)d_in[10];
    const float* conv3_b = (const float*)d_in[11];
    const float* fc1_w   = (const float*)d_in[12];
    const float* fc1_b   = (const float*)d_in[13];
    const float* cls1_w  = (const float*)d_in[14];
    const float* cls1_b  = (const float*)d_in[15];
    const float* cls2_w  = (const float*)d_in[16];
    const float* cls2_b  = (const float*)d_in[17];

    int ne = in_sizes[1] / 2;

    float* out   = (float*)d_out;
    float* out_x = out;                          // [B,210]
    float* out_f = out + (size_t)BB * 210;       // [B,128]

    const int GCNB_SMEM = (64 * 20 + 32 * 68 + 128 * 20 + 128 * 68 + 64) * 4;
    const int CONV_SMEM = 2 * 192 * 36 * 4;      // 55296
    const int FC1_SMEM  = 2 * 160 * 36 * 4;      // 46080

    cudaFuncSetAttribute(k_gcnBmma, cudaFuncAttributeMaxDynamicSharedMemorySize, GCNB_SMEM);
    cudaFuncSetAttribute(k_convmma<64, 4, 2, 224, 32, 48, 96, 3, 64, 0, CW1_OFF>,
                         cudaFuncAttributeMaxDynamicSharedMemorySize, CONV_SMEM);
    cudaFuncSetAttribute(k_convmma<128, 8, 1, 320, 64, 24, 48, 2, 128, 1, CW2_OFF>,
                         cudaFuncAttributeMaxDynamicSharedMemorySize, CONV_SMEM);
    cudaFuncSetAttribute(k_convmma<128, 8, 1, 384, 128, 12, 24, 1, 256, 0, CW3_OFF>,
                         cudaFuncAttributeMaxDynamicSharedMemorySize, CONV_SMEM);
    cudaFuncSetAttribute(k_fc1mma, cudaFuncAttributeMaxDynamicSharedMemorySize, FC1_SMEM);

    k_build_adj<<<1, 256>>>(ei, ne);
    k_prea<<<48, 256>>>();
    k_trW<<<1536, 256>>>(fc1_w);
    k_prew<<<384, 256>>>(conv1_w, conv2_w, conv3_w, cls1_w, cls2_w);

    k_gcnAmma<<<2048, 256>>>(src);
    k_gcnBmma<<<BB * 96 / 128, 256, GCNB_SMEM>>>(gcn1_w, gcn1_b, gcn2_w);
    k_gcnCmma<<<4096, 256>>>(gcn2_b);

    k_convmma<64, 4, 2, 224, 32, 48, 96, 3, 64, 0, CW1_OFF>
        <<<dim3(3072, 1), 256, CONV_SMEM>>>(conv1_b);
    k_convmma<128, 8, 1, 320, 64, 24, 48, 2, 128, 1, CW2_OFF>
        <<<dim3(3072, 1), 256, CONV_SMEM>>>(conv2_b);
    k_convmma<128, 8, 1, 384, 128, 12, 24, 1, 256, 0, CW3_OFF>
        <<<dim3(1536, 2), 256, CONV_SMEM>>>(conv3_b);

    k_fc1mma<<<256, 256, FC1_SMEM>>>(fc1_b, out_f);
    k_clsmma<128, 1, CWC1_OFF><<<dim3(128, 1), 256>>>(cls1_b, nullptr);
    k_clsmma<210, 2, CWC2_OFF><<<dim3(128, 2), 256>>>(cls2_b, out_x);
}